// round 5
// baseline (speedup 1.0000x reference)
#include <cuda_runtime.h>
#include <cuda_bf16.h>
#include <cstdint>
#include <math.h>

// Shapes (fixed): B=2, L=2048, DM=1024, DI=2048, N=16, DC=4, DT=64
#define BB 2
#define LL 2048
#define DM 1024
#define DI 2048
#define NS 16
#define DC 4
#define DT 64
#define ROWS (BB*LL)          // 4096
#define XZW (2*DI)            // 4096
#define DBLW 128              // padded dbl row (dt 0..63 | B 64..79 | C 80..95 | pad)
#define CL 64                 // scan chunk length
#define NC (LL/CL)            // 32 chunks
#define QMAX 16256.0f         // 127*128 fixed-point ceiling

// ================= scratch (device globals) =================
__device__ __align__(256) float g_xz[ROWS * XZW];                  // xi | z (fp32)
__device__ __align__(256) float g_u [ROWS * DI];
__device__ __align__(256) float g_y [ROWS * DI];
__device__ __align__(256) float g_dblp[4 * ROWS * DBLW];           // split-K partials
__device__ __align__(256) float g_dblr[ROWS * DBLW];               // reduced
__device__ __align__(256) float g_delta[ROWS * DI];
__device__ __align__(256) float g_S[BB * NC * DI];                 // per-chunk sum(delta)
__device__ __align__(256) float g_hend[BB * NC * NS * DI];
__device__ __align__(256) float g_hstart[BB * NC * NS * DI];
// int8 fixed-point operands (hi/lo) + scales
__device__ __align__(256) int8_t g_xn1[ROWS * DM],  g_xn0[ROWS * DM];
__device__ __align__(256) int8_t g_y1 [ROWS * DI],  g_y0 [ROWS * DI];
__device__ __align__(256) int8_t g_w1in [XZW * DM], g_w0in [XZW * DM];   // [4096,1024]
__device__ __align__(256) int8_t g_w1out[DM * DI],  g_w0out[DM * DI];    // [1024,2048]
__device__ __align__(256) float g_sxn[ROWS], g_sy[ROWS];
__device__ __align__(256) float g_sbin[XZW], g_sbout[DM];
__device__ __align__(256) float g_part_in[8 * XZW], g_part_out[8 * DM];
// bf16 operands for the two small GEMMs
__device__ __align__(256) __nv_bfloat16 g_u_h [ROWS * DI],  g_u_l [ROWS * DI];
__device__ __align__(256) __nv_bfloat16 g_dt_h[ROWS * DT],  g_dt_l[ROWS * DT];
__device__ __align__(256) __nv_bfloat16 g_wx_h [128 * DI],  g_wx_l [128 * DI];   // [128,2048]
__device__ __align__(256) __nv_bfloat16 g_wdt_h[DI * DT],   g_wdt_l[DI * DT];    // [2048,64]

__device__ __forceinline__ void split_bf16(float v, __nv_bfloat16& h, __nv_bfloat16& l) {
    h = __float2bfloat16(v);
    l = __float2bfloat16(v - __bfloat162float(h));
}
__device__ __forceinline__ void quant15(float v, float inv, int8_t& hi, int8_t& lo) {
    int qi = __float2int_rn(v * inv);
    int h = (qi + 64) >> 7;
    hi = (int8_t)h;
    lo = (int8_t)(qi - (h << 7));
}

// ================= PTX helpers (baseline compute_103 ISA only) =================
__device__ __forceinline__ uint32_t smem_u32(const void* p) {
    uint32_t a;
    asm("{ .reg .u64 t; cvta.to.shared.u64 t, %1; cvt.u32.u64 %0, t; }" : "=r"(a) : "l"(p));
    return a;
}
__device__ __forceinline__ void cp_async16(uint32_t sa, const void* ga) {
    asm volatile("cp.async.cg.shared.global [%0], [%1], 16;" :: "r"(sa), "l"(ga));
}
__device__ __forceinline__ void cp_commit() {
    asm volatile("cp.async.commit_group;" ::: "memory");
}
__device__ __forceinline__ void cp_wait2() {
    asm volatile("cp.async.wait_group 2;" ::: "memory");
}
__device__ __forceinline__ void cp_wait1() {
    asm volatile("cp.async.wait_group 1;" ::: "memory");
}
__device__ __forceinline__ void cp_wait0() {
    asm volatile("cp.async.wait_group 0;" ::: "memory");
}
__device__ __forceinline__ void ldsm4(uint32_t* r, uint32_t addr) {
    asm volatile("ldmatrix.sync.aligned.m8n8.x4.shared.b16 {%0,%1,%2,%3}, [%4];"
        : "=r"(r[0]), "=r"(r[1]), "=r"(r[2]), "=r"(r[3]) : "r"(addr));
}
__device__ __forceinline__ void mma16816(float* d, const uint32_t* a, const uint32_t* b) {
    asm volatile("mma.sync.aligned.m16n8k16.row.col.f32.bf16.bf16.f32 "
        "{%0,%1,%2,%3}, {%4,%5,%6,%7}, {%8,%9}, {%0,%1,%2,%3};"
        : "+f"(d[0]), "+f"(d[1]), "+f"(d[2]), "+f"(d[3])
        : "r"(a[0]), "r"(a[1]), "r"(a[2]), "r"(a[3]), "r"(b[0]), "r"(b[1]));
}
__device__ __forceinline__ void mma_s8(int* d, const uint32_t* a, const uint32_t* b) {
    asm volatile("mma.sync.aligned.m16n8k32.row.col.s32.s8.s8.s32 "
        "{%0,%1,%2,%3}, {%4,%5,%6,%7}, {%8,%9}, {%0,%1,%2,%3};"
        : "+r"(d[0]), "+r"(d[1]), "+r"(d[2]), "+r"(d[3])
        : "r"(a[0]), "r"(a[1]), "r"(a[2]), "r"(a[3]), "r"(b[0]), "r"(b[1]));
}
// swizzled smem byte offset for (row, 16B-chunk) in a [128 rows x 64B] tile
__device__ __forceinline__ uint32_t sw_off(int row, int chunk) {
    return (uint32_t)(row * 64 + ((chunk ^ ((row >> 1) & 3)) << 4));
}

// ================= LayerNorm -> int8 hi/lo + row scale =================
__global__ void ln_kernel(const float* __restrict__ x,
                          const float* __restrict__ gam,
                          const float* __restrict__ bet,
                          int8_t* __restrict__ xn1,
                          int8_t* __restrict__ xn0,
                          float* __restrict__ sxn) {
    int row = blockIdx.x;
    const float4* xr = reinterpret_cast<const float4*>(x + (size_t)row * DM);
    int t = threadIdx.x;
    float4 v = xr[t];
    float s  = v.x + v.y + v.z + v.w;
    float ss = v.x*v.x + v.y*v.y + v.z*v.z + v.w*v.w;
    #pragma unroll
    for (int o = 16; o > 0; o >>= 1) {
        s  += __shfl_xor_sync(0xffffffff, s,  o);
        ss += __shfl_xor_sync(0xffffffff, ss, o);
    }
    __shared__ float rs[8], rss[8], rmx[8];
    int wid = t >> 5, lid = t & 31;
    if (lid == 0) { rs[wid] = s; rss[wid] = ss; }
    __syncthreads();
    __shared__ float smu, srstd;
    if (t == 0) {
        float ts = 0.f, tss = 0.f;
        #pragma unroll
        for (int i = 0; i < 8; i++) { ts += rs[i]; tss += rss[i]; }
        float mu = ts / (float)DM;
        float var = tss / (float)DM - mu * mu;
        smu = mu; srstd = rsqrtf(var + 1e-5f);
    }
    __syncthreads();
    float mu = smu, rstd = srstd;
    const float4* g4 = reinterpret_cast<const float4*>(gam);
    const float4* b4 = reinterpret_cast<const float4*>(bet);
    float4 gg = g4[t], bb = b4[t];
    float o0 = (v.x - mu) * rstd * gg.x + bb.x;
    float o1 = (v.y - mu) * rstd * gg.y + bb.y;
    float o2 = (v.z - mu) * rstd * gg.z + bb.z;
    float o3 = (v.w - mu) * rstd * gg.w + bb.w;
    // row max |o|
    float mx = fmaxf(fmaxf(fabsf(o0), fabsf(o1)), fmaxf(fabsf(o2), fabsf(o3)));
    #pragma unroll
    for (int o = 16; o > 0; o >>= 1) mx = fmaxf(mx, __shfl_xor_sync(0xffffffff, mx, o));
    if (lid == 0) rmx[wid] = mx;
    __syncthreads();
    __shared__ float sinv;
    if (t == 0) {
        float m = 1e-30f;
        #pragma unroll
        for (int i = 0; i < 8; i++) m = fmaxf(m, rmx[i]);
        sinv = QMAX / m;
        sxn[row] = m / QMAX;
    }
    __syncthreads();
    float inv = sinv;
    int8_t h0,l0,h1,l1,h2,l2,h3,l3;
    quant15(o0, inv, h0, l0); quant15(o1, inv, h1, l1);
    quant15(o2, inv, h2, l2); quant15(o3, inv, h3, l3);
    char4 ch = make_char4(h0, h1, h2, h3);
    char4 cl = make_char4(l0, l1, l2, l3);
    reinterpret_cast<char4*>(xn1 + (size_t)row * DM)[t] = ch;
    reinterpret_cast<char4*>(xn0 + (size_t)row * DM)[t] = cl;
}

// ============ per-output-column |max| partials for weight quant ============
__global__ void colmax_kernel(const float* __restrict__ W,
                              float* __restrict__ part, int K, int N) {
    int n = blockIdx.x * 256 + threadIdx.x;
    if (n >= N) return;
    int kper = K >> 3;
    int k0 = blockIdx.y * kper;
    float m = 1e-30f;
    for (int k = k0; k < k0 + kper; k++)
        m = fmaxf(m, fabsf(W[(size_t)k * N + n]));
    part[blockIdx.y * N + n] = m;
}

// ============ weight transpose + int8 quant: W[K,N] -> T[N,K] ============
__global__ void wquant_kernel(const float* __restrict__ W,
                              const float* __restrict__ part,
                              int8_t* __restrict__ T1,
                              int8_t* __restrict__ T0,
                              float* __restrict__ sb,
                              int K, int N) {
    __shared__ float t[32][33];
    int n = blockIdx.x * 32 + threadIdx.x;
    int k0 = blockIdx.y * 32;
    #pragma unroll
    for (int i = 0; i < 4; i++) {
        int k = k0 + threadIdx.y + i * 8;
        t[threadIdx.y + i * 8][threadIdx.x] = W[(size_t)k * N + n];
    }
    __syncthreads();
    int kw = k0 + threadIdx.x;
    #pragma unroll
    for (int i = 0; i < 4; i++) {
        int nn = blockIdx.x * 32 + threadIdx.y + i * 8;
        float pm = 1e-30f;
        #pragma unroll
        for (int j = 0; j < 8; j++) pm = fmaxf(pm, part[j * N + nn]);
        float inv = QMAX / pm;
        int8_t hi, lo;
        quant15(t[threadIdx.x][threadIdx.y + i * 8], inv, hi, lo);
        T1[(size_t)nn * K + kw] = hi;
        T0[(size_t)nn * K + kw] = lo;
        if (kw == 0) sb[nn] = pm / QMAX;
    }
}

// ============ weight transpose + bf16 split (small GEMMs) ============
__global__ void wtrans_kernel(const float* __restrict__ W,
                              __nv_bfloat16* __restrict__ Th,
                              __nv_bfloat16* __restrict__ Tl,
                              int K, int N, int Npad) {
    __shared__ float t[32][33];
    int n = blockIdx.x * 32 + threadIdx.x;
    int k0 = blockIdx.y * 32;
    #pragma unroll
    for (int i = 0; i < 4; i++) {
        int k = k0 + threadIdx.y + i * 8;
        t[threadIdx.y + i * 8][threadIdx.x] = (n < N) ? W[(size_t)k * N + n] : 0.f;
    }
    __syncthreads();
    int kw = k0 + threadIdx.x;
    #pragma unroll
    for (int i = 0; i < 4; i++) {
        int nn = blockIdx.x * 32 + threadIdx.y + i * 8;
        if (nn < Npad) {
            float v = t[threadIdx.x][threadIdx.y + i * 8];
            __nv_bfloat16 h, l;
            split_bf16(v, h, l);
            Th[(size_t)nn * K + kw] = h;
            Tl[(size_t)nn * K + kw] = l;
        }
    }
}

// ============ row quantize y[4096, 2048] -> int8 hi/lo + scale ============
__global__ void rowquant_kernel(const float* __restrict__ Y,
                                int8_t* __restrict__ Y1,
                                int8_t* __restrict__ Y0,
                                float* __restrict__ sy) {
    int row = blockIdx.x;
    int t = threadIdx.x;
    const float4* yr = reinterpret_cast<const float4*>(Y + (size_t)row * DI);
    float4 v0 = yr[t], v1 = yr[t + 256];
    float mx = fmaxf(fmaxf(fabsf(v0.x), fabsf(v0.y)), fmaxf(fabsf(v0.z), fabsf(v0.w)));
    mx = fmaxf(mx, fmaxf(fmaxf(fabsf(v1.x), fabsf(v1.y)), fmaxf(fabsf(v1.z), fabsf(v1.w))));
    #pragma unroll
    for (int o = 16; o > 0; o >>= 1) mx = fmaxf(mx, __shfl_xor_sync(0xffffffff, mx, o));
    __shared__ float rmx[8];
    int wid = t >> 5, lid = t & 31;
    if (lid == 0) rmx[wid] = mx;
    __syncthreads();
    __shared__ float sinv;
    if (t == 0) {
        float m = 1e-30f;
        #pragma unroll
        for (int i = 0; i < 8; i++) m = fmaxf(m, rmx[i]);
        sinv = QMAX / m;
        sy[row] = m / QMAX;
    }
    __syncthreads();
    float inv = sinv;
    int8_t h[8], l[8];
    quant15(v0.x, inv, h[0], l[0]); quant15(v0.y, inv, h[1], l[1]);
    quant15(v0.z, inv, h[2], l[2]); quant15(v0.w, inv, h[3], l[3]);
    quant15(v1.x, inv, h[4], l[4]); quant15(v1.y, inv, h[5], l[5]);
    quant15(v1.z, inv, h[6], l[6]); quant15(v1.w, inv, h[7], l[7]);
    char4* p1 = reinterpret_cast<char4*>(Y1 + (size_t)row * DI);
    char4* p0 = reinterpret_cast<char4*>(Y0 + (size_t)row * DI);
    p1[t] = make_char4(h[0], h[1], h[2], h[3]);
    p1[t + 256] = make_char4(h[4], h[5], h[6], h[7]);
    p0[t] = make_char4(l[0], l[1], l[2], l[3]);
    p0[t + 256] = make_char4(l[4], l[5], l[6], l[7]);
}

#define GSTAGE 32768
#define GSMEM (3 * GSTAGE)

// ================= int8 fixed-point GEMM =================
// C[r,c] = sa[r]*sb[c]*(16384*sum(a1*b1) + 128*sum(a1*b0 + a0*b1)) (+ epilogue)
// A,B stored [*, K] int8 K-major. Tile 128x128, k-tile 64, 3-stage cp.async.
// EPI: 0 none, 1 residual +E[row*ldc+col].
template<int EPI>
__global__ void __launch_bounds__(256, 1) i8_gemm(
    const int8_t* __restrict__ A1, const int8_t* __restrict__ A0,
    const int8_t* __restrict__ B1, const int8_t* __restrict__ B0,
    const float* __restrict__ sa, const float* __restrict__ sb,
    const float* __restrict__ E, float* __restrict__ C,
    int N, int lda, int ldc, int nkt) {
    extern __shared__ __align__(128) char sm[];
    const int tid = threadIdx.x, lane = tid & 31, wid = tid >> 5;
    const int m0 = blockIdx.y * 128, n0 = blockIdx.x * 128;
    const int wm = (wid >> 2) * 64, wn = (wid & 3) * 32;
    const uint32_t sbm = smem_u32(sm);

    int acc1[4][4][4], accx[4][4][4];
    #pragma unroll
    for (int a = 0; a < 4; a++)
        #pragma unroll
        for (int b = 0; b < 4; b++)
            #pragma unroll
            for (int c = 0; c < 4; c++) { acc1[a][b][c] = 0; accx[a][b][c] = 0; }

    auto load_tile = [&](int kt, int stage) {
        uint32_t dst = sbm + stage * GSTAGE;
        #pragma unroll
        for (int j = 0; j < 8; j++) {
            int chunk = tid + j * 256;        // 0..2047
            int t = chunk >> 9;               // 0:A1 1:A0 2:B1 3:B0
            int w = chunk & 511;
            int row = w >> 2, c = w & 3;
            const int8_t* src = (t == 0) ? A1 : (t == 1) ? A0 : (t == 2) ? B1 : B0;
            int g0 = (t < 2 ? m0 : n0) + row;
            const void* gp = src + (size_t)g0 * lda + kt * 64 + c * 16;
            cp_async16(dst + t * 8192 + sw_off(row, c), gp);
        }
        cp_commit();
    };

    load_tile(0, 0);
    if (nkt > 1) load_tile(1, 1);

    const int lrow = lane & 15, lk = lane >> 4;
    for (int i = 0; i < nkt; i++) {
        if (i + 2 < nkt) { load_tile(i + 2, (i + 2) % 3); cp_wait2(); }
        else if (i + 1 < nkt) cp_wait1();
        else cp_wait0();
        __syncthreads();

        uint32_t base = sbm + (i % 3) * GSTAGE;
        #pragma unroll
        for (int ks = 0; ks < 2; ks++) {
            uint32_t a[4][4], b1f[4][2], b0f[4][2];
            #pragma unroll
            for (int mi = 0; mi < 4; mi++)
                ldsm4(a[mi], base + sw_off(wm + mi * 16 + lrow, ks * 2 + lk));
            #pragma unroll
            for (int nj = 0; nj < 2; nj++) {
                uint32_t t4[4];
                ldsm4(t4, base + 16384 + sw_off(wn + nj * 16 + lrow, ks * 2 + lk));
                b1f[nj*2][0] = t4[0]; b1f[nj*2][1] = t4[2];
                b1f[nj*2+1][0] = t4[1]; b1f[nj*2+1][1] = t4[3];
            }
            #pragma unroll
            for (int mi = 0; mi < 4; mi++)
                #pragma unroll
                for (int ni = 0; ni < 4; ni++)
                    mma_s8(acc1[mi][ni], a[mi], b1f[ni]);
            #pragma unroll
            for (int nj = 0; nj < 2; nj++) {
                uint32_t t4[4];
                ldsm4(t4, base + 24576 + sw_off(wn + nj * 16 + lrow, ks * 2 + lk));
                b0f[nj*2][0] = t4[0]; b0f[nj*2][1] = t4[2];
                b0f[nj*2+1][0] = t4[1]; b0f[nj*2+1][1] = t4[3];
            }
            #pragma unroll
            for (int mi = 0; mi < 4; mi++)
                #pragma unroll
                for (int ni = 0; ni < 4; ni++)
                    mma_s8(accx[mi][ni], a[mi], b0f[ni]);
            #pragma unroll
            for (int mi = 0; mi < 4; mi++)
                ldsm4(a[mi], base + 8192 + sw_off(wm + mi * 16 + lrow, ks * 2 + lk));
            #pragma unroll
            for (int mi = 0; mi < 4; mi++)
                #pragma unroll
                for (int ni = 0; ni < 4; ni++)
                    mma_s8(accx[mi][ni], a[mi], b1f[ni]);
        }
        __syncthreads();
    }

    #pragma unroll
    for (int mi = 0; mi < 4; mi++) {
        #pragma unroll
        for (int ni = 0; ni < 4; ni++) {
            int r = m0 + wm + mi * 16 + (lane >> 2);
            int col = n0 + wn + ni * 8 + (lane & 3) * 2;
            float sc0 = sb[col], sc1 = sb[col + 1];
            #pragma unroll
            for (int h = 0; h < 2; h++) {
                int rr = r + h * 8;
                float sr = sa[rr];
                float v0 = sr * sc0 * (16384.f * (float)acc1[mi][ni][h*2]
                                       + 128.f * (float)accx[mi][ni][h*2]);
                float v1 = sr * sc1 * (16384.f * (float)acc1[mi][ni][h*2+1]
                                       + 128.f * (float)accx[mi][ni][h*2+1]);
                size_t off = (size_t)rr * ldc + col;
                if (EPI == 1) { v0 += E[off]; v1 += E[off + 1]; }
                *reinterpret_cast<float2*>(C + off) = make_float2(v0, v1);
            }
        }
    }
}

// ================= bf16 mma GEMM (small GEMMs: W_x, W_dt) =================
template<int EPI>
__global__ void __launch_bounds__(256, 2) mma_gemm(
    const __nv_bfloat16* __restrict__ Ah, const __nv_bfloat16* __restrict__ Al,
    const __nv_bfloat16* __restrict__ Bh, const __nv_bfloat16* __restrict__ Bl,
    const float* __restrict__ E, float* __restrict__ C,
    int N, int lda, int ldc, int nkt, size_t zstride) {
    extern __shared__ __align__(128) char sm[];
    const int tid = threadIdx.x, lane = tid & 31, wid = tid >> 5;
    const int m0 = blockIdx.y * 128, n0 = blockIdx.x * 128;
    const int wm = (wid >> 2) * 64, wn = (wid & 3) * 32;
    const int kt0 = blockIdx.z * nkt;
    C += (size_t)blockIdx.z * zstride;
    const uint32_t sb = smem_u32(sm);

    float d[4][4][4];
    #pragma unroll
    for (int a = 0; a < 4; a++)
        #pragma unroll
        for (int b = 0; b < 4; b++)
            #pragma unroll
            for (int c = 0; c < 4; c++) d[a][b][c] = 0.f;

    auto load_tile = [&](int kt, int stage) {
        uint32_t dst = sb + stage * GSTAGE;
        #pragma unroll
        for (int j = 0; j < 8; j++) {
            int chunk = tid + j * 256;
            int t = chunk >> 9;               // 0:Ah 1:Al 2:Bh 3:Bl
            int w = chunk & 511;
            int row = w >> 2, c = w & 3;
            const __nv_bfloat16* src = (t == 0) ? Ah : (t == 1) ? Al : (t == 2) ? Bh : Bl;
            int g0 = (t < 2 ? m0 : n0) + row;
            const void* gp = (const char*)(src + (size_t)g0 * lda + (kt0 + kt) * 32) + c * 16;
            cp_async16(dst + t * 8192 + sw_off(row, c), gp);
        }
        cp_commit();
    };

    load_tile(0, 0);
    if (nkt > 1) load_tile(1, 1);

    const int lrow = lane & 15, lk = lane >> 4;
    for (int i = 0; i < nkt; i++) {
        if (i + 2 < nkt) { load_tile(i + 2, (i + 2) % 3); cp_wait2(); }
        else if (i + 1 < nkt) cp_wait1();
        else cp_wait0();
        __syncthreads();

        uint32_t base = sb + (i % 3) * GSTAGE;
        #pragma unroll
        for (int ks = 0; ks < 2; ks++) {
            uint32_t a[4][4], bh[4][2], bl[4][2];
            #pragma unroll
            for (int mi = 0; mi < 4; mi++)
                ldsm4(a[mi], base + sw_off(wm + mi * 16 + lrow, ks * 2 + lk));
            #pragma unroll
            for (int nj = 0; nj < 2; nj++) {
                uint32_t t4[4];
                ldsm4(t4, base + 16384 + sw_off(wn + nj * 16 + lrow, ks * 2 + lk));
                bh[nj*2][0] = t4[0]; bh[nj*2][1] = t4[2];
                bh[nj*2+1][0] = t4[1]; bh[nj*2+1][1] = t4[3];
            }
            #pragma unroll
            for (int mi = 0; mi < 4; mi++)
                #pragma unroll
                for (int ni = 0; ni < 4; ni++)
                    mma16816(d[mi][ni], a[mi], bh[ni]);
            #pragma unroll
            for (int nj = 0; nj < 2; nj++) {
                uint32_t t4[4];
                ldsm4(t4, base + 24576 + sw_off(wn + nj * 16 + lrow, ks * 2 + lk));
                bl[nj*2][0] = t4[0]; bl[nj*2][1] = t4[2];
                bl[nj*2+1][0] = t4[1]; bl[nj*2+1][1] = t4[3];
            }
            #pragma unroll
            for (int mi = 0; mi < 4; mi++)
                #pragma unroll
                for (int ni = 0; ni < 4; ni++)
                    mma16816(d[mi][ni], a[mi], bl[ni]);
            #pragma unroll
            for (int mi = 0; mi < 4; mi++)
                ldsm4(a[mi], base + 8192 + sw_off(wm + mi * 16 + lrow, ks * 2 + lk));
            #pragma unroll
            for (int mi = 0; mi < 4; mi++)
                #pragma unroll
                for (int ni = 0; ni < 4; ni++)
                    mma16816(d[mi][ni], a[mi], bh[ni]);
        }
        __syncthreads();
    }

    #pragma unroll
    for (int mi = 0; mi < 4; mi++) {
        #pragma unroll
        for (int ni = 0; ni < 4; ni++) {
            int r = m0 + wm + mi * 16 + (lane >> 2);
            int col = n0 + wn + ni * 8 + (lane & 3) * 2;
            if (col < N) {
                #pragma unroll
                for (int h = 0; h < 2; h++) {
                    int rr = r + h * 8;
                    float v0 = d[mi][ni][h*2], v1 = d[mi][ni][h*2+1];
                    size_t off = (size_t)rr * ldc + col;
                    if (EPI == 1) {
                        v0 += E[off]; v1 += E[off + 1];
                    } else if (EPI == 2) {
                        float a0 = v0 + E[col], a1 = v1 + E[col + 1];
                        v0 = (a0 > 20.f) ? a0 : log1pf(__expf(a0));
                        v1 = (a1 > 20.f) ? a1 : log1pf(__expf(a1));
                    }
                    *reinterpret_cast<float2*>(C + off) = make_float2(v0, v1);
                }
            }
        }
    }
}

// ============ reduce split-K partials -> dblr; split dt -> bf16 hi/lo ============
__global__ void reduce_dbl_kernel(const float* __restrict__ dblp,
                                  float* __restrict__ dblr,
                                  __nv_bfloat16* __restrict__ dth,
                                  __nv_bfloat16* __restrict__ dtl) {
    int i = blockIdx.x * 256 + threadIdx.x;
    if (i >= ROWS * DBLW) return;
    float s = dblp[i] + dblp[i + ROWS*DBLW] + dblp[i + 2*ROWS*DBLW] + dblp[i + 3*ROWS*DBLW];
    dblr[i] = s;
    int col = i & (DBLW - 1);
    if (col < DT) {
        int row = i >> 7;
        __nv_bfloat16 h, l;
        split_bf16(s, h, l);
        dth[row * DT + col] = h;
        dtl[row * DT + col] = l;
    }
}

// ================= depthwise conv + SiLU -> u (fp32 + bf16 hi/lo) =================
__global__ void conv_silu_kernel(const float* __restrict__ xz,
                                 const float* __restrict__ cw,
                                 const float* __restrict__ cb,
                                 float* __restrict__ u,
                                 __nv_bfloat16* __restrict__ uh,
                                 __nv_bfloat16* __restrict__ ul) {
    int idx = blockIdx.x * 256 + threadIdx.x;
    if (idx >= ROWS * DI) return;
    int d = idx & (DI - 1);
    int row = idx >> 11;
    int b = row >> 11;
    int l = row & (LL - 1);
    float w0 = cw[d*DC+0], w1 = cw[d*DC+1], w2 = cw[d*DC+2], w3 = cw[d*DC+3];
    float acc = cb[d];
    size_t base = (size_t)(b * LL) * XZW + d;
    if (l >= 3) acc = fmaf(xz[base + (size_t)(l-3) * XZW], w0, acc);
    if (l >= 2) acc = fmaf(xz[base + (size_t)(l-2) * XZW], w1, acc);
    if (l >= 1) acc = fmaf(xz[base + (size_t)(l-1) * XZW], w2, acc);
    acc = fmaf(xz[base + (size_t)l * XZW], w3, acc);
    float r = acc / (1.f + __expf(-acc));
    u[idx] = r;
    __nv_bfloat16 h, l2;
    split_bf16(r, h, l2);
    uh[idx] = h; ul[idx] = l2;
}

// ================= chunked parallel scan =================
__device__ __forceinline__ bool load_A(const float* __restrict__ A_log, int d, float* A) {
    bool fast = true;
    #pragma unroll
    for (int n = 0; n < NS; n++) {
        A[n] = -__expf(A_log[d * NS + n]);
        fast = fast && (fabsf(A[n] + (float)(n + 1)) < 1e-5f * (float)(n + 1));
    }
    return fast;
}

__global__ void scan_pass1(const float* __restrict__ dblr,
                           const float* __restrict__ delta,
                           const float* __restrict__ u,
                           const float* __restrict__ A_log,
                           float* __restrict__ S_out,
                           float* __restrict__ hend) {
    int d = blockIdx.x * 256 + threadIdx.x;
    int c = blockIdx.y, b = blockIdx.z;
    float A[NS];
    bool fast = load_A(A_log, d, A);
    float h[NS];
    #pragma unroll
    for (int n = 0; n < NS; n++) h[n] = 0.f;
    float S = 0.f;
    size_t rbase = (size_t)b * LL + (size_t)c * CL;
    for (int j = 0; j < CL; j++) {
        size_t row = rbase + j;
        float dl = delta[row * DI + d];
        float ul = u[row * DI + d];
        const float4* Bp = reinterpret_cast<const float4*>(dblr + row * DBLW + DT);
        float4 B0 = Bp[0], B1 = Bp[1], B2 = Bp[2], B3 = Bp[3];
        float Bv[NS] = {B0.x,B0.y,B0.z,B0.w, B1.x,B1.y,B1.z,B1.w,
                        B2.x,B2.y,B2.z,B2.w, B3.x,B3.y,B3.z,B3.w};
        S += dl;
        float su = dl * ul;
        if (fast) {
            float p = __expf(-dl), dA = p;
            #pragma unroll
            for (int n = 0; n < NS; n++) { h[n] = fmaf(dA, h[n], su * Bv[n]); dA *= p; }
        } else {
            #pragma unroll
            for (int n = 0; n < NS; n++) h[n] = fmaf(__expf(dl * A[n]), h[n], su * Bv[n]);
        }
    }
    size_t cb = (size_t)b * NC + c;
    S_out[cb * DI + d] = S;
    #pragma unroll
    for (int n = 0; n < NS; n++) hend[(cb * NS + n) * DI + d] = h[n];
}

__global__ void scan_pass2(const float* __restrict__ S_in,
                           const float* __restrict__ hend,
                           const float* __restrict__ A_log,
                           float* __restrict__ hstart) {
    int d = blockIdx.x * 256 + threadIdx.x;
    int b = blockIdx.y;
    float A[NS];
    bool fast = load_A(A_log, d, A);
    float h[NS];
    #pragma unroll
    for (int n = 0; n < NS; n++) h[n] = 0.f;
    for (int c = 0; c < NC; c++) {
        size_t cb = (size_t)b * NC + c;
        #pragma unroll
        for (int n = 0; n < NS; n++) hstart[(cb * NS + n) * DI + d] = h[n];
        float S = S_in[cb * DI + d];
        if (fast) {
            float p = __expf(-S), dA = p;
            #pragma unroll
            for (int n = 0; n < NS; n++) { h[n] = fmaf(dA, h[n], hend[(cb * NS + n) * DI + d]); dA *= p; }
        } else {
            #pragma unroll
            for (int n = 0; n < NS; n++)
                h[n] = fmaf(__expf(S * A[n]), h[n], hend[(cb * NS + n) * DI + d]);
        }
    }
}

__global__ void scan_pass3(const float* __restrict__ dblr,
                           const float* __restrict__ delta,
                           const float* __restrict__ u,
                           const float* __restrict__ xz,
                           const float* __restrict__ A_log,
                           const float* __restrict__ Dskip,
                           const float* __restrict__ hstart,
                           float* __restrict__ y) {
    int d = blockIdx.x * 256 + threadIdx.x;
    int c = blockIdx.y, b = blockIdx.z;
    float A[NS];
    bool fast = load_A(A_log, d, A);
    float Dd = Dskip[d];
    size_t cb = (size_t)b * NC + c;
    float h[NS];
    #pragma unroll
    for (int n = 0; n < NS; n++) h[n] = hstart[(cb * NS + n) * DI + d];
    size_t rbase = (size_t)b * LL + (size_t)c * CL;
    for (int j = 0; j < CL; j++) {
        size_t row = rbase + j;
        float dl = delta[row * DI + d];
        float ul = u[row * DI + d];
        float zl = xz[row * XZW + DI + d];
        const float4* Bp = reinterpret_cast<const float4*>(dblr + row * DBLW + DT);
        float4 B0 = Bp[0], B1 = Bp[1], B2 = Bp[2], B3 = Bp[3];
        float4 C0 = Bp[4], C1 = Bp[5], C2 = Bp[6], C3 = Bp[7];
        float Bv[NS] = {B0.x,B0.y,B0.z,B0.w, B1.x,B1.y,B1.z,B1.w,
                        B2.x,B2.y,B2.z,B2.w, B3.x,B3.y,B3.z,B3.w};
        float Cv[NS] = {C0.x,C0.y,C0.z,C0.w, C1.x,C1.y,C1.z,C1.w,
                        C2.x,C2.y,C2.z,C2.w, C3.x,C3.y,C3.z,C3.w};
        float su = dl * ul;
        float a0 = 0.f, a1 = 0.f, a2 = 0.f, a3 = 0.f;
        if (fast) {
            float p = __expf(-dl), dA = p;
            #pragma unroll
            for (int n = 0; n < NS; n++) {
                h[n] = fmaf(dA, h[n], su * Bv[n]);
                float* ap = (n & 2) ? ((n & 1) ? &a3 : &a2) : ((n & 1) ? &a1 : &a0);
                *ap = fmaf(h[n], Cv[n], *ap);
                dA *= p;
            }
        } else {
            #pragma unroll
            for (int n = 0; n < NS; n++) {
                h[n] = fmaf(__expf(dl * A[n]), h[n], su * Bv[n]);
                float* ap = (n & 2) ? ((n & 1) ? &a3 : &a2) : ((n & 1) ? &a1 : &a0);
                *ap = fmaf(h[n], Cv[n], *ap);
            }
        }
        float acc = (a0 + a1) + (a2 + a3);
        float sz = zl / (1.f + __expf(-zl));
        y[row * DI + d] = fmaf(ul, Dd, acc) * sz;
    }
}

// ================= launch =================
extern "C" void kernel_launch(void* const* d_in, const int* in_sizes, int n_in,
                              void* d_out, int out_size) {
    const float* x      = (const float*)d_in[0];
    const float* ln_g   = (const float*)d_in[1];
    const float* ln_b   = (const float*)d_in[2];
    const float* W_in   = (const float*)d_in[3];
    const float* conv_w = (const float*)d_in[4];
    const float* conv_b = (const float*)d_in[5];
    const float* W_x    = (const float*)d_in[6];
    const float* W_dt   = (const float*)d_in[7];
    const float* b_dt   = (const float*)d_in[8];
    const float* A_log  = (const float*)d_in[9];
    const float* Dskip  = (const float*)d_in[10];
    const float* W_out  = (const float*)d_in[11];
    float* out = (float*)d_out;

    float *xz, *u, *y, *dblp, *dblr, *delta, *Ssum, *hend, *hstart;
    float *sxn, *sy, *sbin, *sbout, *pin, *pout;
    int8_t *xn1, *xn0, *y1, *y0, *w1in, *w0in, *w1out, *w0out;
    __nv_bfloat16 *uh, *ul, *dth, *dtl, *wxh, *wxl, *wdth, *wdtl;
    cudaGetSymbolAddress((void**)&xz, g_xz);
    cudaGetSymbolAddress((void**)&u, g_u);
    cudaGetSymbolAddress((void**)&y, g_y);
    cudaGetSymbolAddress((void**)&dblp, g_dblp);
    cudaGetSymbolAddress((void**)&dblr, g_dblr);
    cudaGetSymbolAddress((void**)&delta, g_delta);
    cudaGetSymbolAddress((void**)&Ssum, g_S);
    cudaGetSymbolAddress((void**)&hend, g_hend);
    cudaGetSymbolAddress((void**)&hstart, g_hstart);
    cudaGetSymbolAddress((void**)&xn1, g_xn1);   cudaGetSymbolAddress((void**)&xn0, g_xn0);
    cudaGetSymbolAddress((void**)&y1, g_y1);     cudaGetSymbolAddress((void**)&y0, g_y0);
    cudaGetSymbolAddress((void**)&w1in, g_w1in); cudaGetSymbolAddress((void**)&w0in, g_w0in);
    cudaGetSymbolAddress((void**)&w1out, g_w1out); cudaGetSymbolAddress((void**)&w0out, g_w0out);
    cudaGetSymbolAddress((void**)&sxn, g_sxn);   cudaGetSymbolAddress((void**)&sy, g_sy);
    cudaGetSymbolAddress((void**)&sbin, g_sbin); cudaGetSymbolAddress((void**)&sbout, g_sbout);
    cudaGetSymbolAddress((void**)&pin, g_part_in); cudaGetSymbolAddress((void**)&pout, g_part_out);
    cudaGetSymbolAddress((void**)&uh, g_u_h);    cudaGetSymbolAddress((void**)&ul, g_u_l);
    cudaGetSymbolAddress((void**)&dth, g_dt_h);  cudaGetSymbolAddress((void**)&dtl, g_dt_l);
    cudaGetSymbolAddress((void**)&wxh, g_wx_h);  cudaGetSymbolAddress((void**)&wxl, g_wx_l);
    cudaGetSymbolAddress((void**)&wdth, g_wdt_h); cudaGetSymbolAddress((void**)&wdtl, g_wdt_l);

    cudaFuncSetAttribute(mma_gemm<0>, cudaFuncAttributeMaxDynamicSharedMemorySize, GSMEM);
    cudaFuncSetAttribute(mma_gemm<2>, cudaFuncAttributeMaxDynamicSharedMemorySize, GSMEM);
    cudaFuncSetAttribute(i8_gemm<0>, cudaFuncAttributeMaxDynamicSharedMemorySize, GSMEM);
    cudaFuncSetAttribute(i8_gemm<1>, cudaFuncAttributeMaxDynamicSharedMemorySize, GSMEM);

    dim3 tb32(32, 8);
    // --- weight preprocessing ---
    colmax_kernel<<<dim3(XZW/256, 8), 256>>>(W_in, pin, DM, XZW);
    wquant_kernel<<<dim3(XZW/32, DM/32), tb32>>>(W_in, pin, w1in, w0in, sbin, DM, XZW);
    colmax_kernel<<<dim3(DM/256, 8), 256>>>(W_out, pout, DI, DM);
    wquant_kernel<<<dim3(DM/32, DI/32), tb32>>>(W_out, pout, w1out, w0out, sbout, DI, DM);
    wtrans_kernel<<<dim3(4, DI/32), tb32>>>(W_x, wxh, wxl, DI, 96, 128);
    wtrans_kernel<<<dim3(DI/32, DT/32), tb32>>>(W_dt, wdth, wdtl, DT, DI, DI);

    // 1. LayerNorm -> int8 hi/lo + row scale
    ln_kernel<<<ROWS, 256>>>(x, ln_g, ln_b, xn1, xn0, sxn);

    // 2. xz = xn @ W_in   [4096,1024]x[1024,4096]  (int8 fixed-point)
    i8_gemm<0><<<dim3(XZW/128, ROWS/128), 256, GSMEM>>>(xn1, xn0, w1in, w0in,
        sxn, sbin, nullptr, xz, XZW, DM, XZW, DM/64);

    // 3. conv + silu -> u
    conv_silu_kernel<<<(ROWS*DI)/256, 256>>>(xz, conv_w, conv_b, u, uh, ul);

    // 4. dbl = u @ W_x   (bf16, split-K x4)
    mma_gemm<0><<<dim3(1, ROWS/128, 4), 256, GSMEM>>>(uh, ul, wxh, wxl,
        nullptr, dblp, 128, DI, DBLW, (DI/32)/4, (size_t)ROWS * DBLW);

    // 5. reduce + dt split
    reduce_dbl_kernel<<<(ROWS*DBLW)/256, 256>>>(dblp, dblr, dth, dtl);

    // 6. delta = softplus(dt @ W_dt + b_dt)   (bf16)
    mma_gemm<2><<<dim3(DI/128, ROWS/128, 1), 256, GSMEM>>>(dth, dtl, wdth, wdtl,
        b_dt, delta, DI, DT, DI, DT/32, 0);

    // 7. chunked scan -> y (fp32)
    scan_pass1<<<dim3(DI/256, NC, BB), 256>>>(dblr, delta, u, A_log, Ssum, hend);
    scan_pass2<<<dim3(DI/256, BB), 256>>>(Ssum, hend, A_log, hstart);
    scan_pass3<<<dim3(DI/256, NC, BB), 256>>>(dblr, delta, u, xz, A_log, Dskip,
                                              hstart, y);

    // 8. quantize y, then out = x + y @ W_out (int8 fixed-point, residual)
    rowquant_kernel<<<ROWS, 256>>>(y, y1, y0, sy);
    i8_gemm<1><<<dim3(DM/128, ROWS/128), 256, GSMEM>>>(y1, y0, w1out, w0out,
        sy, sbout, x, out, DM, DI, DM, DI/64);
}

// round 6
// speedup vs baseline: 2.4331x; 2.4331x over previous
#include <cuda_runtime.h>
#include <cuda_fp16.h>
#include <cstdint>
#include <math.h>

// Shapes (fixed): B=2, L=2048, DM=1024, DI=2048, N=16, DC=4, DT=64
#define BB 2
#define LL 2048
#define DM 1024
#define DI 2048
#define NS 16
#define DC 4
#define DT 64
#define ROWS (BB*LL)          // 4096
#define XZW (2*DI)            // 4096
#define DBLW 128              // padded dbl row (dt 0..63 | B 64..79 | C 80..95 | pad)
#define CL 64                 // scan chunk length
#define NC (LL/CL)            // 32 chunks

// ================= scratch (device globals) =================
__device__ __align__(256) float g_xz[ROWS * XZW];                  // xi | z (fp32)
__device__ __align__(256) float g_u [ROWS * DI];
__device__ __align__(256) float g_dblp[4 * ROWS * DBLW];           // split-K partials
__device__ __align__(256) float g_dblr[ROWS * DBLW];               // reduced
__device__ __align__(256) float g_delta[ROWS * DI];
__device__ __align__(256) float g_S[BB * NC * DI];                 // per-chunk sum(delta)
__device__ __align__(256) float g_hend[BB * NC * NS * DI];
__device__ __align__(256) float g_hstart[BB * NC * NS * DI];
// fp16 operands
__device__ __align__(256) __half g_xn[ROWS * DM];                  // LN out (single fp16)
__device__ __align__(256) __half g_y [ROWS * DI];                  // scan out (single fp16)
__device__ __align__(256) __half g_u_h [ROWS * DI], g_u_l [ROWS * DI];
__device__ __align__(256) __half g_dt_h[ROWS * DT], g_dt_l[ROWS * DT];
__device__ __align__(256) __half g_win_h[XZW * DM],  g_win_l[XZW * DM];   // [4096,1024]
__device__ __align__(256) __half g_wx_h [128 * DI],  g_wx_l [128 * DI];   // [128,2048]
__device__ __align__(256) __half g_wdt_h[DI * DT],   g_wdt_l[DI * DT];    // [2048,64]
__device__ __align__(256) __half g_wout_h[DM * DI],  g_wout_l[DM * DI];   // [1024,2048]

__device__ __forceinline__ void split_f16(float v, __half& h, __half& l) {
    h = __float2half_rn(v);
    l = __float2half_rn(v - __half2float(h));
}

// ================= PTX helpers (baseline compute_103 ISA only) =================
__device__ __forceinline__ uint32_t smem_u32(const void* p) {
    uint32_t a;
    asm("{ .reg .u64 t; cvta.to.shared.u64 t, %1; cvt.u32.u64 %0, t; }" : "=r"(a) : "l"(p));
    return a;
}
__device__ __forceinline__ void cp_async16(uint32_t sa, const void* ga) {
    asm volatile("cp.async.cg.shared.global [%0], [%1], 16;" :: "r"(sa), "l"(ga));
}
__device__ __forceinline__ void cp_commit() {
    asm volatile("cp.async.commit_group;" ::: "memory");
}
__device__ __forceinline__ void cp_wait2() {
    asm volatile("cp.async.wait_group 2;" ::: "memory");
}
__device__ __forceinline__ void cp_wait1() {
    asm volatile("cp.async.wait_group 1;" ::: "memory");
}
__device__ __forceinline__ void cp_wait0() {
    asm volatile("cp.async.wait_group 0;" ::: "memory");
}
__device__ __forceinline__ void ldsm4(uint32_t* r, uint32_t addr) {
    asm volatile("ldmatrix.sync.aligned.m8n8.x4.shared.b16 {%0,%1,%2,%3}, [%4];"
        : "=r"(r[0]), "=r"(r[1]), "=r"(r[2]), "=r"(r[3]) : "r"(addr));
}
__device__ __forceinline__ void mma_f16(float* d, const uint32_t* a, const uint32_t* b) {
    asm volatile("mma.sync.aligned.m16n8k16.row.col.f32.f16.f16.f32 "
        "{%0,%1,%2,%3}, {%4,%5,%6,%7}, {%8,%9}, {%0,%1,%2,%3};"
        : "+f"(d[0]), "+f"(d[1]), "+f"(d[2]), "+f"(d[3])
        : "r"(a[0]), "r"(a[1]), "r"(a[2]), "r"(a[3]), "r"(b[0]), "r"(b[1]));
}
// swizzled smem byte offset for (row, 16B-chunk) in a [128 rows x 64B] tile
__device__ __forceinline__ uint32_t sw_off(int row, int chunk) {
    return (uint32_t)(row * 64 + ((chunk ^ ((row >> 1) & 3)) << 4));
}

// ================= LayerNorm -> fp16 (single) =================
__global__ void ln_kernel(const float* __restrict__ x,
                          const float* __restrict__ gam,
                          const float* __restrict__ bet,
                          __half* __restrict__ xn) {
    int row = blockIdx.x;
    const float4* xr = reinterpret_cast<const float4*>(x + (size_t)row * DM);
    int t = threadIdx.x;
    float4 v = xr[t];
    float s  = v.x + v.y + v.z + v.w;
    float ss = v.x*v.x + v.y*v.y + v.z*v.z + v.w*v.w;
    #pragma unroll
    for (int o = 16; o > 0; o >>= 1) {
        s  += __shfl_xor_sync(0xffffffff, s,  o);
        ss += __shfl_xor_sync(0xffffffff, ss, o);
    }
    __shared__ float rs[8], rss[8];
    int wid = t >> 5, lid = t & 31;
    if (lid == 0) { rs[wid] = s; rss[wid] = ss; }
    __syncthreads();
    __shared__ float smu, srstd;
    if (t == 0) {
        float ts = 0.f, tss = 0.f;
        #pragma unroll
        for (int i = 0; i < 8; i++) { ts += rs[i]; tss += rss[i]; }
        float mu = ts / (float)DM;
        float var = tss / (float)DM - mu * mu;
        smu = mu; srstd = rsqrtf(var + 1e-5f);
    }
    __syncthreads();
    float mu = smu, rstd = srstd;
    const float4* g4 = reinterpret_cast<const float4*>(gam);
    const float4* b4 = reinterpret_cast<const float4*>(bet);
    float4 gg = g4[t], bb = b4[t];
    float o0 = (v.x - mu) * rstd * gg.x + bb.x;
    float o1 = (v.y - mu) * rstd * gg.y + bb.y;
    float o2 = (v.z - mu) * rstd * gg.z + bb.z;
    float o3 = (v.w - mu) * rstd * gg.w + bb.w;
    __half2* ph = reinterpret_cast<__half2*>(xn + (size_t)row * DM);
    ph[t*2]   = __halves2half2(__float2half_rn(o0), __float2half_rn(o1));
    ph[t*2+1] = __halves2half2(__float2half_rn(o2), __float2half_rn(o3));
}

// ============ weight transpose + fp16 split:  W[K,N] -> T[Npad,K] ============
__global__ void wtrans_kernel(const float* __restrict__ W,
                              __half* __restrict__ Th,
                              __half* __restrict__ Tl,
                              int K, int N, int Npad) {
    __shared__ float t[32][33];
    int n = blockIdx.x * 32 + threadIdx.x;
    int k0 = blockIdx.y * 32;
    #pragma unroll
    for (int i = 0; i < 4; i++) {
        int k = k0 + threadIdx.y + i * 8;
        t[threadIdx.y + i * 8][threadIdx.x] = (n < N) ? W[(size_t)k * N + n] : 0.f;
    }
    __syncthreads();
    int kw = k0 + threadIdx.x;
    #pragma unroll
    for (int i = 0; i < 4; i++) {
        int nn = blockIdx.x * 32 + threadIdx.y + i * 8;
        if (nn < Npad) {
            float v = t[threadIdx.x][threadIdx.y + i * 8];
            __half h, l;
            split_f16(v, h, l);
            Th[(size_t)nn * K + kw] = h;
            Tl[(size_t)nn * K + kw] = l;
        }
    }
}

// ================= GEMM A(fp16 single) x B(fp16 hi/lo), 2 mma passes ==========
// C = A @ (Bh+Bl)^T. Big GEMMs. Stage = A 8KB | Bh 8KB | Bl 8KB = 24KB, 3 stages.
// EPI: 0 none, 1 residual +E[row*ldc+col].
#define STG2 24576
#define SMEM2 (3 * STG2)
template<int EPI>
__global__ void __launch_bounds__(256, 2) gemm2(
    const __half* __restrict__ A,
    const __half* __restrict__ Bh, const __half* __restrict__ Bl,
    const float* __restrict__ E, float* __restrict__ C,
    int N, int lda, int ldc, int nkt) {
    extern __shared__ __align__(128) char sm[];
    const int tid = threadIdx.x, lane = tid & 31, wid = tid >> 5;
    const int m0 = blockIdx.y * 128, n0 = blockIdx.x * 128;
    const int wm = (wid >> 2) * 64, wn = (wid & 3) * 32;
    const uint32_t sb = smem_u32(sm);

    float d[4][4][4];
    #pragma unroll
    for (int a = 0; a < 4; a++)
        #pragma unroll
        for (int b = 0; b < 4; b++)
            #pragma unroll
            for (int c = 0; c < 4; c++) d[a][b][c] = 0.f;

    auto load_tile = [&](int kt, int stage) {
        uint32_t dst = sb + stage * STG2;
        #pragma unroll
        for (int j = 0; j < 6; j++) {
            int chunk = tid + j * 256;        // 0..1535
            int t = chunk >> 9;               // 0:A 1:Bh 2:Bl (uniform per j)
            int w = chunk & 511;
            int row = w >> 2, c = w & 3;
            const __half* src = (t == 0) ? A : (t == 1) ? Bh : Bl;
            int g0 = (t == 0 ? m0 : n0) + row;
            const void* gp = (const char*)(src + (size_t)g0 * lda + kt * 32) + c * 16;
            cp_async16(dst + t * 8192 + sw_off(row, c), gp);
        }
        cp_commit();
    };

    load_tile(0, 0);
    if (nkt > 1) load_tile(1, 1);

    const int lrow = lane & 15, lk = lane >> 4;
    for (int i = 0; i < nkt; i++) {
        if (i + 2 < nkt) { load_tile(i + 2, (i + 2) % 3); cp_wait2(); }
        else if (i + 1 < nkt) cp_wait1();
        else cp_wait0();
        __syncthreads();

        uint32_t base = sb + (i % 3) * STG2;
        #pragma unroll
        for (int ks = 0; ks < 2; ks++) {
            uint32_t a[4][4], bf[4][2];
            #pragma unroll
            for (int mi = 0; mi < 4; mi++)
                ldsm4(a[mi], base + sw_off(wm + mi * 16 + lrow, ks * 2 + lk));
            #pragma unroll
            for (int nj = 0; nj < 2; nj++) {
                uint32_t t4[4];
                ldsm4(t4, base + 8192 + sw_off(wn + nj * 16 + lrow, ks * 2 + lk));
                bf[nj*2][0] = t4[0]; bf[nj*2][1] = t4[2];
                bf[nj*2+1][0] = t4[1]; bf[nj*2+1][1] = t4[3];
            }
            #pragma unroll
            for (int mi = 0; mi < 4; mi++)
                #pragma unroll
                for (int ni = 0; ni < 4; ni++)
                    mma_f16(d[mi][ni], a[mi], bf[ni]);
            #pragma unroll
            for (int nj = 0; nj < 2; nj++) {
                uint32_t t4[4];
                ldsm4(t4, base + 16384 + sw_off(wn + nj * 16 + lrow, ks * 2 + lk));
                bf[nj*2][0] = t4[0]; bf[nj*2][1] = t4[2];
                bf[nj*2+1][0] = t4[1]; bf[nj*2+1][1] = t4[3];
            }
            #pragma unroll
            for (int mi = 0; mi < 4; mi++)
                #pragma unroll
                for (int ni = 0; ni < 4; ni++)
                    mma_f16(d[mi][ni], a[mi], bf[ni]);
        }
        __syncthreads();
    }

    #pragma unroll
    for (int mi = 0; mi < 4; mi++) {
        #pragma unroll
        for (int ni = 0; ni < 4; ni++) {
            int r = m0 + wm + mi * 16 + (lane >> 2);
            int col = n0 + wn + ni * 8 + (lane & 3) * 2;
            #pragma unroll
            for (int h = 0; h < 2; h++) {
                int rr = r + h * 8;
                float v0 = d[mi][ni][h*2], v1 = d[mi][ni][h*2+1];
                size_t off = (size_t)rr * ldc + col;
                if (EPI == 1) { v0 += E[off]; v1 += E[off + 1]; }
                *reinterpret_cast<float2*>(C + off) = make_float2(v0, v1);
            }
        }
    }
}

// ============ GEMM A(hi/lo) x B(hi/lo), 3 mma passes (accurate path) =========
// Stage = Ah|Al|Bh|Bl 8KB each = 32KB, 3 stages. Split-K via gridDim.z.
// EPI: 0 none, 2 softplus(v + E[col]).
#define STG3 32768
#define SMEM3 (3 * STG3)
template<int EPI>
__global__ void __launch_bounds__(256, 2) gemm3(
    const __half* __restrict__ Ah, const __half* __restrict__ Al,
    const __half* __restrict__ Bh, const __half* __restrict__ Bl,
    const float* __restrict__ E, float* __restrict__ C,
    int N, int lda, int ldc, int nkt, size_t zstride) {
    extern __shared__ __align__(128) char sm[];
    const int tid = threadIdx.x, lane = tid & 31, wid = tid >> 5;
    const int m0 = blockIdx.y * 128, n0 = blockIdx.x * 128;
    const int wm = (wid >> 2) * 64, wn = (wid & 3) * 32;
    const int kt0 = blockIdx.z * nkt;
    C += (size_t)blockIdx.z * zstride;
    const uint32_t sb = smem_u32(sm);

    float d[4][4][4];
    #pragma unroll
    for (int a = 0; a < 4; a++)
        #pragma unroll
        for (int b = 0; b < 4; b++)
            #pragma unroll
            for (int c = 0; c < 4; c++) d[a][b][c] = 0.f;

    auto load_tile = [&](int kt, int stage) {
        uint32_t dst = sb + stage * STG3;
        #pragma unroll
        for (int j = 0; j < 8; j++) {
            int chunk = tid + j * 256;
            int t = chunk >> 9;               // 0:Ah 1:Al 2:Bh 3:Bl
            int w = chunk & 511;
            int row = w >> 2, c = w & 3;
            const __half* src = (t == 0) ? Ah : (t == 1) ? Al : (t == 2) ? Bh : Bl;
            int g0 = (t < 2 ? m0 : n0) + row;
            const void* gp = (const char*)(src + (size_t)g0 * lda + (kt0 + kt) * 32) + c * 16;
            cp_async16(dst + t * 8192 + sw_off(row, c), gp);
        }
        cp_commit();
    };

    load_tile(0, 0);
    if (nkt > 1) load_tile(1, 1);

    const int lrow = lane & 15, lk = lane >> 4;
    for (int i = 0; i < nkt; i++) {
        if (i + 2 < nkt) { load_tile(i + 2, (i + 2) % 3); cp_wait2(); }
        else if (i + 1 < nkt) cp_wait1();
        else cp_wait0();
        __syncthreads();

        uint32_t base = sb + (i % 3) * STG3;
        #pragma unroll
        for (int ks = 0; ks < 2; ks++) {
            uint32_t a[4][4], bh[4][2], bl[4][2];
            #pragma unroll
            for (int mi = 0; mi < 4; mi++)
                ldsm4(a[mi], base + sw_off(wm + mi * 16 + lrow, ks * 2 + lk));
            #pragma unroll
            for (int nj = 0; nj < 2; nj++) {
                uint32_t t4[4];
                ldsm4(t4, base + 16384 + sw_off(wn + nj * 16 + lrow, ks * 2 + lk));
                bh[nj*2][0] = t4[0]; bh[nj*2][1] = t4[2];
                bh[nj*2+1][0] = t4[1]; bh[nj*2+1][1] = t4[3];
            }
            #pragma unroll
            for (int mi = 0; mi < 4; mi++)
                #pragma unroll
                for (int ni = 0; ni < 4; ni++)
                    mma_f16(d[mi][ni], a[mi], bh[ni]);
            #pragma unroll
            for (int nj = 0; nj < 2; nj++) {
                uint32_t t4[4];
                ldsm4(t4, base + 24576 + sw_off(wn + nj * 16 + lrow, ks * 2 + lk));
                bl[nj*2][0] = t4[0]; bl[nj*2][1] = t4[2];
                bl[nj*2+1][0] = t4[1]; bl[nj*2+1][1] = t4[3];
            }
            #pragma unroll
            for (int mi = 0; mi < 4; mi++)
                #pragma unroll
                for (int ni = 0; ni < 4; ni++)
                    mma_f16(d[mi][ni], a[mi], bl[ni]);
            #pragma unroll
            for (int mi = 0; mi < 4; mi++)
                ldsm4(a[mi], base + 8192 + sw_off(wm + mi * 16 + lrow, ks * 2 + lk));
            #pragma unroll
            for (int mi = 0; mi < 4; mi++)
                #pragma unroll
                for (int ni = 0; ni < 4; ni++)
                    mma_f16(d[mi][ni], a[mi], bh[ni]);
        }
        __syncthreads();
    }

    #pragma unroll
    for (int mi = 0; mi < 4; mi++) {
        #pragma unroll
        for (int ni = 0; ni < 4; ni++) {
            int r = m0 + wm + mi * 16 + (lane >> 2);
            int col = n0 + wn + ni * 8 + (lane & 3) * 2;
            if (col < N) {
                #pragma unroll
                for (int h = 0; h < 2; h++) {
                    int rr = r + h * 8;
                    float v0 = d[mi][ni][h*2], v1 = d[mi][ni][h*2+1];
                    size_t off = (size_t)rr * ldc + col;
                    if (EPI == 2) {
                        float a0 = v0 + E[col], a1 = v1 + E[col + 1];
                        v0 = (a0 > 20.f) ? a0 : log1pf(__expf(a0));
                        v1 = (a1 > 20.f) ? a1 : log1pf(__expf(a1));
                    }
                    *reinterpret_cast<float2*>(C + off) = make_float2(v0, v1);
                }
            }
        }
    }
}

// ============ reduce split-K partials -> dblr; split dt -> fp16 hi/lo ============
__global__ void reduce_dbl_kernel(const float* __restrict__ dblp,
                                  float* __restrict__ dblr,
                                  __half* __restrict__ dth,
                                  __half* __restrict__ dtl) {
    int i = blockIdx.x * 256 + threadIdx.x;
    if (i >= ROWS * DBLW) return;
    float s = dblp[i] + dblp[i + ROWS*DBLW] + dblp[i + 2*ROWS*DBLW] + dblp[i + 3*ROWS*DBLW];
    dblr[i] = s;
    int col = i & (DBLW - 1);
    if (col < DT) {
        int row = i >> 7;
        __half h, l;
        split_f16(s, h, l);
        dth[row * DT + col] = h;
        dtl[row * DT + col] = l;
    }
}

// ================= depthwise conv + SiLU -> u (fp32 + fp16 hi/lo) =================
__global__ void conv_silu_kernel(const float* __restrict__ xz,
                                 const float* __restrict__ cw,
                                 const float* __restrict__ cb,
                                 float* __restrict__ u,
                                 __half* __restrict__ uh,
                                 __half* __restrict__ ul) {
    int idx = blockIdx.x * 256 + threadIdx.x;
    if (idx >= ROWS * DI) return;
    int d = idx & (DI - 1);
    int row = idx >> 11;
    int b = row >> 11;
    int l = row & (LL - 1);
    float w0 = cw[d*DC+0], w1 = cw[d*DC+1], w2 = cw[d*DC+2], w3 = cw[d*DC+3];
    float acc = cb[d];
    size_t base = (size_t)(b * LL) * XZW + d;
    if (l >= 3) acc = fmaf(xz[base + (size_t)(l-3) * XZW], w0, acc);
    if (l >= 2) acc = fmaf(xz[base + (size_t)(l-2) * XZW], w1, acc);
    if (l >= 1) acc = fmaf(xz[base + (size_t)(l-1) * XZW], w2, acc);
    acc = fmaf(xz[base + (size_t)l * XZW], w3, acc);
    float r = acc / (1.f + __expf(-acc));
    u[idx] = r;
    __half h, l2;
    split_f16(r, h, l2);
    uh[idx] = h; ul[idx] = l2;
}

// ================= chunked parallel scan =================
__device__ __forceinline__ bool load_A(const float* __restrict__ A_log, int d, float* A) {
    bool fast = true;
    #pragma unroll
    for (int n = 0; n < NS; n++) {
        A[n] = -__expf(A_log[d * NS + n]);
        fast = fast && (fabsf(A[n] + (float)(n + 1)) < 1e-5f * (float)(n + 1));
    }
    return fast;
}

__global__ void scan_pass1(const float* __restrict__ dblr,
                           const float* __restrict__ delta,
                           const float* __restrict__ u,
                           const float* __restrict__ A_log,
                           float* __restrict__ S_out,
                           float* __restrict__ hend) {
    int d = blockIdx.x * 256 + threadIdx.x;
    int c = blockIdx.y, b = blockIdx.z;
    float A[NS];
    bool fast = load_A(A_log, d, A);
    float h[NS];
    #pragma unroll
    for (int n = 0; n < NS; n++) h[n] = 0.f;
    float S = 0.f;
    size_t rbase = (size_t)b * LL + (size_t)c * CL;
    for (int j = 0; j < CL; j++) {
        size_t row = rbase + j;
        float dl = delta[row * DI + d];
        float ul = u[row * DI + d];
        const float4* Bp = reinterpret_cast<const float4*>(dblr + row * DBLW + DT);
        float4 B0 = Bp[0], B1 = Bp[1], B2 = Bp[2], B3 = Bp[3];
        float Bv[NS] = {B0.x,B0.y,B0.z,B0.w, B1.x,B1.y,B1.z,B1.w,
                        B2.x,B2.y,B2.z,B2.w, B3.x,B3.y,B3.z,B3.w};
        S += dl;
        float su = dl * ul;
        if (fast) {
            float p = __expf(-dl), dA = p;
            #pragma unroll
            for (int n = 0; n < NS; n++) { h[n] = fmaf(dA, h[n], su * Bv[n]); dA *= p; }
        } else {
            #pragma unroll
            for (int n = 0; n < NS; n++) h[n] = fmaf(__expf(dl * A[n]), h[n], su * Bv[n]);
        }
    }
    size_t cb = (size_t)b * NC + c;
    S_out[cb * DI + d] = S;
    #pragma unroll
    for (int n = 0; n < NS; n++) hend[(cb * NS + n) * DI + d] = h[n];
}

__global__ void scan_pass2(const float* __restrict__ S_in,
                           const float* __restrict__ hend,
                           const float* __restrict__ A_log,
                           float* __restrict__ hstart) {
    int d = blockIdx.x * 256 + threadIdx.x;
    int b = blockIdx.y;
    float A[NS];
    bool fast = load_A(A_log, d, A);
    float h[NS];
    #pragma unroll
    for (int n = 0; n < NS; n++) h[n] = 0.f;
    for (int c = 0; c < NC; c++) {
        size_t cb = (size_t)b * NC + c;
        #pragma unroll
        for (int n = 0; n < NS; n++) hstart[(cb * NS + n) * DI + d] = h[n];
        float S = S_in[cb * DI + d];
        if (fast) {
            float p = __expf(-S), dA = p;
            #pragma unroll
            for (int n = 0; n < NS; n++) { h[n] = fmaf(dA, h[n], hend[(cb * NS + n) * DI + d]); dA *= p; }
        } else {
            #pragma unroll
            for (int n = 0; n < NS; n++)
                h[n] = fmaf(__expf(S * A[n]), h[n], hend[(cb * NS + n) * DI + d]);
        }
    }
}

__global__ void scan_pass3(const float* __restrict__ dblr,
                           const float* __restrict__ delta,
                           const float* __restrict__ u,
                           const float* __restrict__ xz,
                           const float* __restrict__ A_log,
                           const float* __restrict__ Dskip,
                           const float* __restrict__ hstart,
                           __half* __restrict__ y) {
    int d = blockIdx.x * 256 + threadIdx.x;
    int c = blockIdx.y, b = blockIdx.z;
    float A[NS];
    bool fast = load_A(A_log, d, A);
    float Dd = Dskip[d];
    size_t cb = (size_t)b * NC + c;
    float h[NS];
    #pragma unroll
    for (int n = 0; n < NS; n++) h[n] = hstart[(cb * NS + n) * DI + d];
    size_t rbase = (size_t)b * LL + (size_t)c * CL;
    for (int j = 0; j < CL; j++) {
        size_t row = rbase + j;
        float dl = delta[row * DI + d];
        float ul = u[row * DI + d];
        float zl = xz[row * XZW + DI + d];
        const float4* Bp = reinterpret_cast<const float4*>(dblr + row * DBLW + DT);
        float4 B0 = Bp[0], B1 = Bp[1], B2 = Bp[2], B3 = Bp[3];
        float4 C0 = Bp[4], C1 = Bp[5], C2 = Bp[6], C3 = Bp[7];
        float Bv[NS] = {B0.x,B0.y,B0.z,B0.w, B1.x,B1.y,B1.z,B1.w,
                        B2.x,B2.y,B2.z,B2.w, B3.x,B3.y,B3.z,B3.w};
        float Cv[NS] = {C0.x,C0.y,C0.z,C0.w, C1.x,C1.y,C1.z,C1.w,
                        C2.x,C2.y,C2.z,C2.w, C3.x,C3.y,C3.z,C3.w};
        float su = dl * ul;
        float a0 = 0.f, a1 = 0.f, a2 = 0.f, a3 = 0.f;
        if (fast) {
            float p = __expf(-dl), dA = p;
            #pragma unroll
            for (int n = 0; n < NS; n++) {
                h[n] = fmaf(dA, h[n], su * Bv[n]);
                float* ap = (n & 2) ? ((n & 1) ? &a3 : &a2) : ((n & 1) ? &a1 : &a0);
                *ap = fmaf(h[n], Cv[n], *ap);
                dA *= p;
            }
        } else {
            #pragma unroll
            for (int n = 0; n < NS; n++) {
                h[n] = fmaf(__expf(dl * A[n]), h[n], su * Bv[n]);
                float* ap = (n & 2) ? ((n & 1) ? &a3 : &a2) : ((n & 1) ? &a1 : &a0);
                *ap = fmaf(h[n], Cv[n], *ap);
            }
        }
        float acc = (a0 + a1) + (a2 + a3);
        float sz = zl / (1.f + __expf(-zl));
        y[row * DI + d] = __float2half_rn(fmaf(ul, Dd, acc) * sz);
    }
}

// ================= launch =================
extern "C" void kernel_launch(void* const* d_in, const int* in_sizes, int n_in,
                              void* d_out, int out_size) {
    const float* x      = (const float*)d_in[0];
    const float* ln_g   = (const float*)d_in[1];
    const float* ln_b   = (const float*)d_in[2];
    const float* W_in   = (const float*)d_in[3];
    const float* conv_w = (const float*)d_in[4];
    const float* conv_b = (const float*)d_in[5];
    const float* W_x    = (const float*)d_in[6];
    const float* W_dt   = (const float*)d_in[7];
    const float* b_dt   = (const float*)d_in[8];
    const float* A_log  = (const float*)d_in[9];
    const float* Dskip  = (const float*)d_in[10];
    const float* W_out  = (const float*)d_in[11];
    float* out = (float*)d_out;

    float *xz, *u, *dblp, *dblr, *delta, *Ssum, *hend, *hstart;
    __half *xn, *y, *uh, *ul, *dth, *dtl;
    __half *winh, *winl, *wxh, *wxl, *wdth, *wdtl, *wouth, *woutl;
    cudaGetSymbolAddress((void**)&xz, g_xz);
    cudaGetSymbolAddress((void**)&u, g_u);
    cudaGetSymbolAddress((void**)&dblp, g_dblp);
    cudaGetSymbolAddress((void**)&dblr, g_dblr);
    cudaGetSymbolAddress((void**)&delta, g_delta);
    cudaGetSymbolAddress((void**)&Ssum, g_S);
    cudaGetSymbolAddress((void**)&hend, g_hend);
    cudaGetSymbolAddress((void**)&hstart, g_hstart);
    cudaGetSymbolAddress((void**)&xn, g_xn);
    cudaGetSymbolAddress((void**)&y, g_y);
    cudaGetSymbolAddress((void**)&uh, g_u_h);    cudaGetSymbolAddress((void**)&ul, g_u_l);
    cudaGetSymbolAddress((void**)&dth, g_dt_h);  cudaGetSymbolAddress((void**)&dtl, g_dt_l);
    cudaGetSymbolAddress((void**)&winh, g_win_h);   cudaGetSymbolAddress((void**)&winl, g_win_l);
    cudaGetSymbolAddress((void**)&wxh, g_wx_h);     cudaGetSymbolAddress((void**)&wxl, g_wx_l);
    cudaGetSymbolAddress((void**)&wdth, g_wdt_h);   cudaGetSymbolAddress((void**)&wdtl, g_wdt_l);
    cudaGetSymbolAddress((void**)&wouth, g_wout_h); cudaGetSymbolAddress((void**)&woutl, g_wout_l);

    cudaFuncSetAttribute(gemm2<0>, cudaFuncAttributeMaxDynamicSharedMemorySize, SMEM2);
    cudaFuncSetAttribute(gemm2<1>, cudaFuncAttributeMaxDynamicSharedMemorySize, SMEM2);
    cudaFuncSetAttribute(gemm3<0>, cudaFuncAttributeMaxDynamicSharedMemorySize, SMEM3);
    cudaFuncSetAttribute(gemm3<2>, cudaFuncAttributeMaxDynamicSharedMemorySize, SMEM3);

    dim3 tb32(32, 8);
    // weight transpose+split: W[K,N] -> [Npad,K] fp16 hi/lo
    wtrans_kernel<<<dim3(XZW/32, DM/32), tb32>>>(W_in, winh, winl, DM, XZW, XZW);
    wtrans_kernel<<<dim3(4, DI/32), tb32>>>(W_x, wxh, wxl, DI, 96, 128);
    wtrans_kernel<<<dim3(DI/32, DT/32), tb32>>>(W_dt, wdth, wdtl, DT, DI, DI);
    wtrans_kernel<<<dim3(DM/32, DI/32), tb32>>>(W_out, wouth, woutl, DI, DM, DM);

    // 1. LayerNorm -> xn fp16
    ln_kernel<<<ROWS, 256>>>(x, ln_g, ln_b, xn);

    // 2. xz = xn @ W_in   [4096,1024]x[1024,4096]  (2-pass fp16)
    gemm2<0><<<dim3(XZW/128, ROWS/128), 256, SMEM2>>>(xn, winh, winl,
        nullptr, xz, XZW, DM, XZW, DM/32);

    // 3. conv + silu -> u (fp32 + fp16 hi/lo)
    conv_silu_kernel<<<(ROWS*DI)/256, 256>>>(xz, conv_w, conv_b, u, uh, ul);

    // 4. dbl = u @ W_x   (3-pass fp16, split-K x4)
    gemm3<0><<<dim3(1, ROWS/128, 4), 256, SMEM3>>>(uh, ul, wxh, wxl,
        nullptr, dblp, 128, DI, DBLW, (DI/32)/4, (size_t)ROWS * DBLW);

    // 5. reduce + dt split
    reduce_dbl_kernel<<<(ROWS*DBLW)/256, 256>>>(dblp, dblr, dth, dtl);

    // 6. delta = softplus(dt @ W_dt + b_dt)   (3-pass fp16)
    gemm3<2><<<dim3(DI/128, ROWS/128, 1), 256, SMEM3>>>(dth, dtl, wdth, wdtl,
        b_dt, delta, DI, DT, DI, DT/32, 0);

    // 7. chunked scan -> y fp16
    scan_pass1<<<dim3(DI/256, NC, BB), 256>>>(dblr, delta, u, A_log, Ssum, hend);
    scan_pass2<<<dim3(DI/256, BB), 256>>>(Ssum, hend, A_log, hstart);
    scan_pass3<<<dim3(DI/256, NC, BB), 256>>>(dblr, delta, u, xz, A_log, Dskip,
                                              hstart, y);

    // 8. out = x + y @ W_out   (2-pass fp16, residual)
    gemm2<1><<<dim3(DM/128, ROWS/128), 256, SMEM2>>>(y, wouth, woutl,
        x, out, DM, DI, DM, DI/32);
}

// round 7
// speedup vs baseline: 3.0620x; 1.2584x over previous
#include <cuda_runtime.h>
#include <cuda_fp16.h>
#include <cstdint>
#include <math.h>

// Shapes (fixed): B=2, L=2048, DM=1024, DI=2048, N=16, DC=4, DT=64
#define BB 2
#define LL 2048
#define DM 1024
#define DI 2048
#define NS 16
#define DC 4
#define DT 64
#define ROWS (BB*LL)          // 4096
#define XZW (2*DI)            // 4096
#define DBLW 128              // padded dbl row (dt 0..63 | B 64..79 | C 80..95 | pad)
#define CL 64                 // scan chunk length
#define NC (LL/CL)            // 32 chunks

// ================= scratch (device globals) =================
__device__ __align__(256) float g_xz[ROWS * XZW];                  // xi | z (fp32)
__device__ __align__(256) float g_u [ROWS * DI];
__device__ __align__(256) float g_dblp[4 * ROWS * DBLW];           // split-K partials
__device__ __align__(256) float g_dblr[ROWS * DBLW];               // reduced
__device__ __align__(256) float g_delta[ROWS * DI];
__device__ __align__(256) float g_S[BB * NC * DI];                 // per-chunk sum(delta)
__device__ __align__(256) float g_hend[BB * NC * NS * DI];
__device__ __align__(256) float g_hstart[BB * NC * NS * DI];
// fp16 operands
__device__ __align__(256) __half g_xn[ROWS * DM];                  // LN out (single fp16)
__device__ __align__(256) __half g_y [ROWS * DI];                  // scan out (single fp16)
__device__ __align__(256) __half g_u_h [ROWS * DI], g_u_l [ROWS * DI];
__device__ __align__(256) __half g_dt_h[ROWS * DT], g_dt_l[ROWS * DT];
__device__ __align__(256) __half g_win [XZW * DM];                 // [4096,1024] single
__device__ __align__(256) __half g_wout[DM * DI];                  // [1024,2048] single
__device__ __align__(256) __half g_wx_h [128 * DI],  g_wx_l [128 * DI];   // [128,2048]
__device__ __align__(256) __half g_wdt_h[DI * DT],   g_wdt_l[DI * DT];    // [2048,64]

__device__ __forceinline__ void split_f16(float v, __half& h, __half& l) {
    h = __float2half_rn(v);
    l = __float2half_rn(v - __half2float(h));
}

// ================= PTX helpers (baseline compute_103 ISA only) =================
__device__ __forceinline__ uint32_t smem_u32(const void* p) {
    uint32_t a;
    asm("{ .reg .u64 t; cvta.to.shared.u64 t, %1; cvt.u32.u64 %0, t; }" : "=r"(a) : "l"(p));
    return a;
}
__device__ __forceinline__ void cp_async16(uint32_t sa, const void* ga) {
    asm volatile("cp.async.cg.shared.global [%0], [%1], 16;" :: "r"(sa), "l"(ga));
}
__device__ __forceinline__ void cp_commit() {
    asm volatile("cp.async.commit_group;" ::: "memory");
}
__device__ __forceinline__ void cp_wait2() {
    asm volatile("cp.async.wait_group 2;" ::: "memory");
}
__device__ __forceinline__ void cp_wait1() {
    asm volatile("cp.async.wait_group 1;" ::: "memory");
}
__device__ __forceinline__ void cp_wait0() {
    asm volatile("cp.async.wait_group 0;" ::: "memory");
}
__device__ __forceinline__ void ldsm4(uint32_t* r, uint32_t addr) {
    asm volatile("ldmatrix.sync.aligned.m8n8.x4.shared.b16 {%0,%1,%2,%3}, [%4];"
        : "=r"(r[0]), "=r"(r[1]), "=r"(r[2]), "=r"(r[3]) : "r"(addr));
}
__device__ __forceinline__ void mma_f16(float* d, const uint32_t* a, const uint32_t* b) {
    asm volatile("mma.sync.aligned.m16n8k16.row.col.f32.f16.f16.f32 "
        "{%0,%1,%2,%3}, {%4,%5,%6,%7}, {%8,%9}, {%0,%1,%2,%3};"
        : "+f"(d[0]), "+f"(d[1]), "+f"(d[2]), "+f"(d[3])
        : "r"(a[0]), "r"(a[1]), "r"(a[2]), "r"(a[3]), "r"(b[0]), "r"(b[1]));
}
// swizzled smem byte offset for (row, 16B-chunk) in a [128 rows x 64B] tile
__device__ __forceinline__ uint32_t sw_off(int row, int chunk) {
    return (uint32_t)(row * 64 + ((chunk ^ ((row >> 1) & 3)) << 4));
}

// ================= LayerNorm -> fp16 (single) =================
__global__ void ln_kernel(const float* __restrict__ x,
                          const float* __restrict__ gam,
                          const float* __restrict__ bet,
                          __half* __restrict__ xn) {
    int row = blockIdx.x;
    const float4* xr = reinterpret_cast<const float4*>(x + (size_t)row * DM);
    int t = threadIdx.x;
    float4 v = xr[t];
    float s  = v.x + v.y + v.z + v.w;
    float ss = v.x*v.x + v.y*v.y + v.z*v.z + v.w*v.w;
    #pragma unroll
    for (int o = 16; o > 0; o >>= 1) {
        s  += __shfl_xor_sync(0xffffffff, s,  o);
        ss += __shfl_xor_sync(0xffffffff, ss, o);
    }
    __shared__ float rs[8], rss[8];
    int wid = t >> 5, lid = t & 31;
    if (lid == 0) { rs[wid] = s; rss[wid] = ss; }
    __syncthreads();
    __shared__ float smu, srstd;
    if (t == 0) {
        float ts = 0.f, tss = 0.f;
        #pragma unroll
        for (int i = 0; i < 8; i++) { ts += rs[i]; tss += rss[i]; }
        float mu = ts / (float)DM;
        float var = tss / (float)DM - mu * mu;
        smu = mu; srstd = rsqrtf(var + 1e-5f);
    }
    __syncthreads();
    float mu = smu, rstd = srstd;
    const float4* g4 = reinterpret_cast<const float4*>(gam);
    const float4* b4 = reinterpret_cast<const float4*>(bet);
    float4 gg = g4[t], bb = b4[t];
    float o0 = (v.x - mu) * rstd * gg.x + bb.x;
    float o1 = (v.y - mu) * rstd * gg.y + bb.y;
    float o2 = (v.z - mu) * rstd * gg.z + bb.z;
    float o3 = (v.w - mu) * rstd * gg.w + bb.w;
    __half2* ph = reinterpret_cast<__half2*>(xn + (size_t)row * DM);
    ph[t*2]   = __halves2half2(__float2half_rn(o0), __float2half_rn(o1));
    ph[t*2+1] = __halves2half2(__float2half_rn(o2), __float2half_rn(o3));
}

// ============ weight transpose, single fp16:  W[K,N] -> T[N,K] ============
__global__ void wtrans1_kernel(const float* __restrict__ W,
                               __half* __restrict__ Th,
                               int K, int N) {
    __shared__ float t[32][33];
    int n = blockIdx.x * 32 + threadIdx.x;
    int k0 = blockIdx.y * 32;
    #pragma unroll
    for (int i = 0; i < 4; i++) {
        int k = k0 + threadIdx.y + i * 8;
        t[threadIdx.y + i * 8][threadIdx.x] = W[(size_t)k * N + n];
    }
    __syncthreads();
    int kw = k0 + threadIdx.x;
    #pragma unroll
    for (int i = 0; i < 4; i++) {
        int nn = blockIdx.x * 32 + threadIdx.y + i * 8;
        Th[(size_t)nn * K + kw] = __float2half_rn(t[threadIdx.x][threadIdx.y + i * 8]);
    }
}

// ============ weight transpose + fp16 split:  W[K,N] -> T[Npad,K] ============
__global__ void wtrans_kernel(const float* __restrict__ W,
                              __half* __restrict__ Th,
                              __half* __restrict__ Tl,
                              int K, int N, int Npad) {
    __shared__ float t[32][33];
    int n = blockIdx.x * 32 + threadIdx.x;
    int k0 = blockIdx.y * 32;
    #pragma unroll
    for (int i = 0; i < 4; i++) {
        int k = k0 + threadIdx.y + i * 8;
        t[threadIdx.y + i * 8][threadIdx.x] = (n < N) ? W[(size_t)k * N + n] : 0.f;
    }
    __syncthreads();
    int kw = k0 + threadIdx.x;
    #pragma unroll
    for (int i = 0; i < 4; i++) {
        int nn = blockIdx.x * 32 + threadIdx.y + i * 8;
        if (nn < Npad) {
            float v = t[threadIdx.x][threadIdx.y + i * 8];
            __half h, l;
            split_f16(v, h, l);
            Th[(size_t)nn * K + kw] = h;
            Tl[(size_t)nn * K + kw] = l;
        }
    }
}

// ================= GEMM A(fp16) x B(fp16), 1 mma pass =================
// C = A @ B^T. Big GEMMs. Stage = A 8KB | B 8KB = 16KB, 3 stages.
// EPI: 0 none, 1 residual +E[row*ldc+col].
#define STG1 16384
#define SMEM1 (3 * STG1)
template<int EPI>
__global__ void __launch_bounds__(256, 2) gemm1(
    const __half* __restrict__ A, const __half* __restrict__ B,
    const float* __restrict__ E, float* __restrict__ C,
    int N, int lda, int ldc, int nkt) {
    extern __shared__ __align__(128) char sm[];
    const int tid = threadIdx.x, lane = tid & 31, wid = tid >> 5;
    const int m0 = blockIdx.y * 128, n0 = blockIdx.x * 128;
    const int wm = (wid >> 2) * 64, wn = (wid & 3) * 32;
    const uint32_t sb = smem_u32(sm);

    float d[4][4][4];
    #pragma unroll
    for (int a = 0; a < 4; a++)
        #pragma unroll
        for (int b = 0; b < 4; b++)
            #pragma unroll
            for (int c = 0; c < 4; c++) d[a][b][c] = 0.f;

    auto load_tile = [&](int kt, int stage) {
        uint32_t dst = sb + stage * STG1;
        #pragma unroll
        for (int j = 0; j < 4; j++) {
            int chunk = tid + j * 256;        // 0..1023
            int t = chunk >> 9;               // 0:A 1:B (uniform per j)
            int w = chunk & 511;
            int row = w >> 2, c = w & 3;
            const __half* src = (t == 0) ? A : B;
            int g0 = (t == 0 ? m0 : n0) + row;
            const void* gp = (const char*)(src + (size_t)g0 * lda + kt * 32) + c * 16;
            cp_async16(dst + t * 8192 + sw_off(row, c), gp);
        }
        cp_commit();
    };

    load_tile(0, 0);
    if (nkt > 1) load_tile(1, 1);

    const int lrow = lane & 15, lk = lane >> 4;
    for (int i = 0; i < nkt; i++) {
        if (i + 2 < nkt) { load_tile(i + 2, (i + 2) % 3); cp_wait2(); }
        else if (i + 1 < nkt) cp_wait1();
        else cp_wait0();
        __syncthreads();

        uint32_t base = sb + (i % 3) * STG1;
        #pragma unroll
        for (int ks = 0; ks < 2; ks++) {
            uint32_t a[4][4], bf[4][2];
            #pragma unroll
            for (int mi = 0; mi < 4; mi++)
                ldsm4(a[mi], base + sw_off(wm + mi * 16 + lrow, ks * 2 + lk));
            #pragma unroll
            for (int nj = 0; nj < 2; nj++) {
                uint32_t t4[4];
                ldsm4(t4, base + 8192 + sw_off(wn + nj * 16 + lrow, ks * 2 + lk));
                bf[nj*2][0] = t4[0]; bf[nj*2][1] = t4[2];
                bf[nj*2+1][0] = t4[1]; bf[nj*2+1][1] = t4[3];
            }
            #pragma unroll
            for (int mi = 0; mi < 4; mi++)
                #pragma unroll
                for (int ni = 0; ni < 4; ni++)
                    mma_f16(d[mi][ni], a[mi], bf[ni]);
        }
        __syncthreads();
    }

    #pragma unroll
    for (int mi = 0; mi < 4; mi++) {
        #pragma unroll
        for (int ni = 0; ni < 4; ni++) {
            int r = m0 + wm + mi * 16 + (lane >> 2);
            int col = n0 + wn + ni * 8 + (lane & 3) * 2;
            #pragma unroll
            for (int h = 0; h < 2; h++) {
                int rr = r + h * 8;
                float v0 = d[mi][ni][h*2], v1 = d[mi][ni][h*2+1];
                size_t off = (size_t)rr * ldc + col;
                if (EPI == 1) { v0 += E[off]; v1 += E[off + 1]; }
                *reinterpret_cast<float2*>(C + off) = make_float2(v0, v1);
            }
        }
    }
}

// ============ GEMM A(hi/lo) x B(hi/lo), 3 mma passes (accurate path) =========
// Stage = Ah|Al|Bh|Bl 8KB each = 32KB, 3 stages. Split-K via gridDim.z.
// EPI: 0 none, 2 softplus(v + E[col]).
#define STG3 32768
#define SMEM3 (3 * STG3)
template<int EPI>
__global__ void __launch_bounds__(256, 2) gemm3(
    const __half* __restrict__ Ah, const __half* __restrict__ Al,
    const __half* __restrict__ Bh, const __half* __restrict__ Bl,
    const float* __restrict__ E, float* __restrict__ C,
    int N, int lda, int ldc, int nkt, size_t zstride) {
    extern __shared__ __align__(128) char sm[];
    const int tid = threadIdx.x, lane = tid & 31, wid = tid >> 5;
    const int m0 = blockIdx.y * 128, n0 = blockIdx.x * 128;
    const int wm = (wid >> 2) * 64, wn = (wid & 3) * 32;
    const int kt0 = blockIdx.z * nkt;
    C += (size_t)blockIdx.z * zstride;
    const uint32_t sb = smem_u32(sm);

    float d[4][4][4];
    #pragma unroll
    for (int a = 0; a < 4; a++)
        #pragma unroll
        for (int b = 0; b < 4; b++)
            #pragma unroll
            for (int c = 0; c < 4; c++) d[a][b][c] = 0.f;

    auto load_tile = [&](int kt, int stage) {
        uint32_t dst = sb + stage * STG3;
        #pragma unroll
        for (int j = 0; j < 8; j++) {
            int chunk = tid + j * 256;
            int t = chunk >> 9;               // 0:Ah 1:Al 2:Bh 3:Bl
            int w = chunk & 511;
            int row = w >> 2, c = w & 3;
            const __half* src = (t == 0) ? Ah : (t == 1) ? Al : (t == 2) ? Bh : Bl;
            int g0 = (t < 2 ? m0 : n0) + row;
            const void* gp = (const char*)(src + (size_t)g0 * lda + (kt0 + kt) * 32) + c * 16;
            cp_async16(dst + t * 8192 + sw_off(row, c), gp);
        }
        cp_commit();
    };

    load_tile(0, 0);
    if (nkt > 1) load_tile(1, 1);

    const int lrow = lane & 15, lk = lane >> 4;
    for (int i = 0; i < nkt; i++) {
        if (i + 2 < nkt) { load_tile(i + 2, (i + 2) % 3); cp_wait2(); }
        else if (i + 1 < nkt) cp_wait1();
        else cp_wait0();
        __syncthreads();

        uint32_t base = sb + (i % 3) * STG3;
        #pragma unroll
        for (int ks = 0; ks < 2; ks++) {
            uint32_t a[4][4], bh[4][2], bl[4][2];
            #pragma unroll
            for (int mi = 0; mi < 4; mi++)
                ldsm4(a[mi], base + sw_off(wm + mi * 16 + lrow, ks * 2 + lk));
            #pragma unroll
            for (int nj = 0; nj < 2; nj++) {
                uint32_t t4[4];
                ldsm4(t4, base + 16384 + sw_off(wn + nj * 16 + lrow, ks * 2 + lk));
                bh[nj*2][0] = t4[0]; bh[nj*2][1] = t4[2];
                bh[nj*2+1][0] = t4[1]; bh[nj*2+1][1] = t4[3];
            }
            #pragma unroll
            for (int mi = 0; mi < 4; mi++)
                #pragma unroll
                for (int ni = 0; ni < 4; ni++)
                    mma_f16(d[mi][ni], a[mi], bh[ni]);
            #pragma unroll
            for (int nj = 0; nj < 2; nj++) {
                uint32_t t4[4];
                ldsm4(t4, base + 24576 + sw_off(wn + nj * 16 + lrow, ks * 2 + lk));
                bl[nj*2][0] = t4[0]; bl[nj*2][1] = t4[2];
                bl[nj*2+1][0] = t4[1]; bl[nj*2+1][1] = t4[3];
            }
            #pragma unroll
            for (int mi = 0; mi < 4; mi++)
                #pragma unroll
                for (int ni = 0; ni < 4; ni++)
                    mma_f16(d[mi][ni], a[mi], bl[ni]);
            #pragma unroll
            for (int mi = 0; mi < 4; mi++)
                ldsm4(a[mi], base + 8192 + sw_off(wm + mi * 16 + lrow, ks * 2 + lk));
            #pragma unroll
            for (int mi = 0; mi < 4; mi++)
                #pragma unroll
                for (int ni = 0; ni < 4; ni++)
                    mma_f16(d[mi][ni], a[mi], bh[ni]);
        }
        __syncthreads();
    }

    #pragma unroll
    for (int mi = 0; mi < 4; mi++) {
        #pragma unroll
        for (int ni = 0; ni < 4; ni++) {
            int r = m0 + wm + mi * 16 + (lane >> 2);
            int col = n0 + wn + ni * 8 + (lane & 3) * 2;
            if (col < N) {
                #pragma unroll
                for (int h = 0; h < 2; h++) {
                    int rr = r + h * 8;
                    float v0 = d[mi][ni][h*2], v1 = d[mi][ni][h*2+1];
                    size_t off = (size_t)rr * ldc + col;
                    if (EPI == 2) {
                        float a0 = v0 + E[col], a1 = v1 + E[col + 1];
                        v0 = (a0 > 20.f) ? a0 : log1pf(__expf(a0));
                        v1 = (a1 > 20.f) ? a1 : log1pf(__expf(a1));
                    }
                    *reinterpret_cast<float2*>(C + off) = make_float2(v0, v1);
                }
            }
        }
    }
}

// ============ reduce split-K partials -> dblr; split dt -> fp16 hi/lo ============
__global__ void reduce_dbl_kernel(const float* __restrict__ dblp,
                                  float* __restrict__ dblr,
                                  __half* __restrict__ dth,
                                  __half* __restrict__ dtl) {
    int i = blockIdx.x * 256 + threadIdx.x;
    if (i >= ROWS * DBLW) return;
    float s = dblp[i] + dblp[i + ROWS*DBLW] + dblp[i + 2*ROWS*DBLW] + dblp[i + 3*ROWS*DBLW];
    dblr[i] = s;
    int col = i & (DBLW - 1);
    if (col < DT) {
        int row = i >> 7;
        __half h, l;
        split_f16(s, h, l);
        dth[row * DT + col] = h;
        dtl[row * DT + col] = l;
    }
}

// ================= depthwise conv + SiLU -> u (fp32 + fp16 hi/lo) =================
__global__ void conv_silu_kernel(const float* __restrict__ xz,
                                 const float* __restrict__ cw,
                                 const float* __restrict__ cb,
                                 float* __restrict__ u,
                                 __half* __restrict__ uh,
                                 __half* __restrict__ ul) {
    int idx = blockIdx.x * 256 + threadIdx.x;
    if (idx >= ROWS * DI) return;
    int d = idx & (DI - 1);
    int row = idx >> 11;
    int b = row >> 11;
    int l = row & (LL - 1);
    float w0 = cw[d*DC+0], w1 = cw[d*DC+1], w2 = cw[d*DC+2], w3 = cw[d*DC+3];
    float acc = cb[d];
    size_t base = (size_t)(b * LL) * XZW + d;
    if (l >= 3) acc = fmaf(xz[base + (size_t)(l-3) * XZW], w0, acc);
    if (l >= 2) acc = fmaf(xz[base + (size_t)(l-2) * XZW], w1, acc);
    if (l >= 1) acc = fmaf(xz[base + (size_t)(l-1) * XZW], w2, acc);
    acc = fmaf(xz[base + (size_t)l * XZW], w3, acc);
    float r = acc / (1.f + __expf(-acc));
    u[idx] = r;
    __half h, l2;
    split_f16(r, h, l2);
    uh[idx] = h; ul[idx] = l2;
}

// ================= chunked parallel scan =================
__device__ __forceinline__ bool load_A(const float* __restrict__ A_log, int d, float* A) {
    bool fast = true;
    #pragma unroll
    for (int n = 0; n < NS; n++) {
        A[n] = -__expf(A_log[d * NS + n]);
        fast = fast && (fabsf(A[n] + (float)(n + 1)) < 1e-5f * (float)(n + 1));
    }
    return fast;
}

__global__ void scan_pass1(const float* __restrict__ dblr,
                           const float* __restrict__ delta,
                           const float* __restrict__ u,
                           const float* __restrict__ A_log,
                           float* __restrict__ S_out,
                           float* __restrict__ hend) {
    int d = blockIdx.x * 256 + threadIdx.x;
    int c = blockIdx.y, b = blockIdx.z;
    float A[NS];
    bool fast = load_A(A_log, d, A);
    float h[NS];
    #pragma unroll
    for (int n = 0; n < NS; n++) h[n] = 0.f;
    float S = 0.f;
    size_t rbase = (size_t)b * LL + (size_t)c * CL;
    for (int j = 0; j < CL; j++) {
        size_t row = rbase + j;
        float dl = delta[row * DI + d];
        float ul = u[row * DI + d];
        const float4* Bp = reinterpret_cast<const float4*>(dblr + row * DBLW + DT);
        float4 B0 = Bp[0], B1 = Bp[1], B2 = Bp[2], B3 = Bp[3];
        float Bv[NS] = {B0.x,B0.y,B0.z,B0.w, B1.x,B1.y,B1.z,B1.w,
                        B2.x,B2.y,B2.z,B2.w, B3.x,B3.y,B3.z,B3.w};
        S += dl;
        float su = dl * ul;
        if (fast) {
            float p = __expf(-dl), dA = p;
            #pragma unroll
            for (int n = 0; n < NS; n++) { h[n] = fmaf(dA, h[n], su * Bv[n]); dA *= p; }
        } else {
            #pragma unroll
            for (int n = 0; n < NS; n++) h[n] = fmaf(__expf(dl * A[n]), h[n], su * Bv[n]);
        }
    }
    size_t cb = (size_t)b * NC + c;
    S_out[cb * DI + d] = S;
    #pragma unroll
    for (int n = 0; n < NS; n++) hend[(cb * NS + n) * DI + d] = h[n];
}

__global__ void scan_pass2(const float* __restrict__ S_in,
                           const float* __restrict__ hend,
                           const float* __restrict__ A_log,
                           float* __restrict__ hstart) {
    int d = blockIdx.x * 256 + threadIdx.x;
    int b = blockIdx.y;
    float A[NS];
    bool fast = load_A(A_log, d, A);
    float h[NS];
    #pragma unroll
    for (int n = 0; n < NS; n++) h[n] = 0.f;
    for (int c = 0; c < NC; c++) {
        size_t cb = (size_t)b * NC + c;
        #pragma unroll
        for (int n = 0; n < NS; n++) hstart[(cb * NS + n) * DI + d] = h[n];
        float S = S_in[cb * DI + d];
        if (fast) {
            float p = __expf(-S), dA = p;
            #pragma unroll
            for (int n = 0; n < NS; n++) { h[n] = fmaf(dA, h[n], hend[(cb * NS + n) * DI + d]); dA *= p; }
        } else {
            #pragma unroll
            for (int n = 0; n < NS; n++)
                h[n] = fmaf(__expf(S * A[n]), h[n], hend[(cb * NS + n) * DI + d]);
        }
    }
}

__global__ void scan_pass3(const float* __restrict__ dblr,
                           const float* __restrict__ delta,
                           const float* __restrict__ u,
                           const float* __restrict__ xz,
                           const float* __restrict__ A_log,
                           const float* __restrict__ Dskip,
                           const float* __restrict__ hstart,
                           __half* __restrict__ y) {
    int d = blockIdx.x * 256 + threadIdx.x;
    int c = blockIdx.y, b = blockIdx.z;
    float A[NS];
    bool fast = load_A(A_log, d, A);
    float Dd = Dskip[d];
    size_t cb = (size_t)b * NC + c;
    float h[NS];
    #pragma unroll
    for (int n = 0; n < NS; n++) h[n] = hstart[(cb * NS + n) * DI + d];
    size_t rbase = (size_t)b * LL + (size_t)c * CL;
    for (int j = 0; j < CL; j++) {
        size_t row = rbase + j;
        float dl = delta[row * DI + d];
        float ul = u[row * DI + d];
        float zl = xz[row * XZW + DI + d];
        const float4* Bp = reinterpret_cast<const float4*>(dblr + row * DBLW + DT);
        float4 B0 = Bp[0], B1 = Bp[1], B2 = Bp[2], B3 = Bp[3];
        float4 C0 = Bp[4], C1 = Bp[5], C2 = Bp[6], C3 = Bp[7];
        float Bv[NS] = {B0.x,B0.y,B0.z,B0.w, B1.x,B1.y,B1.z,B1.w,
                        B2.x,B2.y,B2.z,B2.w, B3.x,B3.y,B3.z,B3.w};
        float Cv[NS] = {C0.x,C0.y,C0.z,C0.w, C1.x,C1.y,C1.z,C1.w,
                        C2.x,C2.y,C2.z,C2.w, C3.x,C3.y,C3.z,C3.w};
        float su = dl * ul;
        float a0 = 0.f, a1 = 0.f, a2 = 0.f, a3 = 0.f;
        if (fast) {
            float p = __expf(-dl), dA = p;
            #pragma unroll
            for (int n = 0; n < NS; n++) {
                h[n] = fmaf(dA, h[n], su * Bv[n]);
                float* ap = (n & 2) ? ((n & 1) ? &a3 : &a2) : ((n & 1) ? &a1 : &a0);
                *ap = fmaf(h[n], Cv[n], *ap);
                dA *= p;
            }
        } else {
            #pragma unroll
            for (int n = 0; n < NS; n++) {
                h[n] = fmaf(__expf(dl * A[n]), h[n], su * Bv[n]);
                float* ap = (n & 2) ? ((n & 1) ? &a3 : &a2) : ((n & 1) ? &a1 : &a0);
                *ap = fmaf(h[n], Cv[n], *ap);
            }
        }
        float acc = (a0 + a1) + (a2 + a3);
        float sz = zl / (1.f + __expf(-zl));
        y[row * DI + d] = __float2half_rn(fmaf(ul, Dd, acc) * sz);
    }
}

// ================= launch =================
extern "C" void kernel_launch(void* const* d_in, const int* in_sizes, int n_in,
                              void* d_out, int out_size) {
    const float* x      = (const float*)d_in[0];
    const float* ln_g   = (const float*)d_in[1];
    const float* ln_b   = (const float*)d_in[2];
    const float* W_in   = (const float*)d_in[3];
    const float* conv_w = (const float*)d_in[4];
    const float* conv_b = (const float*)d_in[5];
    const float* W_x    = (const float*)d_in[6];
    const float* W_dt   = (const float*)d_in[7];
    const float* b_dt   = (const float*)d_in[8];
    const float* A_log  = (const float*)d_in[9];
    const float* Dskip  = (const float*)d_in[10];
    const float* W_out  = (const float*)d_in[11];
    float* out = (float*)d_out;

    float *xz, *u, *dblp, *dblr, *delta, *Ssum, *hend, *hstart;
    __half *xn, *y, *uh, *ul, *dth, *dtl;
    __half *win, *wout, *wxh, *wxl, *wdth, *wdtl;
    cudaGetSymbolAddress((void**)&xz, g_xz);
    cudaGetSymbolAddress((void**)&u, g_u);
    cudaGetSymbolAddress((void**)&dblp, g_dblp);
    cudaGetSymbolAddress((void**)&dblr, g_dblr);
    cudaGetSymbolAddress((void**)&delta, g_delta);
    cudaGetSymbolAddress((void**)&Ssum, g_S);
    cudaGetSymbolAddress((void**)&hend, g_hend);
    cudaGetSymbolAddress((void**)&hstart, g_hstart);
    cudaGetSymbolAddress((void**)&xn, g_xn);
    cudaGetSymbolAddress((void**)&y, g_y);
    cudaGetSymbolAddress((void**)&uh, g_u_h);    cudaGetSymbolAddress((void**)&ul, g_u_l);
    cudaGetSymbolAddress((void**)&dth, g_dt_h);  cudaGetSymbolAddress((void**)&dtl, g_dt_l);
    cudaGetSymbolAddress((void**)&win, g_win);
    cudaGetSymbolAddress((void**)&wout, g_wout);
    cudaGetSymbolAddress((void**)&wxh, g_wx_h);     cudaGetSymbolAddress((void**)&wxl, g_wx_l);
    cudaGetSymbolAddress((void**)&wdth, g_wdt_h);   cudaGetSymbolAddress((void**)&wdtl, g_wdt_l);

    cudaFuncSetAttribute(gemm1<0>, cudaFuncAttributeMaxDynamicSharedMemorySize, SMEM1);
    cudaFuncSetAttribute(gemm1<1>, cudaFuncAttributeMaxDynamicSharedMemorySize, SMEM1);
    cudaFuncSetAttribute(gemm3<0>, cudaFuncAttributeMaxDynamicSharedMemorySize, SMEM3);
    cudaFuncSetAttribute(gemm3<2>, cudaFuncAttributeMaxDynamicSharedMemorySize, SMEM3);

    dim3 tb32(32, 8);
    // weight transpose: big GEMM weights single fp16, small ones hi/lo
    wtrans1_kernel<<<dim3(XZW/32, DM/32), tb32>>>(W_in, win, DM, XZW);
    wtrans1_kernel<<<dim3(DM/32, DI/32), tb32>>>(W_out, wout, DI, DM);
    wtrans_kernel<<<dim3(4, DI/32), tb32>>>(W_x, wxh, wxl, DI, 96, 128);
    wtrans_kernel<<<dim3(DI/32, DT/32), tb32>>>(W_dt, wdth, wdtl, DT, DI, DI);

    // 1. LayerNorm -> xn fp16
    ln_kernel<<<ROWS, 256>>>(x, ln_g, ln_b, xn);

    // 2. xz = xn @ W_in   [4096,1024]x[1024,4096]  (1-pass fp16)
    gemm1<0><<<dim3(XZW/128, ROWS/128), 256, SMEM1>>>(xn, win,
        nullptr, xz, XZW, DM, XZW, DM/32);

    // 3. conv + silu -> u (fp32 + fp16 hi/lo)
    conv_silu_kernel<<<(ROWS*DI)/256, 256>>>(xz, conv_w, conv_b, u, uh, ul);

    // 4. dbl = u @ W_x   (3-pass fp16, split-K x4)
    gemm3<0><<<dim3(1, ROWS/128, 4), 256, SMEM3>>>(uh, ul, wxh, wxl,
        nullptr, dblp, 128, DI, DBLW, (DI/32)/4, (size_t)ROWS * DBLW);

    // 5. reduce + dt split
    reduce_dbl_kernel<<<(ROWS*DBLW)/256, 256>>>(dblp, dblr, dth, dtl);

    // 6. delta = softplus(dt @ W_dt + b_dt)   (3-pass fp16)
    gemm3<2><<<dim3(DI/128, ROWS/128, 1), 256, SMEM3>>>(dth, dtl, wdth, wdtl,
        b_dt, delta, DI, DT, DI, DT/32, 0);

    // 7. chunked scan -> y fp16
    scan_pass1<<<dim3(DI/256, NC, BB), 256>>>(dblr, delta, u, A_log, Ssum, hend);
    scan_pass2<<<dim3(DI/256, BB), 256>>>(Ssum, hend, A_log, hstart);
    scan_pass3<<<dim3(DI/256, NC, BB), 256>>>(dblr, delta, u, xz, A_log, Dskip,
                                              hstart, y);

    // 8. out = x + y @ W_out   (1-pass fp16, residual)
    gemm1<1><<<dim3(DM/128, ROWS/128), 256, SMEM1>>>(y, wout,
        x, out, DM, DI, DM, DI/32);
}

// round 8
// speedup vs baseline: 3.2954x; 1.0762x over previous
#include <cuda_runtime.h>
#include <cuda_fp16.h>
#include <cstdint>
#include <math.h>

// Shapes (fixed): B=2, L=2048, DM=1024, DI=2048, N=16, DC=4, DT=64
#define BB 2
#define LL 2048
#define DM 1024
#define DI 2048
#define NS 16
#define DC 4
#define DT 64
#define ROWS (BB*LL)          // 4096
#define XZW (2*DI)            // 4096
#define DBLW 128              // padded dbl row (dt 0..63 | B 64..79 | C 80..95 | pad)
#define CL 64                 // scan chunk length
#define NC (LL/CL)            // 32 chunks

// ================= scratch (device globals) =================
__device__ __align__(256) __half g_xz[ROWS * XZW];                 // xi | z (fp16)
__device__ __align__(256) float g_dblp[4 * ROWS * DBLW];           // split-K partials
__device__ __align__(256) float g_dblr[ROWS * DBLW];               // reduced
__device__ __align__(256) float g_delta[ROWS * DI];
__device__ __align__(256) float g_S[BB * NC * DI];                 // per-chunk sum(delta)
__device__ __align__(256) float g_hend[BB * NC * NS * DI];
__device__ __align__(256) float g_hstart[BB * NC * NS * DI];
// fp16 operands
__device__ __align__(256) __half g_xn[ROWS * DM];                  // LN out
__device__ __align__(256) __half g_y [ROWS * DI];                  // scan out
__device__ __align__(256) __half g_u [ROWS * DI];                  // conv+silu out
__device__ __align__(256) __half g_dt[ROWS * DT];                  // dt (single)
__device__ __align__(256) __half g_win [XZW * DM];                 // [4096,1024] single
__device__ __align__(256) __half g_wout[DM * DI];                  // [1024,2048] single
__device__ __align__(256) __half g_wx_h [128 * DI],  g_wx_l [128 * DI];   // [128,2048]
__device__ __align__(256) __half g_wdt_h[DI * DT],   g_wdt_l[DI * DT];    // [2048,64]

__device__ __forceinline__ void split_f16(float v, __half& h, __half& l) {
    h = __float2half_rn(v);
    l = __float2half_rn(v - __half2float(h));
}

// ================= PTX helpers (baseline compute_103 ISA only) =================
__device__ __forceinline__ uint32_t smem_u32(const void* p) {
    uint32_t a;
    asm("{ .reg .u64 t; cvta.to.shared.u64 t, %1; cvt.u32.u64 %0, t; }" : "=r"(a) : "l"(p));
    return a;
}
__device__ __forceinline__ void cp_async16(uint32_t sa, const void* ga) {
    asm volatile("cp.async.cg.shared.global [%0], [%1], 16;" :: "r"(sa), "l"(ga));
}
__device__ __forceinline__ void cp_commit() {
    asm volatile("cp.async.commit_group;" ::: "memory");
}
__device__ __forceinline__ void cp_wait1() {
    asm volatile("cp.async.wait_group 1;" ::: "memory");
}
__device__ __forceinline__ void cp_wait0() {
    asm volatile("cp.async.wait_group 0;" ::: "memory");
}
__device__ __forceinline__ void ldsm4(uint32_t* r, uint32_t addr) {
    asm volatile("ldmatrix.sync.aligned.m8n8.x4.shared.b16 {%0,%1,%2,%3}, [%4];"
        : "=r"(r[0]), "=r"(r[1]), "=r"(r[2]), "=r"(r[3]) : "r"(addr));
}
__device__ __forceinline__ void mma_f16(float* d, const uint32_t* a, const uint32_t* b) {
    asm volatile("mma.sync.aligned.m16n8k16.row.col.f32.f16.f16.f32 "
        "{%0,%1,%2,%3}, {%4,%5,%6,%7}, {%8,%9}, {%0,%1,%2,%3};"
        : "+f"(d[0]), "+f"(d[1]), "+f"(d[2]), "+f"(d[3])
        : "r"(a[0]), "r"(a[1]), "r"(a[2]), "r"(a[3]), "r"(b[0]), "r"(b[1]));
}
// swizzled smem byte offset for (row, 16B-chunk) in a [128 rows x 64B] tile
__device__ __forceinline__ uint32_t sw_off(int row, int chunk) {
    return (uint32_t)(row * 64 + ((chunk ^ ((row >> 1) & 3)) << 4));
}

// ================= LayerNorm -> fp16 =================
__global__ void ln_kernel(const float* __restrict__ x,
                          const float* __restrict__ gam,
                          const float* __restrict__ bet,
                          __half* __restrict__ xn) {
    int row = blockIdx.x;
    const float4* xr = reinterpret_cast<const float4*>(x + (size_t)row * DM);
    int t = threadIdx.x;
    float4 v = xr[t];
    float s  = v.x + v.y + v.z + v.w;
    float ss = v.x*v.x + v.y*v.y + v.z*v.z + v.w*v.w;
    #pragma unroll
    for (int o = 16; o > 0; o >>= 1) {
        s  += __shfl_xor_sync(0xffffffff, s,  o);
        ss += __shfl_xor_sync(0xffffffff, ss, o);
    }
    __shared__ float rs[8], rss[8];
    int wid = t >> 5, lid = t & 31;
    if (lid == 0) { rs[wid] = s; rss[wid] = ss; }
    __syncthreads();
    __shared__ float smu, srstd;
    if (t == 0) {
        float ts = 0.f, tss = 0.f;
        #pragma unroll
        for (int i = 0; i < 8; i++) { ts += rs[i]; tss += rss[i]; }
        float mu = ts / (float)DM;
        float var = tss / (float)DM - mu * mu;
        smu = mu; srstd = rsqrtf(var + 1e-5f);
    }
    __syncthreads();
    float mu = smu, rstd = srstd;
    const float4* g4 = reinterpret_cast<const float4*>(gam);
    const float4* b4 = reinterpret_cast<const float4*>(bet);
    float4 gg = g4[t], bb = b4[t];
    float o0 = (v.x - mu) * rstd * gg.x + bb.x;
    float o1 = (v.y - mu) * rstd * gg.y + bb.y;
    float o2 = (v.z - mu) * rstd * gg.z + bb.z;
    float o3 = (v.w - mu) * rstd * gg.w + bb.w;
    __half2* ph = reinterpret_cast<__half2*>(xn + (size_t)row * DM);
    ph[t*2]   = __halves2half2(__float2half_rn(o0), __float2half_rn(o1));
    ph[t*2+1] = __halves2half2(__float2half_rn(o2), __float2half_rn(o3));
}

// ============ weight transpose, single fp16:  W[K,N] -> T[N,K] ============
__global__ void wtrans1_kernel(const float* __restrict__ W,
                               __half* __restrict__ Th,
                               int K, int N) {
    __shared__ float t[32][33];
    int n = blockIdx.x * 32 + threadIdx.x;
    int k0 = blockIdx.y * 32;
    #pragma unroll
    for (int i = 0; i < 4; i++) {
        int k = k0 + threadIdx.y + i * 8;
        t[threadIdx.y + i * 8][threadIdx.x] = W[(size_t)k * N + n];
    }
    __syncthreads();
    int kw = k0 + threadIdx.x;
    #pragma unroll
    for (int i = 0; i < 4; i++) {
        int nn = blockIdx.x * 32 + threadIdx.y + i * 8;
        Th[(size_t)nn * K + kw] = __float2half_rn(t[threadIdx.x][threadIdx.y + i * 8]);
    }
}

// ============ weight transpose + fp16 split:  W[K,N] -> T[Npad,K] ============
__global__ void wtrans_kernel(const float* __restrict__ W,
                              __half* __restrict__ Th,
                              __half* __restrict__ Tl,
                              int K, int N, int Npad) {
    __shared__ float t[32][33];
    int n = blockIdx.x * 32 + threadIdx.x;
    int k0 = blockIdx.y * 32;
    #pragma unroll
    for (int i = 0; i < 4; i++) {
        int k = k0 + threadIdx.y + i * 8;
        t[threadIdx.y + i * 8][threadIdx.x] = (n < N) ? W[(size_t)k * N + n] : 0.f;
    }
    __syncthreads();
    int kw = k0 + threadIdx.x;
    #pragma unroll
    for (int i = 0; i < 4; i++) {
        int nn = blockIdx.x * 32 + threadIdx.y + i * 8;
        if (nn < Npad) {
            float v = t[threadIdx.x][threadIdx.y + i * 8];
            __half h, l;
            split_f16(v, h, l);
            Th[(size_t)nn * K + kw] = h;
            Tl[(size_t)nn * K + kw] = l;
        }
    }
}

// ================= GEMM A(fp16) x B(fp16), 1 mma pass =================
// Stage = A 8KB | B 8KB = 16KB, 3 stages, single barrier per ktile.
// EPI 0: store fp16, EPI 1: fp32 store with residual +E.
#define STG1 16384
#define SMEM1 (3 * STG1)
template<int EPI>
__global__ void __launch_bounds__(256, 2) gemm1(
    const __half* __restrict__ A, const __half* __restrict__ B,
    const float* __restrict__ E, void* __restrict__ Cv,
    int lda, int ldc, int nkt) {
    extern __shared__ __align__(128) char sm[];
    const int tid = threadIdx.x, lane = tid & 31, wid = tid >> 5;
    const int m0 = blockIdx.y * 128, n0 = blockIdx.x * 128;
    const int wm = (wid >> 2) * 64, wn = (wid & 3) * 32;
    const uint32_t sb = smem_u32(sm);

    float d[4][4][4];
    #pragma unroll
    for (int a = 0; a < 4; a++)
        #pragma unroll
        for (int b = 0; b < 4; b++)
            #pragma unroll
            for (int c = 0; c < 4; c++) d[a][b][c] = 0.f;

    auto load_tile = [&](int kt, int stage) {
        uint32_t dst = sb + stage * STG1;
        #pragma unroll
        for (int j = 0; j < 4; j++) {
            int chunk = tid + j * 256;        // 0..1023
            int t = chunk >> 9;               // 0:A 1:B (uniform per j)
            int w = chunk & 511;
            int row = w >> 2, c = w & 3;
            const __half* src = (t == 0) ? A : B;
            int g0 = (t == 0 ? m0 : n0) + row;
            const void* gp = (const char*)(src + (size_t)g0 * lda + kt * 32) + c * 16;
            cp_async16(dst + t * 8192 + sw_off(row, c), gp);
        }
        cp_commit();
    };

    load_tile(0, 0);
    load_tile(1, 1);

    const int lrow = lane & 15, lk = lane >> 4;
    for (int i = 0; i < nkt; i++) {
        if (i + 1 < nkt) cp_wait1(); else cp_wait0();
        __syncthreads();
        if (i + 2 < nkt) load_tile(i + 2, (i + 2) % 3);

        uint32_t base = sb + (i % 3) * STG1;
        #pragma unroll
        for (int ks = 0; ks < 2; ks++) {
            uint32_t a[4][4], bf[4][2];
            #pragma unroll
            for (int mi = 0; mi < 4; mi++)
                ldsm4(a[mi], base + sw_off(wm + mi * 16 + lrow, ks * 2 + lk));
            #pragma unroll
            for (int nj = 0; nj < 2; nj++) {
                uint32_t t4[4];
                ldsm4(t4, base + 8192 + sw_off(wn + nj * 16 + lrow, ks * 2 + lk));
                bf[nj*2][0] = t4[0]; bf[nj*2][1] = t4[2];
                bf[nj*2+1][0] = t4[1]; bf[nj*2+1][1] = t4[3];
            }
            #pragma unroll
            for (int mi = 0; mi < 4; mi++)
                #pragma unroll
                for (int ni = 0; ni < 4; ni++)
                    mma_f16(d[mi][ni], a[mi], bf[ni]);
        }
    }

    #pragma unroll
    for (int mi = 0; mi < 4; mi++) {
        #pragma unroll
        for (int ni = 0; ni < 4; ni++) {
            int r = m0 + wm + mi * 16 + (lane >> 2);
            int col = n0 + wn + ni * 8 + (lane & 3) * 2;
            #pragma unroll
            for (int h = 0; h < 2; h++) {
                int rr = r + h * 8;
                float v0 = d[mi][ni][h*2], v1 = d[mi][ni][h*2+1];
                size_t off = (size_t)rr * ldc + col;
                if (EPI == 0) {
                    __half* C = (__half*)Cv;
                    *reinterpret_cast<__half2*>(C + off) =
                        __halves2half2(__float2half_rn(v0), __float2half_rn(v1));
                } else {
                    float* C = (float*)Cv;
                    v0 += E[off]; v1 += E[off + 1];
                    *reinterpret_cast<float2*>(C + off) = make_float2(v0, v1);
                }
            }
        }
    }
}

// ========== GEMM A(fp16 single) x B(fp16 hi/lo), 2 mma passes ==========
// Stage = A 8KB | Bh 8KB | Bl 8KB = 24KB, 3 stages. Split-K via gridDim.z.
// EPI: 0 none (fp32 out), 2 softplus(v + E[col]) (fp32 out).
#define STG2 24576
#define SMEM2 (3 * STG2)
template<int EPI>
__global__ void __launch_bounds__(256, 2) gemm2(
    const __half* __restrict__ A,
    const __half* __restrict__ Bh, const __half* __restrict__ Bl,
    const float* __restrict__ E, float* __restrict__ C,
    int N, int lda, int ldc, int nkt, size_t zstride) {
    extern __shared__ __align__(128) char sm[];
    const int tid = threadIdx.x, lane = tid & 31, wid = tid >> 5;
    const int m0 = blockIdx.y * 128, n0 = blockIdx.x * 128;
    const int wm = (wid >> 2) * 64, wn = (wid & 3) * 32;
    const int kt0 = blockIdx.z * nkt;
    C += (size_t)blockIdx.z * zstride;
    const uint32_t sb = smem_u32(sm);

    float d[4][4][4];
    #pragma unroll
    for (int a = 0; a < 4; a++)
        #pragma unroll
        for (int b = 0; b < 4; b++)
            #pragma unroll
            for (int c = 0; c < 4; c++) d[a][b][c] = 0.f;

    auto load_tile = [&](int kt, int stage) {
        uint32_t dst = sb + stage * STG2;
        #pragma unroll
        for (int j = 0; j < 6; j++) {
            int chunk = tid + j * 256;        // 0..1535
            int t = chunk >> 9;               // 0:A 1:Bh 2:Bl (uniform per j)
            int w = chunk & 511;
            int row = w >> 2, c = w & 3;
            const __half* src = (t == 0) ? A : (t == 1) ? Bh : Bl;
            int g0 = (t == 0 ? m0 : n0) + row;
            const void* gp = (const char*)(src + (size_t)g0 * lda + (kt0 + kt) * 32) + c * 16;
            cp_async16(dst + t * 8192 + sw_off(row, c), gp);
        }
        cp_commit();
    };

    load_tile(0, 0);
    if (nkt > 1) load_tile(1, 1);

    const int lrow = lane & 15, lk = lane >> 4;
    for (int i = 0; i < nkt; i++) {
        if (i + 1 < nkt) cp_wait1(); else cp_wait0();
        __syncthreads();
        if (i + 2 < nkt) load_tile(i + 2, (i + 2) % 3);

        uint32_t base = sb + (i % 3) * STG2;
        #pragma unroll
        for (int ks = 0; ks < 2; ks++) {
            uint32_t a[4][4], bf[4][2];
            #pragma unroll
            for (int mi = 0; mi < 4; mi++)
                ldsm4(a[mi], base + sw_off(wm + mi * 16 + lrow, ks * 2 + lk));
            #pragma unroll
            for (int nj = 0; nj < 2; nj++) {
                uint32_t t4[4];
                ldsm4(t4, base + 8192 + sw_off(wn + nj * 16 + lrow, ks * 2 + lk));
                bf[nj*2][0] = t4[0]; bf[nj*2][1] = t4[2];
                bf[nj*2+1][0] = t4[1]; bf[nj*2+1][1] = t4[3];
            }
            #pragma unroll
            for (int mi = 0; mi < 4; mi++)
                #pragma unroll
                for (int ni = 0; ni < 4; ni++)
                    mma_f16(d[mi][ni], a[mi], bf[ni]);
            #pragma unroll
            for (int nj = 0; nj < 2; nj++) {
                uint32_t t4[4];
                ldsm4(t4, base + 16384 + sw_off(wn + nj * 16 + lrow, ks * 2 + lk));
                bf[nj*2][0] = t4[0]; bf[nj*2][1] = t4[2];
                bf[nj*2+1][0] = t4[1]; bf[nj*2+1][1] = t4[3];
            }
            #pragma unroll
            for (int mi = 0; mi < 4; mi++)
                #pragma unroll
                for (int ni = 0; ni < 4; ni++)
                    mma_f16(d[mi][ni], a[mi], bf[ni]);
        }
    }

    #pragma unroll
    for (int mi = 0; mi < 4; mi++) {
        #pragma unroll
        for (int ni = 0; ni < 4; ni++) {
            int r = m0 + wm + mi * 16 + (lane >> 2);
            int col = n0 + wn + ni * 8 + (lane & 3) * 2;
            if (col < N) {
                #pragma unroll
                for (int h = 0; h < 2; h++) {
                    int rr = r + h * 8;
                    float v0 = d[mi][ni][h*2], v1 = d[mi][ni][h*2+1];
                    size_t off = (size_t)rr * ldc + col;
                    if (EPI == 2) {
                        float a0 = v0 + E[col], a1 = v1 + E[col + 1];
                        v0 = (a0 > 20.f) ? a0 : log1pf(__expf(a0));
                        v1 = (a1 > 20.f) ? a1 : log1pf(__expf(a1));
                    }
                    *reinterpret_cast<float2*>(C + off) = make_float2(v0, v1);
                }
            }
        }
    }
}

// ============ reduce split-K partials -> dblr; dt -> fp16 ============
__global__ void reduce_dbl_kernel(const float* __restrict__ dblp,
                                  float* __restrict__ dblr,
                                  __half* __restrict__ dt) {
    int i = blockIdx.x * 256 + threadIdx.x;
    if (i >= ROWS * DBLW) return;
    float s = dblp[i] + dblp[i + ROWS*DBLW] + dblp[i + 2*ROWS*DBLW] + dblp[i + 3*ROWS*DBLW];
    dblr[i] = s;
    int col = i & (DBLW - 1);
    if (col < DT) {
        int row = i >> 7;
        dt[row * DT + col] = __float2half_rn(s);
    }
}

// ================= depthwise conv + SiLU -> u (fp16) =================
__global__ void conv_silu_kernel(const __half* __restrict__ xz,
                                 const float* __restrict__ cw,
                                 const float* __restrict__ cb,
                                 __half* __restrict__ u) {
    int idx = blockIdx.x * 256 + threadIdx.x;
    if (idx >= ROWS * DI) return;
    int d = idx & (DI - 1);
    int row = idx >> 11;
    int b = row >> 11;
    int l = row & (LL - 1);
    float w0 = cw[d*DC+0], w1 = cw[d*DC+1], w2 = cw[d*DC+2], w3 = cw[d*DC+3];
    float acc = cb[d];
    size_t base = (size_t)(b * LL) * XZW + d;
    if (l >= 3) acc = fmaf(__half2float(xz[base + (size_t)(l-3) * XZW]), w0, acc);
    if (l >= 2) acc = fmaf(__half2float(xz[base + (size_t)(l-2) * XZW]), w1, acc);
    if (l >= 1) acc = fmaf(__half2float(xz[base + (size_t)(l-1) * XZW]), w2, acc);
    acc = fmaf(__half2float(xz[base + (size_t)l * XZW]), w3, acc);
    float r = acc / (1.f + __expf(-acc));
    u[idx] = __float2half_rn(r);
}

// ================= chunked parallel scan =================
__device__ __forceinline__ bool load_A(const float* __restrict__ A_log, int d, float* A) {
    bool fast = true;
    #pragma unroll
    for (int n = 0; n < NS; n++) {
        A[n] = -__expf(A_log[d * NS + n]);
        fast = fast && (fabsf(A[n] + (float)(n + 1)) < 1e-5f * (float)(n + 1));
    }
    return fast;
}

__global__ void scan_pass1(const float* __restrict__ dblr,
                           const float* __restrict__ delta,
                           const __half* __restrict__ u,
                           const float* __restrict__ A_log,
                           float* __restrict__ S_out,
                           float* __restrict__ hend) {
    int d = blockIdx.x * 256 + threadIdx.x;
    int c = blockIdx.y, b = blockIdx.z;
    float A[NS];
    bool fast = load_A(A_log, d, A);
    float h[NS];
    #pragma unroll
    for (int n = 0; n < NS; n++) h[n] = 0.f;
    float S = 0.f;
    size_t rbase = (size_t)b * LL + (size_t)c * CL;
    for (int j = 0; j < CL; j++) {
        size_t row = rbase + j;
        float dl = delta[row * DI + d];
        float ul = __half2float(u[row * DI + d]);
        const float4* Bp = reinterpret_cast<const float4*>(dblr + row * DBLW + DT);
        float4 B0 = Bp[0], B1 = Bp[1], B2 = Bp[2], B3 = Bp[3];
        float Bv[NS] = {B0.x,B0.y,B0.z,B0.w, B1.x,B1.y,B1.z,B1.w,
                        B2.x,B2.y,B2.z,B2.w, B3.x,B3.y,B3.z,B3.w};
        S += dl;
        float su = dl * ul;
        if (fast) {
            float p = __expf(-dl), dA = p;
            #pragma unroll
            for (int n = 0; n < NS; n++) { h[n] = fmaf(dA, h[n], su * Bv[n]); dA *= p; }
        } else {
            #pragma unroll
            for (int n = 0; n < NS; n++) h[n] = fmaf(__expf(dl * A[n]), h[n], su * Bv[n]);
        }
    }
    size_t cb = (size_t)b * NC + c;
    S_out[cb * DI + d] = S;
    #pragma unroll
    for (int n = 0; n < NS; n++) hend[(cb * NS + n) * DI + d] = h[n];
}

__global__ void scan_pass2(const float* __restrict__ S_in,
                           const float* __restrict__ hend,
                           const float* __restrict__ A_log,
                           float* __restrict__ hstart) {
    int d = blockIdx.x * 256 + threadIdx.x;
    int b = blockIdx.y;
    float A[NS];
    bool fast = load_A(A_log, d, A);
    float h[NS];
    #pragma unroll
    for (int n = 0; n < NS; n++) h[n] = 0.f;
    for (int c = 0; c < NC; c++) {
        size_t cb = (size_t)b * NC + c;
        #pragma unroll
        for (int n = 0; n < NS; n++) hstart[(cb * NS + n) * DI + d] = h[n];
        float S = S_in[cb * DI + d];
        if (fast) {
            float p = __expf(-S), dA = p;
            #pragma unroll
            for (int n = 0; n < NS; n++) { h[n] = fmaf(dA, h[n], hend[(cb * NS + n) * DI + d]); dA *= p; }
        } else {
            #pragma unroll
            for (int n = 0; n < NS; n++)
                h[n] = fmaf(__expf(S * A[n]), h[n], hend[(cb * NS + n) * DI + d]);
        }
    }
}

__global__ void scan_pass3(const float* __restrict__ dblr,
                           const float* __restrict__ delta,
                           const __half* __restrict__ u,
                           const __half* __restrict__ xz,
                           const float* __restrict__ A_log,
                           const float* __restrict__ Dskip,
                           const float* __restrict__ hstart,
                           __half* __restrict__ y) {
    int d = blockIdx.x * 256 + threadIdx.x;
    int c = blockIdx.y, b = blockIdx.z;
    float A[NS];
    bool fast = load_A(A_log, d, A);
    float Dd = Dskip[d];
    size_t cb = (size_t)b * NC + c;
    float h[NS];
    #pragma unroll
    for (int n = 0; n < NS; n++) h[n] = hstart[(cb * NS + n) * DI + d];
    size_t rbase = (size_t)b * LL + (size_t)c * CL;
    for (int j = 0; j < CL; j++) {
        size_t row = rbase + j;
        float dl = delta[row * DI + d];
        float ul = __half2float(u[row * DI + d]);
        float zl = __half2float(xz[row * XZW + DI + d]);
        const float4* Bp = reinterpret_cast<const float4*>(dblr + row * DBLW + DT);
        float4 B0 = Bp[0], B1 = Bp[1], B2 = Bp[2], B3 = Bp[3];
        float4 C0 = Bp[4], C1 = Bp[5], C2 = Bp[6], C3 = Bp[7];
        float Bv[NS] = {B0.x,B0.y,B0.z,B0.w, B1.x,B1.y,B1.z,B1.w,
                        B2.x,B2.y,B2.z,B2.w, B3.x,B3.y,B3.z,B3.w};
        float Cv[NS] = {C0.x,C0.y,C0.z,C0.w, C1.x,C1.y,C1.z,C1.w,
                        C2.x,C2.y,C2.z,C2.w, C3.x,C3.y,C3.z,C3.w};
        float su = dl * ul;
        float a0 = 0.f, a1 = 0.f, a2 = 0.f, a3 = 0.f;
        if (fast) {
            float p = __expf(-dl), dA = p;
            #pragma unroll
            for (int n = 0; n < NS; n++) {
                h[n] = fmaf(dA, h[n], su * Bv[n]);
                float* ap = (n & 2) ? ((n & 1) ? &a3 : &a2) : ((n & 1) ? &a1 : &a0);
                *ap = fmaf(h[n], Cv[n], *ap);
                dA *= p;
            }
        } else {
            #pragma unroll
            for (int n = 0; n < NS; n++) {
                h[n] = fmaf(__expf(dl * A[n]), h[n], su * Bv[n]);
                float* ap = (n & 2) ? ((n & 1) ? &a3 : &a2) : ((n & 1) ? &a1 : &a0);
                *ap = fmaf(h[n], Cv[n], *ap);
            }
        }
        float acc = (a0 + a1) + (a2 + a3);
        float sz = zl / (1.f + __expf(-zl));
        y[row * DI + d] = __float2half_rn(fmaf(ul, Dd, acc) * sz);
    }
}

// ================= launch =================
extern "C" void kernel_launch(void* const* d_in, const int* in_sizes, int n_in,
                              void* d_out, int out_size) {
    const float* x      = (const float*)d_in[0];
    const float* ln_g   = (const float*)d_in[1];
    const float* ln_b   = (const float*)d_in[2];
    const float* W_in   = (const float*)d_in[3];
    const float* conv_w = (const float*)d_in[4];
    const float* conv_b = (const float*)d_in[5];
    const float* W_x    = (const float*)d_in[6];
    const float* W_dt   = (const float*)d_in[7];
    const float* b_dt   = (const float*)d_in[8];
    const float* A_log  = (const float*)d_in[9];
    const float* Dskip  = (const float*)d_in[10];
    const float* W_out  = (const float*)d_in[11];
    float* out = (float*)d_out;

    float *dblp, *dblr, *delta, *Ssum, *hend, *hstart;
    __half *xz, *xn, *y, *u, *dt;
    __half *win, *wout, *wxh, *wxl, *wdth, *wdtl;
    cudaGetSymbolAddress((void**)&xz, g_xz);
    cudaGetSymbolAddress((void**)&dblp, g_dblp);
    cudaGetSymbolAddress((void**)&dblr, g_dblr);
    cudaGetSymbolAddress((void**)&delta, g_delta);
    cudaGetSymbolAddress((void**)&Ssum, g_S);
    cudaGetSymbolAddress((void**)&hend, g_hend);
    cudaGetSymbolAddress((void**)&hstart, g_hstart);
    cudaGetSymbolAddress((void**)&xn, g_xn);
    cudaGetSymbolAddress((void**)&y, g_y);
    cudaGetSymbolAddress((void**)&u, g_u);
    cudaGetSymbolAddress((void**)&dt, g_dt);
    cudaGetSymbolAddress((void**)&win, g_win);
    cudaGetSymbolAddress((void**)&wout, g_wout);
    cudaGetSymbolAddress((void**)&wxh, g_wx_h);     cudaGetSymbolAddress((void**)&wxl, g_wx_l);
    cudaGetSymbolAddress((void**)&wdth, g_wdt_h);   cudaGetSymbolAddress((void**)&wdtl, g_wdt_l);

    cudaFuncSetAttribute(gemm1<0>, cudaFuncAttributeMaxDynamicSharedMemorySize, SMEM1);
    cudaFuncSetAttribute(gemm1<1>, cudaFuncAttributeMaxDynamicSharedMemorySize, SMEM1);
    cudaFuncSetAttribute(gemm2<0>, cudaFuncAttributeMaxDynamicSharedMemorySize, SMEM2);
    cudaFuncSetAttribute(gemm2<2>, cudaFuncAttributeMaxDynamicSharedMemorySize, SMEM2);

    dim3 tb32(32, 8);
    // weight transpose: big GEMM weights single fp16, small ones hi/lo
    wtrans1_kernel<<<dim3(XZW/32, DM/32), tb32>>>(W_in, win, DM, XZW);
    wtrans1_kernel<<<dim3(DM/32, DI/32), tb32>>>(W_out, wout, DI, DM);
    wtrans_kernel<<<dim3(4, DI/32), tb32>>>(W_x, wxh, wxl, DI, 96, 128);
    wtrans_kernel<<<dim3(DI/32, DT/32), tb32>>>(W_dt, wdth, wdtl, DT, DI, DI);

    // 1. LayerNorm -> xn fp16
    ln_kernel<<<ROWS, 256>>>(x, ln_g, ln_b, xn);

    // 2. xz = xn @ W_in   [4096,1024]x[1024,4096]  (1-pass fp16, fp16 out)
    gemm1<0><<<dim3(XZW/128, ROWS/128), 256, SMEM1>>>(xn, win,
        nullptr, xz, DM, XZW, DM/32);

    // 3. conv + silu -> u fp16
    conv_silu_kernel<<<(ROWS*DI)/256, 256>>>(xz, conv_w, conv_b, u);

    // 4. dbl = u @ W_x   (2-pass: A single, B hi/lo; split-K x4)
    gemm2<0><<<dim3(1, ROWS/128, 4), 256, SMEM2>>>(u, wxh, wxl,
        nullptr, dblp, 128, DI, DBLW, (DI/32)/4, (size_t)ROWS * DBLW);

    // 5. reduce + dt
    reduce_dbl_kernel<<<(ROWS*DBLW)/256, 256>>>(dblp, dblr, dt);

    // 6. delta = softplus(dt @ W_dt + b_dt)   (2-pass)
    gemm2<2><<<dim3(DI/128, ROWS/128, 1), 256, SMEM2>>>(dt, wdth, wdtl,
        b_dt, delta, DI, DT, DI, DT/32, 0);

    // 7. chunked scan -> y fp16
    scan_pass1<<<dim3(DI/256, NC, BB), 256>>>(dblr, delta, u, A_log, Ssum, hend);
    scan_pass2<<<dim3(DI/256, BB), 256>>>(Ssum, hend, A_log, hstart);
    scan_pass3<<<dim3(DI/256, NC, BB), 256>>>(dblr, delta, u, xz, A_log, Dskip,
                                              hstart, y);

    // 8. out = x + y @ W_out   (1-pass fp16, residual)
    gemm1<1><<<dim3(DM/128, ROWS/128), 256, SMEM1>>>(y, wout,
        x, out, DI, DM, DI/32);
}

// round 9
// speedup vs baseline: 3.4957x; 1.0608x over previous
#include <cuda_runtime.h>
#include <cuda_fp16.h>
#include <cstdint>
#include <math.h>

// Shapes (fixed): B=2, L=2048, DM=1024, DI=2048, N=16, DC=4, DT=64
#define BB 2
#define LL 2048
#define DM 1024
#define DI 2048
#define NS 16
#define DC 4
#define DT 64
#define ROWS (BB*LL)          // 4096
#define XZW (2*DI)            // 4096
#define DBLW 128              // padded dbl row (dt 0..63 | B 64..79 | C 80..95 | pad)
#define CL 64                 // scan chunk length
#define NC (LL/CL)            // 32 chunks

// ================= scratch (device globals) =================
__device__ __align__(256) __half g_xz[ROWS * XZW];                 // xi | z (fp16)
__device__ __align__(256) float g_dblp[4 * ROWS * DBLW];           // split-K partials
__device__ __align__(256) float g_dblr[ROWS * DBLW];               // reduced
__device__ __align__(256) __half g_delta[ROWS * DI];               // fp16 delta
__device__ __align__(256) float g_S[BB * NC * DI];                 // per-chunk sum(delta)
__device__ __align__(256) float g_hend[BB * NC * NS * DI];
__device__ __align__(256) float g_hstart[BB * NC * NS * DI];
// fp16 operands
__device__ __align__(256) __half g_xn[ROWS * DM];                  // LN out
__device__ __align__(256) __half g_y [ROWS * DI];                  // scan out
__device__ __align__(256) __half g_u [ROWS * DI];                  // conv+silu out
__device__ __align__(256) __half g_dt[ROWS * DT];                  // dt (single)
__device__ __align__(256) __half g_win [XZW * DM];                 // [4096,1024]
__device__ __align__(256) __half g_wout[DM * DI];                  // [1024,2048]
__device__ __align__(256) __half g_wx  [128 * DI];                 // [128,2048] padded
__device__ __align__(256) __half g_wdt [DI * DT];                  // [2048,64]

// ================= PTX helpers (baseline compute_103 ISA only) =================
__device__ __forceinline__ uint32_t smem_u32(const void* p) {
    uint32_t a;
    asm("{ .reg .u64 t; cvta.to.shared.u64 t, %1; cvt.u32.u64 %0, t; }" : "=r"(a) : "l"(p));
    return a;
}
__device__ __forceinline__ void cp_async16(uint32_t sa, const void* ga) {
    asm volatile("cp.async.cg.shared.global [%0], [%1], 16;" :: "r"(sa), "l"(ga));
}
__device__ __forceinline__ void cp_commit() {
    asm volatile("cp.async.commit_group;" ::: "memory");
}
__device__ __forceinline__ void cp_wait1() {
    asm volatile("cp.async.wait_group 1;" ::: "memory");
}
__device__ __forceinline__ void cp_wait0() {
    asm volatile("cp.async.wait_group 0;" ::: "memory");
}
__device__ __forceinline__ void ldsm4(uint32_t* r, uint32_t addr) {
    asm volatile("ldmatrix.sync.aligned.m8n8.x4.shared.b16 {%0,%1,%2,%3}, [%4];"
        : "=r"(r[0]), "=r"(r[1]), "=r"(r[2]), "=r"(r[3]) : "r"(addr));
}
__device__ __forceinline__ void mma_f16(float* d, const uint32_t* a, const uint32_t* b) {
    asm volatile("mma.sync.aligned.m16n8k16.row.col.f32.f16.f16.f32 "
        "{%0,%1,%2,%3}, {%4,%5,%6,%7}, {%8,%9}, {%0,%1,%2,%3};"
        : "+f"(d[0]), "+f"(d[1]), "+f"(d[2]), "+f"(d[3])
        : "r"(a[0]), "r"(a[1]), "r"(a[2]), "r"(a[3]), "r"(b[0]), "r"(b[1]));
}
// swizzled smem byte offset for (row, 16B-chunk) in a [128 rows x 64B] tile
__device__ __forceinline__ uint32_t sw_off(int row, int chunk) {
    return (uint32_t)(row * 64 + ((chunk ^ ((row >> 1) & 3)) << 4));
}

// ================= LayerNorm -> fp16 =================
__global__ void ln_kernel(const float* __restrict__ x,
                          const float* __restrict__ gam,
                          const float* __restrict__ bet,
                          __half* __restrict__ xn) {
    int row = blockIdx.x;
    const float4* xr = reinterpret_cast<const float4*>(x + (size_t)row * DM);
    int t = threadIdx.x;
    float4 v = xr[t];
    float s  = v.x + v.y + v.z + v.w;
    float ss = v.x*v.x + v.y*v.y + v.z*v.z + v.w*v.w;
    #pragma unroll
    for (int o = 16; o > 0; o >>= 1) {
        s  += __shfl_xor_sync(0xffffffff, s,  o);
        ss += __shfl_xor_sync(0xffffffff, ss, o);
    }
    __shared__ float rs[8], rss[8];
    int wid = t >> 5, lid = t & 31;
    if (lid == 0) { rs[wid] = s; rss[wid] = ss; }
    __syncthreads();
    __shared__ float smu, srstd;
    if (t == 0) {
        float ts = 0.f, tss = 0.f;
        #pragma unroll
        for (int i = 0; i < 8; i++) { ts += rs[i]; tss += rss[i]; }
        float mu = ts / (float)DM;
        float var = tss / (float)DM - mu * mu;
        smu = mu; srstd = rsqrtf(var + 1e-5f);
    }
    __syncthreads();
    float mu = smu, rstd = srstd;
    const float4* g4 = reinterpret_cast<const float4*>(gam);
    const float4* b4 = reinterpret_cast<const float4*>(bet);
    float4 gg = g4[t], bb = b4[t];
    float o0 = (v.x - mu) * rstd * gg.x + bb.x;
    float o1 = (v.y - mu) * rstd * gg.y + bb.y;
    float o2 = (v.z - mu) * rstd * gg.z + bb.z;
    float o3 = (v.w - mu) * rstd * gg.w + bb.w;
    __half2* ph = reinterpret_cast<__half2*>(xn + (size_t)row * DM);
    ph[t*2]   = __halves2half2(__float2half_rn(o0), __float2half_rn(o1));
    ph[t*2+1] = __halves2half2(__float2half_rn(o2), __float2half_rn(o3));
}

// ============ fused weight prep: 4 transposes in one launch ============
// block ranges: [0,4096) W_in, [4096,6144) W_out, [6144,6400) W_x, [6400,6528) W_dt
__device__ __forceinline__ void trans_body(const float* __restrict__ W,
                                           __half* __restrict__ T,
                                           int K, int N, int bx, int by) {
    __shared__ float t[32][33];
    int n = bx * 32 + threadIdx.x;
    int k0 = by * 32;
    #pragma unroll
    for (int i = 0; i < 4; i++) {
        int k = k0 + threadIdx.y + i * 8;
        t[threadIdx.y + i * 8][threadIdx.x] = (n < N) ? W[(size_t)k * N + n] : 0.f;
    }
    __syncthreads();
    int kw = k0 + threadIdx.x;
    #pragma unroll
    for (int i = 0; i < 4; i++) {
        int nn = bx * 32 + threadIdx.y + i * 8;
        T[(size_t)nn * K + kw] = __float2half_rn(t[threadIdx.x][threadIdx.y + i * 8]);
    }
}

__global__ void prep_weights(const float* __restrict__ W_in,
                             const float* __restrict__ W_out,
                             const float* __restrict__ W_x,
                             const float* __restrict__ W_dt,
                             __half* __restrict__ win,
                             __half* __restrict__ wout,
                             __half* __restrict__ wx,
                             __half* __restrict__ wdt) {
    int bid = blockIdx.x;
    if (bid < 4096) {                 // W_in [1024,4096] -> win[4096,1024]
        trans_body(W_in, win, DM, XZW, bid & 127, bid >> 7);
    } else if (bid < 6144) {          // W_out [2048,1024] -> wout[1024,2048]
        int b = bid - 4096;
        trans_body(W_out, wout, DI, DM, b & 31, b >> 5);
    } else if (bid < 6400) {          // W_x [2048,96] -> wx[128,2048] (zero-pad)
        int b = bid - 6144;
        trans_body(W_x, wx, DI, 96, b & 3, b >> 2);
    } else {                          // W_dt [64,2048] -> wdt[2048,64]
        int b = bid - 6400;
        trans_body(W_dt, wdt, DT, DI, b & 63, b >> 6);
    }
}

// ================= unified fp16 GEMM, 1 mma pass =================
// C[m,n] = A[m,:] . B[n,:], A [M,lda] fp16, B [Ntile*gx, lda] fp16 K-major.
// Split-K via gridDim.z (kt0 = z*nkt, C += z*zstride).
// EPI 0: fp16 out. 1: fp32 out += E[off] (residual). 2: softplus(v+E[col]) -> fp16.
// 3: fp32 plain out.
#define STG1 16384
#define SMEM1 (3 * STG1)
template<int EPI>
__global__ void __launch_bounds__(256, 2) gemmk(
    const __half* __restrict__ A, const __half* __restrict__ B,
    const float* __restrict__ E, void* __restrict__ Cv,
    int lda, int ldc, int nkt, size_t zstride) {
    extern __shared__ __align__(128) char sm[];
    const int tid = threadIdx.x, lane = tid & 31, wid = tid >> 5;
    const int m0 = blockIdx.y * 128, n0 = blockIdx.x * 128;
    const int wm = (wid >> 2) * 64, wn = (wid & 3) * 32;
    const int kt0 = blockIdx.z * nkt;
    const size_t coff = (size_t)blockIdx.z * zstride;
    const uint32_t sb = smem_u32(sm);

    float d[4][4][4];
    #pragma unroll
    for (int a = 0; a < 4; a++)
        #pragma unroll
        for (int b = 0; b < 4; b++)
            #pragma unroll
            for (int c = 0; c < 4; c++) d[a][b][c] = 0.f;

    auto load_tile = [&](int kt, int stage) {
        uint32_t dst = sb + stage * STG1;
        #pragma unroll
        for (int j = 0; j < 4; j++) {
            int chunk = tid + j * 256;        // 0..1023
            int t = chunk >> 9;               // 0:A 1:B (uniform per j)
            int w = chunk & 511;
            int row = w >> 2, c = w & 3;
            const __half* src = (t == 0) ? A : B;
            int g0 = (t == 0 ? m0 : n0) + row;
            const void* gp = (const char*)(src + (size_t)g0 * lda + (kt0 + kt) * 32) + c * 16;
            cp_async16(dst + t * 8192 + sw_off(row, c), gp);
        }
        cp_commit();
    };

    load_tile(0, 0);
    load_tile(1, 1);

    const int lrow = lane & 15, lk = lane >> 4;
    for (int i = 0; i < nkt; i++) {
        if (i + 1 < nkt) cp_wait1(); else cp_wait0();
        __syncthreads();
        if (i + 2 < nkt) load_tile(i + 2, (i + 2) % 3);

        uint32_t base = sb + (i % 3) * STG1;
        #pragma unroll
        for (int ks = 0; ks < 2; ks++) {
            uint32_t a[4][4], bf[4][2];
            #pragma unroll
            for (int mi = 0; mi < 4; mi++)
                ldsm4(a[mi], base + sw_off(wm + mi * 16 + lrow, ks * 2 + lk));
            #pragma unroll
            for (int nj = 0; nj < 2; nj++) {
                uint32_t t4[4];
                ldsm4(t4, base + 8192 + sw_off(wn + nj * 16 + lrow, ks * 2 + lk));
                bf[nj*2][0] = t4[0]; bf[nj*2][1] = t4[2];
                bf[nj*2+1][0] = t4[1]; bf[nj*2+1][1] = t4[3];
            }
            #pragma unroll
            for (int mi = 0; mi < 4; mi++)
                #pragma unroll
                for (int ni = 0; ni < 4; ni++)
                    mma_f16(d[mi][ni], a[mi], bf[ni]);
        }
    }

    #pragma unroll
    for (int mi = 0; mi < 4; mi++) {
        #pragma unroll
        for (int ni = 0; ni < 4; ni++) {
            int r = m0 + wm + mi * 16 + (lane >> 2);
            int col = n0 + wn + ni * 8 + (lane & 3) * 2;
            #pragma unroll
            for (int h = 0; h < 2; h++) {
                int rr = r + h * 8;
                float v0 = d[mi][ni][h*2], v1 = d[mi][ni][h*2+1];
                size_t off = coff + (size_t)rr * ldc + col;
                if (EPI == 0) {
                    __half* C = (__half*)Cv;
                    *reinterpret_cast<__half2*>(C + off) =
                        __halves2half2(__float2half_rn(v0), __float2half_rn(v1));
                } else if (EPI == 1) {
                    float* C = (float*)Cv;
                    v0 += E[off]; v1 += E[off + 1];
                    *reinterpret_cast<float2*>(C + off) = make_float2(v0, v1);
                } else if (EPI == 2) {
                    float a0 = v0 + E[col], a1 = v1 + E[col + 1];
                    v0 = (a0 > 20.f) ? a0 : log1pf(__expf(a0));
                    v1 = (a1 > 20.f) ? a1 : log1pf(__expf(a1));
                    __half* C = (__half*)Cv;
                    *reinterpret_cast<__half2*>(C + off) =
                        __halves2half2(__float2half_rn(v0), __float2half_rn(v1));
                } else {
                    float* C = (float*)Cv;
                    *reinterpret_cast<float2*>(C + off) = make_float2(v0, v1);
                }
            }
        }
    }
}

// ============ reduce split-K partials -> dblr; dt -> fp16 ============
__global__ void reduce_dbl_kernel(const float* __restrict__ dblp,
                                  float* __restrict__ dblr,
                                  __half* __restrict__ dt) {
    int i = blockIdx.x * 256 + threadIdx.x;
    if (i >= ROWS * DBLW) return;
    float s = dblp[i] + dblp[i + ROWS*DBLW] + dblp[i + 2*ROWS*DBLW] + dblp[i + 3*ROWS*DBLW];
    dblr[i] = s;
    int col = i & (DBLW - 1);
    if (col < DT) {
        int row = i >> 7;
        dt[row * DT + col] = __float2half_rn(s);
    }
}

// ================= depthwise conv + SiLU -> u (fp16) =================
__global__ void conv_silu_kernel(const __half* __restrict__ xz,
                                 const float* __restrict__ cw,
                                 const float* __restrict__ cb,
                                 __half* __restrict__ u) {
    int idx = blockIdx.x * 256 + threadIdx.x;
    if (idx >= ROWS * DI) return;
    int d = idx & (DI - 1);
    int row = idx >> 11;
    int b = row >> 11;
    int l = row & (LL - 1);
    float w0 = cw[d*DC+0], w1 = cw[d*DC+1], w2 = cw[d*DC+2], w3 = cw[d*DC+3];
    float acc = cb[d];
    size_t base = (size_t)(b * LL) * XZW + d;
    if (l >= 3) acc = fmaf(__half2float(xz[base + (size_t)(l-3) * XZW]), w0, acc);
    if (l >= 2) acc = fmaf(__half2float(xz[base + (size_t)(l-2) * XZW]), w1, acc);
    if (l >= 1) acc = fmaf(__half2float(xz[base + (size_t)(l-1) * XZW]), w2, acc);
    acc = fmaf(__half2float(xz[base + (size_t)l * XZW]), w3, acc);
    float r = acc / (1.f + __expf(-acc));
    u[idx] = __float2half_rn(r);
}

// ================= chunked parallel scan =================
__device__ __forceinline__ bool load_A(const float* __restrict__ A_log, int d, float* A) {
    bool fast = true;
    #pragma unroll
    for (int n = 0; n < NS; n++) {
        A[n] = -__expf(A_log[d * NS + n]);
        fast = fast && (fabsf(A[n] + (float)(n + 1)) < 1e-5f * (float)(n + 1));
    }
    return fast;
}
// pw[k] = p^(k+1), log-depth tree
__device__ __forceinline__ void pow_tree(float p, float* pw) {
    pw[0] = p;
    #pragma unroll
    for (int k = 1; k < NS; k++) pw[k] = pw[(k - 1) >> 1] * pw[k >> 1];
}

__global__ void scan_pass1(const float* __restrict__ dblr,
                           const __half* __restrict__ delta,
                           const __half* __restrict__ u,
                           const float* __restrict__ A_log,
                           float* __restrict__ S_out,
                           float* __restrict__ hend) {
    int d = blockIdx.x * 256 + threadIdx.x;
    int c = blockIdx.y, b = blockIdx.z;
    float A[NS];
    bool fast = load_A(A_log, d, A);
    float h[NS];
    #pragma unroll
    for (int n = 0; n < NS; n++) h[n] = 0.f;
    float S = 0.f;
    size_t rbase = (size_t)b * LL + (size_t)c * CL;
    for (int j = 0; j < CL; j++) {
        size_t row = rbase + j;
        float dl = __half2float(delta[row * DI + d]);
        float ul = __half2float(u[row * DI + d]);
        const float4* Bp = reinterpret_cast<const float4*>(dblr + row * DBLW + DT);
        float4 B0 = Bp[0], B1 = Bp[1], B2 = Bp[2], B3 = Bp[3];
        float Bv[NS] = {B0.x,B0.y,B0.z,B0.w, B1.x,B1.y,B1.z,B1.w,
                        B2.x,B2.y,B2.z,B2.w, B3.x,B3.y,B3.z,B3.w};
        S += dl;
        float su = dl * ul;
        if (fast) {
            float pw[NS];
            pow_tree(__expf(-dl), pw);
            #pragma unroll
            for (int n = 0; n < NS; n++) h[n] = fmaf(pw[n], h[n], su * Bv[n]);
        } else {
            #pragma unroll
            for (int n = 0; n < NS; n++) h[n] = fmaf(__expf(dl * A[n]), h[n], su * Bv[n]);
        }
    }
    size_t cb = (size_t)b * NC + c;
    S_out[cb * DI + d] = S;
    #pragma unroll
    for (int n = 0; n < NS; n++) hend[(cb * NS + n) * DI + d] = h[n];
}

__global__ void scan_pass2(const float* __restrict__ S_in,
                           const float* __restrict__ hend,
                           const float* __restrict__ A_log,
                           float* __restrict__ hstart) {
    int d = blockIdx.x * 256 + threadIdx.x;
    int b = blockIdx.y;
    float A[NS];
    bool fast = load_A(A_log, d, A);
    float h[NS];
    #pragma unroll
    for (int n = 0; n < NS; n++) h[n] = 0.f;
    for (int c = 0; c < NC; c++) {
        size_t cb = (size_t)b * NC + c;
        #pragma unroll
        for (int n = 0; n < NS; n++) hstart[(cb * NS + n) * DI + d] = h[n];
        float S = S_in[cb * DI + d];
        if (fast) {
            float pw[NS];
            pow_tree(__expf(-S), pw);
            #pragma unroll
            for (int n = 0; n < NS; n++)
                h[n] = fmaf(pw[n], h[n], hend[(cb * NS + n) * DI + d]);
        } else {
            #pragma unroll
            for (int n = 0; n < NS; n++)
                h[n] = fmaf(__expf(S * A[n]), h[n], hend[(cb * NS + n) * DI + d]);
        }
    }
}

__global__ void scan_pass3(const float* __restrict__ dblr,
                           const __half* __restrict__ delta,
                           const __half* __restrict__ u,
                           const __half* __restrict__ xz,
                           const float* __restrict__ A_log,
                           const float* __restrict__ Dskip,
                           const float* __restrict__ hstart,
                           __half* __restrict__ y) {
    int d = blockIdx.x * 256 + threadIdx.x;
    int c = blockIdx.y, b = blockIdx.z;
    float A[NS];
    bool fast = load_A(A_log, d, A);
    float Dd = Dskip[d];
    size_t cb = (size_t)b * NC + c;
    float h[NS];
    #pragma unroll
    for (int n = 0; n < NS; n++) h[n] = hstart[(cb * NS + n) * DI + d];
    size_t rbase = (size_t)b * LL + (size_t)c * CL;
    for (int j = 0; j < CL; j++) {
        size_t row = rbase + j;
        float dl = __half2float(delta[row * DI + d]);
        float ul = __half2float(u[row * DI + d]);
        float zl = __half2float(xz[row * XZW + DI + d]);
        const float4* Bp = reinterpret_cast<const float4*>(dblr + row * DBLW + DT);
        float4 B0 = Bp[0], B1 = Bp[1], B2 = Bp[2], B3 = Bp[3];
        float4 C0 = Bp[4], C1 = Bp[5], C2 = Bp[6], C3 = Bp[7];
        float Bv[NS] = {B0.x,B0.y,B0.z,B0.w, B1.x,B1.y,B1.z,B1.w,
                        B2.x,B2.y,B2.z,B2.w, B3.x,B3.y,B3.z,B3.w};
        float Cv[NS] = {C0.x,C0.y,C0.z,C0.w, C1.x,C1.y,C1.z,C1.w,
                        C2.x,C2.y,C2.z,C2.w, C3.x,C3.y,C3.z,C3.w};
        float su = dl * ul;
        float a0 = 0.f, a1 = 0.f, a2 = 0.f, a3 = 0.f;
        if (fast) {
            float pw[NS];
            pow_tree(__expf(-dl), pw);
            #pragma unroll
            for (int n = 0; n < NS; n++) {
                h[n] = fmaf(pw[n], h[n], su * Bv[n]);
                float* ap = (n & 2) ? ((n & 1) ? &a3 : &a2) : ((n & 1) ? &a1 : &a0);
                *ap = fmaf(h[n], Cv[n], *ap);
            }
        } else {
            #pragma unroll
            for (int n = 0; n < NS; n++) {
                h[n] = fmaf(__expf(dl * A[n]), h[n], su * Bv[n]);
                float* ap = (n & 2) ? ((n & 1) ? &a3 : &a2) : ((n & 1) ? &a1 : &a0);
                *ap = fmaf(h[n], Cv[n], *ap);
            }
        }
        float acc = (a0 + a1) + (a2 + a3);
        float sz = zl / (1.f + __expf(-zl));
        y[row * DI + d] = __float2half_rn(fmaf(ul, Dd, acc) * sz);
    }
}

// ================= launch =================
extern "C" void kernel_launch(void* const* d_in, const int* in_sizes, int n_in,
                              void* d_out, int out_size) {
    const float* x      = (const float*)d_in[0];
    const float* ln_g   = (const float*)d_in[1];
    const float* ln_b   = (const float*)d_in[2];
    const float* W_in   = (const float*)d_in[3];
    const float* conv_w = (const float*)d_in[4];
    const float* conv_b = (const float*)d_in[5];
    const float* W_x    = (const float*)d_in[6];
    const float* W_dt   = (const float*)d_in[7];
    const float* b_dt   = (const float*)d_in[8];
    const float* A_log  = (const float*)d_in[9];
    const float* Dskip  = (const float*)d_in[10];
    const float* W_out  = (const float*)d_in[11];
    float* out = (float*)d_out;

    float *dblp, *dblr, *Ssum, *hend, *hstart;
    __half *xz, *xn, *y, *u, *dt, *delta;
    __half *win, *wout, *wx, *wdt;
    cudaGetSymbolAddress((void**)&xz, g_xz);
    cudaGetSymbolAddress((void**)&dblp, g_dblp);
    cudaGetSymbolAddress((void**)&dblr, g_dblr);
    cudaGetSymbolAddress((void**)&delta, g_delta);
    cudaGetSymbolAddress((void**)&Ssum, g_S);
    cudaGetSymbolAddress((void**)&hend, g_hend);
    cudaGetSymbolAddress((void**)&hstart, g_hstart);
    cudaGetSymbolAddress((void**)&xn, g_xn);
    cudaGetSymbolAddress((void**)&y, g_y);
    cudaGetSymbolAddress((void**)&u, g_u);
    cudaGetSymbolAddress((void**)&dt, g_dt);
    cudaGetSymbolAddress((void**)&win, g_win);
    cudaGetSymbolAddress((void**)&wout, g_wout);
    cudaGetSymbolAddress((void**)&wx, g_wx);
    cudaGetSymbolAddress((void**)&wdt, g_wdt);

    cudaFuncSetAttribute(gemmk<0>, cudaFuncAttributeMaxDynamicSharedMemorySize, SMEM1);
    cudaFuncSetAttribute(gemmk<1>, cudaFuncAttributeMaxDynamicSharedMemorySize, SMEM1);
    cudaFuncSetAttribute(gemmk<2>, cudaFuncAttributeMaxDynamicSharedMemorySize, SMEM1);
    cudaFuncSetAttribute(gemmk<3>, cudaFuncAttributeMaxDynamicSharedMemorySize, SMEM1);

    // 0. fused weight prep (4 transposes) + LayerNorm
    prep_weights<<<6528, dim3(32, 8)>>>(W_in, W_out, W_x, W_dt, win, wout, wx, wdt);
    ln_kernel<<<ROWS, 256>>>(x, ln_g, ln_b, xn);

    // 1. xz = xn @ W_in   [4096,1024]x[1024,4096] -> fp16
    gemmk<0><<<dim3(XZW/128, ROWS/128, 1), 256, SMEM1>>>(xn, win,
        nullptr, xz, DM, XZW, DM/32, 0);

    // 2. conv + silu -> u fp16
    conv_silu_kernel<<<(ROWS*DI)/256, 256>>>(xz, conv_w, conv_b, u);

    // 3. dbl = u @ W_x   (split-K x4 -> fp32 partials)
    gemmk<3><<<dim3(1, ROWS/128, 4), 256, SMEM1>>>(u, wx,
        nullptr, dblp, DI, DBLW, (DI/32)/4, (size_t)ROWS * DBLW);

    // 4. reduce + dt fp16
    reduce_dbl_kernel<<<(ROWS*DBLW)/256, 256>>>(dblp, dblr, dt);

    // 5. delta = softplus(dt @ W_dt + b_dt) -> fp16
    gemmk<2><<<dim3(DI/128, ROWS/128, 1), 256, SMEM1>>>(dt, wdt,
        b_dt, delta, DT, DI, DT/32, 0);

    // 6. chunked scan -> y fp16
    scan_pass1<<<dim3(DI/256, NC, BB), 256>>>(dblr, delta, u, A_log, Ssum, hend);
    scan_pass2<<<dim3(DI/256, BB), 256>>>(Ssum, hend, A_log, hstart);
    scan_pass3<<<dim3(DI/256, NC, BB), 256>>>(dblr, delta, u, xz, A_log, Dskip,
                                              hstart, y);

    // 7. out = x + y @ W_out
    gemmk<1><<<dim3(DM/128, ROWS/128, 1), 256, SMEM1>>>(y, wout,
        x, out, DI, DM, DI/32, 0);
}

// round 10
// speedup vs baseline: 3.6884x; 1.0551x over previous
#include <cuda_runtime.h>
#include <cuda_fp16.h>
#include <cstdint>
#include <math.h>

// Shapes (fixed): B=2, L=2048, DM=1024, DI=2048, N=16, DC=4, DT=64
#define BB 2
#define LL 2048
#define DM 1024
#define DI 2048
#define NS 16
#define DC 4
#define DT 64
#define ROWS (BB*LL)          // 4096
#define XZW (2*DI)            // 4096
#define DBLW 128              // padded dbl row (dt 0..63 | B 64..79 | C 80..95 | pad)
#define CL 64                 // scan chunk length
#define NC (LL/CL)            // 32 chunks
#define CRS 8                 // conv rows per thread

// ================= scratch (device globals) =================
__device__ __align__(256) __half g_xz[ROWS * XZW];                 // xi | z (fp16)
__device__ __align__(256) float g_dblp[4 * ROWS * DBLW];           // split-K partials
__device__ __align__(256) float g_dblr[ROWS * DBLW];               // reduced
__device__ __align__(256) __half g_delta[ROWS * DI];               // fp16 delta
__device__ __align__(256) float g_S[BB * NC * DI];                 // per-chunk sum(delta)
__device__ __align__(256) float g_hend[BB * NC * NS * DI];
__device__ __align__(256) float g_hstart[BB * NC * NS * DI];
// fp16 operands
__device__ __align__(256) __half g_xn[ROWS * DM];                  // LN out
__device__ __align__(256) __half g_y [ROWS * DI];                  // scan out
__device__ __align__(256) __half g_u [ROWS * DI];                  // conv+silu out
__device__ __align__(256) __half g_dt[ROWS * DT];                  // dt (single)
__device__ __align__(256) __half g_win [XZW * DM];                 // [4096,1024]
__device__ __align__(256) __half g_wout[DM * DI];                  // [1024,2048]
__device__ __align__(256) __half g_wx  [128 * DI];                 // [128,2048] padded
__device__ __align__(256) __half g_wdt [DI * DT];                  // [2048,64]

// ================= PTX helpers (baseline compute_103 ISA only) =================
__device__ __forceinline__ uint32_t smem_u32(const void* p) {
    uint32_t a;
    asm("{ .reg .u64 t; cvta.to.shared.u64 t, %1; cvt.u32.u64 %0, t; }" : "=r"(a) : "l"(p));
    return a;
}
__device__ __forceinline__ void cp_async16(uint32_t sa, const void* ga) {
    asm volatile("cp.async.cg.shared.global [%0], [%1], 16;" :: "r"(sa), "l"(ga));
}
__device__ __forceinline__ void cp_commit() {
    asm volatile("cp.async.commit_group;" ::: "memory");
}
__device__ __forceinline__ void cp_wait1() {
    asm volatile("cp.async.wait_group 1;" ::: "memory");
}
__device__ __forceinline__ void cp_wait0() {
    asm volatile("cp.async.wait_group 0;" ::: "memory");
}
__device__ __forceinline__ void ldsm4(uint32_t* r, uint32_t addr) {
    asm volatile("ldmatrix.sync.aligned.m8n8.x4.shared.b16 {%0,%1,%2,%3}, [%4];"
        : "=r"(r[0]), "=r"(r[1]), "=r"(r[2]), "=r"(r[3]) : "r"(addr));
}
__device__ __forceinline__ void mma_f16(float* d, const uint32_t* a, const uint32_t* b) {
    asm volatile("mma.sync.aligned.m16n8k16.row.col.f32.f16.f16.f32 "
        "{%0,%1,%2,%3}, {%4,%5,%6,%7}, {%8,%9}, {%0,%1,%2,%3};"
        : "+f"(d[0]), "+f"(d[1]), "+f"(d[2]), "+f"(d[3])
        : "r"(a[0]), "r"(a[1]), "r"(a[2]), "r"(a[3]), "r"(b[0]), "r"(b[1]));
}
// swizzled smem byte offset for (row, 16B-chunk) in a [128 rows x 64B] tile
__device__ __forceinline__ uint32_t sw_off(int row, int chunk) {
    return (uint32_t)(row * 64 + ((chunk ^ ((row >> 1) & 3)) << 4));
}
__device__ __forceinline__ void unpack8(uint4 v, float* f) {
    __half2 h;
    h = *reinterpret_cast<__half2*>(&v.x); f[0] = __low2float(h); f[1] = __high2float(h);
    h = *reinterpret_cast<__half2*>(&v.y); f[2] = __low2float(h); f[3] = __high2float(h);
    h = *reinterpret_cast<__half2*>(&v.z); f[4] = __low2float(h); f[5] = __high2float(h);
    h = *reinterpret_cast<__half2*>(&v.w); f[6] = __low2float(h); f[7] = __high2float(h);
}

// ============ fused weight prep (4 transposes) + LayerNorm ============
// blocks [0,4096) W_in, [4096,6144) W_out, [6144,6400) W_x, [6400,6528) W_dt,
// [6528, 6528+4096) LayerNorm rows.
__device__ __forceinline__ void trans_body(const float* __restrict__ W,
                                           __half* __restrict__ T,
                                           int K, int N, int bx, int by) {
    __shared__ float t[32][33];
    int tx = threadIdx.x & 31, ty = threadIdx.x >> 5;
    int n = bx * 32 + tx;
    int k0 = by * 32;
    #pragma unroll
    for (int i = 0; i < 4; i++) {
        int k = k0 + ty + i * 8;
        t[ty + i * 8][tx] = (n < N) ? W[(size_t)k * N + n] : 0.f;
    }
    __syncthreads();
    int kw = k0 + tx;
    #pragma unroll
    for (int i = 0; i < 4; i++) {
        int nn = bx * 32 + ty + i * 8;
        T[(size_t)nn * K + kw] = __float2half_rn(t[tx][ty + i * 8]);
    }
}

__device__ __forceinline__ void ln_body(const float* __restrict__ x,
                                        const float* __restrict__ gam,
                                        const float* __restrict__ bet,
                                        __half* __restrict__ xn, int row) {
    const float4* xr = reinterpret_cast<const float4*>(x + (size_t)row * DM);
    int t = threadIdx.x;
    float4 v = xr[t];
    float s  = v.x + v.y + v.z + v.w;
    float ss = v.x*v.x + v.y*v.y + v.z*v.z + v.w*v.w;
    #pragma unroll
    for (int o = 16; o > 0; o >>= 1) {
        s  += __shfl_xor_sync(0xffffffff, s,  o);
        ss += __shfl_xor_sync(0xffffffff, ss, o);
    }
    __shared__ float rs[8], rss[8];
    int wid = t >> 5, lid = t & 31;
    if (lid == 0) { rs[wid] = s; rss[wid] = ss; }
    __syncthreads();
    __shared__ float smu, srstd;
    if (t == 0) {
        float ts = 0.f, tss = 0.f;
        #pragma unroll
        for (int i = 0; i < 8; i++) { ts += rs[i]; tss += rss[i]; }
        float mu = ts / (float)DM;
        float var = tss / (float)DM - mu * mu;
        smu = mu; srstd = rsqrtf(var + 1e-5f);
    }
    __syncthreads();
    float mu = smu, rstd = srstd;
    const float4* g4 = reinterpret_cast<const float4*>(gam);
    const float4* b4 = reinterpret_cast<const float4*>(bet);
    float4 gg = g4[t], bb = b4[t];
    float o0 = (v.x - mu) * rstd * gg.x + bb.x;
    float o1 = (v.y - mu) * rstd * gg.y + bb.y;
    float o2 = (v.z - mu) * rstd * gg.z + bb.z;
    float o3 = (v.w - mu) * rstd * gg.w + bb.w;
    __half2* ph = reinterpret_cast<__half2*>(xn + (size_t)row * DM);
    ph[t*2]   = __halves2half2(__float2half_rn(o0), __float2half_rn(o1));
    ph[t*2+1] = __halves2half2(__float2half_rn(o2), __float2half_rn(o3));
}

__global__ void prep_kernel(const float* __restrict__ W_in,
                            const float* __restrict__ W_out,
                            const float* __restrict__ W_x,
                            const float* __restrict__ W_dt,
                            const float* __restrict__ x,
                            const float* __restrict__ ln_g,
                            const float* __restrict__ ln_b,
                            __half* __restrict__ win,
                            __half* __restrict__ wout,
                            __half* __restrict__ wx,
                            __half* __restrict__ wdt,
                            __half* __restrict__ xn) {
    int bid = blockIdx.x;
    if (bid < 4096) {                 // W_in [1024,4096] -> win[4096,1024]
        trans_body(W_in, win, DM, XZW, bid & 127, bid >> 7);
    } else if (bid < 6144) {          // W_out [2048,1024] -> wout[1024,2048]
        int b = bid - 4096;
        trans_body(W_out, wout, DI, DM, b & 31, b >> 5);
    } else if (bid < 6400) {          // W_x [2048,96] -> wx[128,2048] (zero-pad)
        int b = bid - 6144;
        trans_body(W_x, wx, DI, 96, b & 3, b >> 2);
    } else if (bid < 6528) {          // W_dt [64,2048] -> wdt[2048,64]
        int b = bid - 6400;
        trans_body(W_dt, wdt, DT, DI, b & 63, b >> 6);
    } else {                          // LayerNorm
        ln_body(x, ln_g, ln_b, xn, bid - 6528);
    }
}

// ================= unified fp16 GEMM, 1 mma pass =================
// EPI 0: fp16 out. 1: fp32 out += E[off]. 2: softplus(v+E[col]) -> fp16. 3: fp32.
#define STG1 16384
#define SMEM1 (3 * STG1)
template<int EPI>
__global__ void __launch_bounds__(256, 2) gemmk(
    const __half* __restrict__ A, const __half* __restrict__ B,
    const float* __restrict__ E, void* __restrict__ Cv,
    int lda, int ldc, int nkt, size_t zstride) {
    extern __shared__ __align__(128) char sm[];
    const int tid = threadIdx.x, lane = tid & 31, wid = tid >> 5;
    const int m0 = blockIdx.y * 128, n0 = blockIdx.x * 128;
    const int wm = (wid >> 2) * 64, wn = (wid & 3) * 32;
    const int kt0 = blockIdx.z * nkt;
    const size_t coff = (size_t)blockIdx.z * zstride;
    const uint32_t sb = smem_u32(sm);

    float d[4][4][4];
    #pragma unroll
    for (int a = 0; a < 4; a++)
        #pragma unroll
        for (int b = 0; b < 4; b++)
            #pragma unroll
            for (int c = 0; c < 4; c++) d[a][b][c] = 0.f;

    auto load_tile = [&](int kt, int stage) {
        uint32_t dst = sb + stage * STG1;
        #pragma unroll
        for (int j = 0; j < 4; j++) {
            int chunk = tid + j * 256;        // 0..1023
            int t = chunk >> 9;               // 0:A 1:B (uniform per j)
            int w = chunk & 511;
            int row = w >> 2, c = w & 3;
            const __half* src = (t == 0) ? A : B;
            int g0 = (t == 0 ? m0 : n0) + row;
            const void* gp = (const char*)(src + (size_t)g0 * lda + (kt0 + kt) * 32) + c * 16;
            cp_async16(dst + t * 8192 + sw_off(row, c), gp);
        }
        cp_commit();
    };

    load_tile(0, 0);
    load_tile(1, 1);

    const int lrow = lane & 15, lk = lane >> 4;
    for (int i = 0; i < nkt; i++) {
        if (i + 1 < nkt) cp_wait1(); else cp_wait0();
        __syncthreads();
        if (i + 2 < nkt) load_tile(i + 2, (i + 2) % 3);

        uint32_t base = sb + (i % 3) * STG1;
        #pragma unroll
        for (int ks = 0; ks < 2; ks++) {
            uint32_t a[4][4], bf[4][2];
            #pragma unroll
            for (int mi = 0; mi < 4; mi++)
                ldsm4(a[mi], base + sw_off(wm + mi * 16 + lrow, ks * 2 + lk));
            #pragma unroll
            for (int nj = 0; nj < 2; nj++) {
                uint32_t t4[4];
                ldsm4(t4, base + 8192 + sw_off(wn + nj * 16 + lrow, ks * 2 + lk));
                bf[nj*2][0] = t4[0]; bf[nj*2][1] = t4[2];
                bf[nj*2+1][0] = t4[1]; bf[nj*2+1][1] = t4[3];
            }
            #pragma unroll
            for (int mi = 0; mi < 4; mi++)
                #pragma unroll
                for (int ni = 0; ni < 4; ni++)
                    mma_f16(d[mi][ni], a[mi], bf[ni]);
        }
    }

    #pragma unroll
    for (int mi = 0; mi < 4; mi++) {
        #pragma unroll
        for (int ni = 0; ni < 4; ni++) {
            int r = m0 + wm + mi * 16 + (lane >> 2);
            int col = n0 + wn + ni * 8 + (lane & 3) * 2;
            #pragma unroll
            for (int h = 0; h < 2; h++) {
                int rr = r + h * 8;
                float v0 = d[mi][ni][h*2], v1 = d[mi][ni][h*2+1];
                size_t off = coff + (size_t)rr * ldc + col;
                if (EPI == 0) {
                    __half* C = (__half*)Cv;
                    *reinterpret_cast<__half2*>(C + off) =
                        __halves2half2(__float2half_rn(v0), __float2half_rn(v1));
                } else if (EPI == 1) {
                    float* C = (float*)Cv;
                    v0 += E[off]; v1 += E[off + 1];
                    *reinterpret_cast<float2*>(C + off) = make_float2(v0, v1);
                } else if (EPI == 2) {
                    float a0 = v0 + E[col], a1 = v1 + E[col + 1];
                    v0 = (a0 > 20.f) ? a0 : log1pf(__expf(a0));
                    v1 = (a1 > 20.f) ? a1 : log1pf(__expf(a1));
                    __half* C = (__half*)Cv;
                    *reinterpret_cast<__half2*>(C + off) =
                        __halves2half2(__float2half_rn(v0), __float2half_rn(v1));
                } else {
                    float* C = (float*)Cv;
                    *reinterpret_cast<float2*>(C + off) = make_float2(v0, v1);
                }
            }
        }
    }
}

// ============ reduce split-K partials -> dblr; dt -> fp16 ============
__global__ void reduce_dbl_kernel(const float* __restrict__ dblp,
                                  float* __restrict__ dblr,
                                  __half* __restrict__ dt) {
    int i = blockIdx.x * 256 + threadIdx.x;
    if (i >= ROWS * DBLW) return;
    float s = dblp[i] + dblp[i + ROWS*DBLW] + dblp[i + 2*ROWS*DBLW] + dblp[i + 3*ROWS*DBLW];
    dblr[i] = s;
    int col = i & (DBLW - 1);
    if (col < DT) {
        int row = i >> 7;
        dt[row * DT + col] = __float2half_rn(s);
    }
}

// ======== vectorized depthwise conv + SiLU -> u (8 ch x 8 rows / thread) ========
__global__ void conv_silu_kernel(const __half* __restrict__ xz,
                                 const float* __restrict__ cw,
                                 const float* __restrict__ cb,
                                 __half* __restrict__ u) {
    int idx = blockIdx.x * 256 + threadIdx.x;
    int ncg = DI / 8;                  // 256 channel groups
    int cg = idx & (ncg - 1);
    int strip = idx >> 8;              // 0 .. ROWS/CRS-1
    int d0 = cg * 8;
    int row0 = strip * CRS;
    int b = row0 >> 11;
    int l0 = row0 & (LL - 1);

    // weights (float4 per channel) + bias
    float w[8][4], bias[8];
    #pragma unroll
    for (int c = 0; c < 8; c++) {
        float4 wv = reinterpret_cast<const float4*>(cw)[d0 + c];
        w[c][0] = wv.x; w[c][1] = wv.y; w[c][2] = wv.z; w[c][3] = wv.w;
        bias[c] = cb[d0 + c];
    }

    size_t xbase = ((size_t)b * LL + l0) * XZW + d0;   // xz stride XZW
    size_t ubase = ((size_t)b * LL + l0) * DI + d0;    // u stride DI

    // sliding window: rows l0-3, l0-2, l0-1
    float xw[3][8];
    #pragma unroll
    for (int k = 0; k < 3; k++) {
        int lk = l0 - 3 + k;
        if (lk >= 0) {
            uint4 v = *reinterpret_cast<const uint4*>(xz + xbase + (size_t)(k - 3) * XZW);
            unpack8(v, xw[k]);
        } else {
            #pragma unroll
            for (int c = 0; c < 8; c++) xw[k][c] = 0.f;
        }
    }

    #pragma unroll
    for (int j = 0; j < CRS; j++) {
        uint4 v = *reinterpret_cast<const uint4*>(xz + xbase + (size_t)j * XZW);
        float cur[8];
        unpack8(v, cur);
        uint4 ov;
        __half2* oh = reinterpret_cast<__half2*>(&ov);
        #pragma unroll
        for (int c = 0; c < 8; c += 2) {
            float a0 = bias[c]   + xw[0][c]  *w[c][0]   + xw[1][c]  *w[c][1]   + xw[2][c]  *w[c][2]   + cur[c]  *w[c][3];
            float a1 = bias[c+1] + xw[0][c+1]*w[c+1][0] + xw[1][c+1]*w[c+1][1] + xw[2][c+1]*w[c+1][2] + cur[c+1]*w[c+1][3];
            float r0 = a0 / (1.f + __expf(-a0));
            float r1 = a1 / (1.f + __expf(-a1));
            oh[c >> 1] = __halves2half2(__float2half_rn(r0), __float2half_rn(r1));
        }
        *reinterpret_cast<uint4*>(u + ubase + (size_t)j * DI) = ov;
        #pragma unroll
        for (int c = 0; c < 8; c++) { xw[0][c] = xw[1][c]; xw[1][c] = xw[2][c]; xw[2][c] = cur[c]; }
    }
}

// ================= chunked parallel scan =================
__device__ __forceinline__ bool load_A(const float* __restrict__ A_log, int d, float* A) {
    bool fast = true;
    #pragma unroll
    for (int n = 0; n < NS; n++) {
        A[n] = -__expf(A_log[d * NS + n]);
        fast = fast && (fabsf(A[n] + (float)(n + 1)) < 1e-5f * (float)(n + 1));
    }
    return fast;
}
// pw[k] = p^(k+1), log-depth tree
__device__ __forceinline__ void pow_tree(float p, float* pw) {
    pw[0] = p;
    #pragma unroll
    for (int k = 1; k < NS; k++) pw[k] = pw[(k - 1) >> 1] * pw[k >> 1];
}

__global__ void scan_pass1(const float* __restrict__ dblr,
                           const __half* __restrict__ delta,
                           const __half* __restrict__ u,
                           const float* __restrict__ A_log,
                           float* __restrict__ S_out,
                           float* __restrict__ hend) {
    int d = blockIdx.x * 256 + threadIdx.x;
    int c = blockIdx.y, b = blockIdx.z;
    float A[NS];
    bool fast = load_A(A_log, d, A);
    float h[NS];
    #pragma unroll
    for (int n = 0; n < NS; n++) h[n] = 0.f;
    float S = 0.f;
    size_t rbase = (size_t)b * LL + (size_t)c * CL;
    for (int j = 0; j < CL; j++) {
        size_t row = rbase + j;
        float dl = __half2float(delta[row * DI + d]);
        float ul = __half2float(u[row * DI + d]);
        const float4* Bp = reinterpret_cast<const float4*>(dblr + row * DBLW + DT);
        float4 B0 = Bp[0], B1 = Bp[1], B2 = Bp[2], B3 = Bp[3];
        float Bv[NS] = {B0.x,B0.y,B0.z,B0.w, B1.x,B1.y,B1.z,B1.w,
                        B2.x,B2.y,B2.z,B2.w, B3.x,B3.y,B3.z,B3.w};
        S += dl;
        float su = dl * ul;
        if (fast) {
            float pw[NS];
            pow_tree(__expf(-dl), pw);
            #pragma unroll
            for (int n = 0; n < NS; n++) h[n] = fmaf(pw[n], h[n], su * Bv[n]);
        } else {
            #pragma unroll
            for (int n = 0; n < NS; n++) h[n] = fmaf(__expf(dl * A[n]), h[n], su * Bv[n]);
        }
    }
    size_t cb = (size_t)b * NC + c;
    S_out[cb * DI + d] = S;
    #pragma unroll
    for (int n = 0; n < NS; n++) hend[(cb * NS + n) * DI + d] = h[n];
}

__global__ void scan_pass2(const float* __restrict__ S_in,
                           const float* __restrict__ hend,
                           const float* __restrict__ A_log,
                           float* __restrict__ hstart) {
    int d = blockIdx.x * 256 + threadIdx.x;
    int b = blockIdx.y;
    float A[NS];
    bool fast = load_A(A_log, d, A);
    float h[NS];
    #pragma unroll
    for (int n = 0; n < NS; n++) h[n] = 0.f;
    for (int c = 0; c < NC; c++) {
        size_t cb = (size_t)b * NC + c;
        #pragma unroll
        for (int n = 0; n < NS; n++) hstart[(cb * NS + n) * DI + d] = h[n];
        float S = S_in[cb * DI + d];
        if (fast) {
            float pw[NS];
            pow_tree(__expf(-S), pw);
            #pragma unroll
            for (int n = 0; n < NS; n++)
                h[n] = fmaf(pw[n], h[n], hend[(cb * NS + n) * DI + d]);
        } else {
            #pragma unroll
            for (int n = 0; n < NS; n++)
                h[n] = fmaf(__expf(S * A[n]), h[n], hend[(cb * NS + n) * DI + d]);
        }
    }
}

__global__ void scan_pass3(const float* __restrict__ dblr,
                           const __half* __restrict__ delta,
                           const __half* __restrict__ u,
                           const __half* __restrict__ xz,
                           const float* __restrict__ A_log,
                           const float* __restrict__ Dskip,
                           const float* __restrict__ hstart,
                           __half* __restrict__ y) {
    int d = blockIdx.x * 256 + threadIdx.x;
    int c = blockIdx.y, b = blockIdx.z;
    float A[NS];
    bool fast = load_A(A_log, d, A);
    float Dd = Dskip[d];
    size_t cb = (size_t)b * NC + c;
    float h[NS];
    #pragma unroll
    for (int n = 0; n < NS; n++) h[n] = hstart[(cb * NS + n) * DI + d];
    size_t rbase = (size_t)b * LL + (size_t)c * CL;
    for (int j = 0; j < CL; j++) {
        size_t row = rbase + j;
        float dl = __half2float(delta[row * DI + d]);
        float ul = __half2float(u[row * DI + d]);
        float zl = __half2float(xz[row * XZW + DI + d]);
        const float4* Bp = reinterpret_cast<const float4*>(dblr + row * DBLW + DT);
        float4 B0 = Bp[0], B1 = Bp[1], B2 = Bp[2], B3 = Bp[3];
        float4 C0 = Bp[4], C1 = Bp[5], C2 = Bp[6], C3 = Bp[7];
        float Bv[NS] = {B0.x,B0.y,B0.z,B0.w, B1.x,B1.y,B1.z,B1.w,
                        B2.x,B2.y,B2.z,B2.w, B3.x,B3.y,B3.z,B3.w};
        float Cv[NS] = {C0.x,C0.y,C0.z,C0.w, C1.x,C1.y,C1.z,C1.w,
                        C2.x,C2.y,C2.z,C2.w, C3.x,C3.y,C3.z,C3.w};
        float su = dl * ul;
        float a0 = 0.f, a1 = 0.f, a2 = 0.f, a3 = 0.f;
        if (fast) {
            float pw[NS];
            pow_tree(__expf(-dl), pw);
            #pragma unroll
            for (int n = 0; n < NS; n++) {
                h[n] = fmaf(pw[n], h[n], su * Bv[n]);
                float* ap = (n & 2) ? ((n & 1) ? &a3 : &a2) : ((n & 1) ? &a1 : &a0);
                *ap = fmaf(h[n], Cv[n], *ap);
            }
        } else {
            #pragma unroll
            for (int n = 0; n < NS; n++) {
                h[n] = fmaf(__expf(dl * A[n]), h[n], su * Bv[n]);
                float* ap = (n & 2) ? ((n & 1) ? &a3 : &a2) : ((n & 1) ? &a1 : &a0);
                *ap = fmaf(h[n], Cv[n], *ap);
            }
        }
        float acc = (a0 + a1) + (a2 + a3);
        float sz = zl / (1.f + __expf(-zl));
        y[row * DI + d] = __float2half_rn(fmaf(ul, Dd, acc) * sz);
    }
}

// ================= launch =================
extern "C" void kernel_launch(void* const* d_in, const int* in_sizes, int n_in,
                              void* d_out, int out_size) {
    const float* x      = (const float*)d_in[0];
    const float* ln_g   = (const float*)d_in[1];
    const float* ln_b   = (const float*)d_in[2];
    const float* W_in   = (const float*)d_in[3];
    const float* conv_w = (const float*)d_in[4];
    const float* conv_b = (const float*)d_in[5];
    const float* W_x    = (const float*)d_in[6];
    const float* W_dt   = (const float*)d_in[7];
    const float* b_dt   = (const float*)d_in[8];
    const float* A_log  = (const float*)d_in[9];
    const float* Dskip  = (const float*)d_in[10];
    const float* W_out  = (const float*)d_in[11];
    float* out = (float*)d_out;

    float *dblp, *dblr, *Ssum, *hend, *hstart;
    __half *xz, *xn, *y, *u, *dt, *delta;
    __half *win, *wout, *wx, *wdt;
    cudaGetSymbolAddress((void**)&xz, g_xz);
    cudaGetSymbolAddress((void**)&dblp, g_dblp);
    cudaGetSymbolAddress((void**)&dblr, g_dblr);
    cudaGetSymbolAddress((void**)&delta, g_delta);
    cudaGetSymbolAddress((void**)&Ssum, g_S);
    cudaGetSymbolAddress((void**)&hend, g_hend);
    cudaGetSymbolAddress((void**)&hstart, g_hstart);
    cudaGetSymbolAddress((void**)&xn, g_xn);
    cudaGetSymbolAddress((void**)&y, g_y);
    cudaGetSymbolAddress((void**)&u, g_u);
    cudaGetSymbolAddress((void**)&dt, g_dt);
    cudaGetSymbolAddress((void**)&win, g_win);
    cudaGetSymbolAddress((void**)&wout, g_wout);
    cudaGetSymbolAddress((void**)&wx, g_wx);
    cudaGetSymbolAddress((void**)&wdt, g_wdt);

    cudaFuncSetAttribute(gemmk<0>, cudaFuncAttributeMaxDynamicSharedMemorySize, SMEM1);
    cudaFuncSetAttribute(gemmk<1>, cudaFuncAttributeMaxDynamicSharedMemorySize, SMEM1);
    cudaFuncSetAttribute(gemmk<2>, cudaFuncAttributeMaxDynamicSharedMemorySize, SMEM1);
    cudaFuncSetAttribute(gemmk<3>, cudaFuncAttributeMaxDynamicSharedMemorySize, SMEM1);

    // 0. fused weight prep (4 transposes) + LayerNorm, one launch
    prep_kernel<<<6528 + ROWS, 256>>>(W_in, W_out, W_x, W_dt, x, ln_g, ln_b,
                                      win, wout, wx, wdt, xn);

    // 1. xz = xn @ W_in   [4096,1024]x[1024,4096] -> fp16
    gemmk<0><<<dim3(XZW/128, ROWS/128, 1), 256, SMEM1>>>(xn, win,
        nullptr, xz, DM, XZW, DM/32, 0);

    // 2. conv + silu -> u fp16 (vectorized, sliding window)
    conv_silu_kernel<<<(ROWS/CRS) * (DI/8) / 256, 256>>>(xz, conv_w, conv_b, u);

    // 3. dbl = u @ W_x   (split-K x4 -> fp32 partials)
    gemmk<3><<<dim3(1, ROWS/128, 4), 256, SMEM1>>>(u, wx,
        nullptr, dblp, DI, DBLW, (DI/32)/4, (size_t)ROWS * DBLW);

    // 4. reduce + dt fp16
    reduce_dbl_kernel<<<(ROWS*DBLW)/256, 256>>>(dblp, dblr, dt);

    // 5. delta = softplus(dt @ W_dt + b_dt) -> fp16
    gemmk<2><<<dim3(DI/128, ROWS/128, 1), 256, SMEM1>>>(dt, wdt,
        b_dt, delta, DT, DI, DT/32, 0);

    // 6. chunked scan -> y fp16
    scan_pass1<<<dim3(DI/256, NC, BB), 256>>>(dblr, delta, u, A_log, Ssum, hend);
    scan_pass2<<<dim3(DI/256, BB), 256>>>(Ssum, hend, A_log, hstart);
    scan_pass3<<<dim3(DI/256, NC, BB), 256>>>(dblr, delta, u, xz, A_log, Dskip,
                                              hstart, y);

    // 7. out = x + y @ W_out
    gemmk<1><<<dim3(DM/128, ROWS/128, 1), 256, SMEM1>>>(y, wout,
        x, out, DI, DM, DI/32, 0);
}

// round 11
// speedup vs baseline: 3.9675x; 1.0757x over previous
#include <cuda_runtime.h>
#include <cuda_fp16.h>
#include <cstdint>
#include <math.h>

// Shapes (fixed): B=2, L=2048, DM=1024, DI=2048, N=16, DC=4, DT=64
#define BB 2
#define LL 2048
#define DM 1024
#define DI 2048
#define NS 16
#define DC 4
#define DT 64
#define ROWS (BB*LL)          // 4096
#define XZW (2*DI)            // 4096
#define DBLW 128              // padded dbl row (dt 0..63 | B 64..79 | C 80..95 | pad)
#define CL 64                 // scan chunk length
#define NC (LL/CL)            // 32 chunks
#define CRS 8                 // conv rows per thread

// ================= scratch (device globals) =================
__device__ __align__(256) __half g_xz[ROWS * XZW];                 // xi | z (fp16)
__device__ __align__(256) float g_dblp[4 * ROWS * DBLW];           // split-K partials
__device__ __align__(256) float g_dblr[ROWS * DBLW];               // reduced
__device__ __align__(256) __half g_delta[ROWS * DI];               // fp16 delta
__device__ __align__(256) float g_S[BB * NC * DI];                 // per-chunk sum(delta)
__device__ __align__(256) float g_hend[BB * NC * NS * DI];
__device__ __align__(256) float g_hstart[BB * NC * NS * DI];
// fp16 operands
__device__ __align__(256) __half g_xn[ROWS * DM];                  // LN out
__device__ __align__(256) __half g_y [ROWS * DI];                  // scan out
__device__ __align__(256) __half g_u [ROWS * DI];                  // conv+silu out
__device__ __align__(256) __half g_dt[ROWS * DT];                  // dt (single)
__device__ __align__(256) __half g_win [XZW * DM];                 // [4096,1024]
__device__ __align__(256) __half g_wout[DM * DI];                  // [1024,2048]
__device__ __align__(256) __half g_wx  [128 * DI];                 // [128,2048] padded
__device__ __align__(256) __half g_wdt [DI * DT];                  // [2048,64]

// ================= PTX helpers (baseline compute_103 ISA only) =================
__device__ __forceinline__ uint32_t smem_u32(const void* p) {
    uint32_t a;
    asm("{ .reg .u64 t; cvta.to.shared.u64 t, %1; cvt.u32.u64 %0, t; }" : "=r"(a) : "l"(p));
    return a;
}
__device__ __forceinline__ void cp_async16(uint32_t sa, const void* ga) {
    asm volatile("cp.async.cg.shared.global [%0], [%1], 16;" :: "r"(sa), "l"(ga));
}
__device__ __forceinline__ void cp_commit() {
    asm volatile("cp.async.commit_group;" ::: "memory");
}
__device__ __forceinline__ void cp_wait1() {
    asm volatile("cp.async.wait_group 1;" ::: "memory");
}
__device__ __forceinline__ void cp_wait0() {
    asm volatile("cp.async.wait_group 0;" ::: "memory");
}
__device__ __forceinline__ void ldsm4(uint32_t* r, uint32_t addr) {
    asm volatile("ldmatrix.sync.aligned.m8n8.x4.shared.b16 {%0,%1,%2,%3}, [%4];"
        : "=r"(r[0]), "=r"(r[1]), "=r"(r[2]), "=r"(r[3]) : "r"(addr));
}
__device__ __forceinline__ void mma_f16(float* d, const uint32_t* a, const uint32_t* b) {
    asm volatile("mma.sync.aligned.m16n8k16.row.col.f32.f16.f16.f32 "
        "{%0,%1,%2,%3}, {%4,%5,%6,%7}, {%8,%9}, {%0,%1,%2,%3};"
        : "+f"(d[0]), "+f"(d[1]), "+f"(d[2]), "+f"(d[3])
        : "r"(a[0]), "r"(a[1]), "r"(a[2]), "r"(a[3]), "r"(b[0]), "r"(b[1]));
}
// SW128 swizzled byte offset for (row, 16B-chunk c in 0..7) in a [128 x 128B] tile
__device__ __forceinline__ uint32_t sw128(int row, int c) {
    return (uint32_t)(row * 128 + ((c ^ (row & 7)) << 4));
}
__device__ __forceinline__ void unpack8(uint4 v, float* f) {
    __half2 h;
    h = *reinterpret_cast<__half2*>(&v.x); f[0] = __low2float(h); f[1] = __high2float(h);
    h = *reinterpret_cast<__half2*>(&v.y); f[2] = __low2float(h); f[3] = __high2float(h);
    h = *reinterpret_cast<__half2*>(&v.z); f[4] = __low2float(h); f[5] = __high2float(h);
    h = *reinterpret_cast<__half2*>(&v.w); f[6] = __low2float(h); f[7] = __high2float(h);
}

// ============ fused weight prep (4 transposes) + LayerNorm ============
__device__ __forceinline__ void trans_body(const float* __restrict__ W,
                                           __half* __restrict__ T,
                                           int K, int N, int bx, int by) {
    __shared__ float t[32][33];
    int tx = threadIdx.x & 31, ty = threadIdx.x >> 5;
    int n = bx * 32 + tx;
    int k0 = by * 32;
    #pragma unroll
    for (int i = 0; i < 4; i++) {
        int k = k0 + ty + i * 8;
        t[ty + i * 8][tx] = (n < N) ? W[(size_t)k * N + n] : 0.f;
    }
    __syncthreads();
    int kw = k0 + tx;
    #pragma unroll
    for (int i = 0; i < 4; i++) {
        int nn = bx * 32 + ty + i * 8;
        T[(size_t)nn * K + kw] = __float2half_rn(t[tx][ty + i * 8]);
    }
}

__device__ __forceinline__ void ln_body(const float* __restrict__ x,
                                        const float* __restrict__ gam,
                                        const float* __restrict__ bet,
                                        __half* __restrict__ xn, int row) {
    const float4* xr = reinterpret_cast<const float4*>(x + (size_t)row * DM);
    int t = threadIdx.x;
    float4 v = xr[t];
    float s  = v.x + v.y + v.z + v.w;
    float ss = v.x*v.x + v.y*v.y + v.z*v.z + v.w*v.w;
    #pragma unroll
    for (int o = 16; o > 0; o >>= 1) {
        s  += __shfl_xor_sync(0xffffffff, s,  o);
        ss += __shfl_xor_sync(0xffffffff, ss, o);
    }
    __shared__ float rs[8], rss[8];
    int wid = t >> 5, lid = t & 31;
    if (lid == 0) { rs[wid] = s; rss[wid] = ss; }
    __syncthreads();
    __shared__ float smu, srstd;
    if (t == 0) {
        float ts = 0.f, tss = 0.f;
        #pragma unroll
        for (int i = 0; i < 8; i++) { ts += rs[i]; tss += rss[i]; }
        float mu = ts / (float)DM;
        float var = tss / (float)DM - mu * mu;
        smu = mu; srstd = rsqrtf(var + 1e-5f);
    }
    __syncthreads();
    float mu = smu, rstd = srstd;
    const float4* g4 = reinterpret_cast<const float4*>(gam);
    const float4* b4 = reinterpret_cast<const float4*>(bet);
    float4 gg = g4[t], bb = b4[t];
    float o0 = (v.x - mu) * rstd * gg.x + bb.x;
    float o1 = (v.y - mu) * rstd * gg.y + bb.y;
    float o2 = (v.z - mu) * rstd * gg.z + bb.z;
    float o3 = (v.w - mu) * rstd * gg.w + bb.w;
    __half2* ph = reinterpret_cast<__half2*>(xn + (size_t)row * DM);
    ph[t*2]   = __halves2half2(__float2half_rn(o0), __float2half_rn(o1));
    ph[t*2+1] = __halves2half2(__float2half_rn(o2), __float2half_rn(o3));
}

__global__ void prep_kernel(const float* __restrict__ W_in,
                            const float* __restrict__ W_out,
                            const float* __restrict__ W_x,
                            const float* __restrict__ W_dt,
                            const float* __restrict__ x,
                            const float* __restrict__ ln_g,
                            const float* __restrict__ ln_b,
                            __half* __restrict__ win,
                            __half* __restrict__ wout,
                            __half* __restrict__ wx,
                            __half* __restrict__ wdt,
                            __half* __restrict__ xn) {
    int bid = blockIdx.x;
    if (bid < 4096) {
        trans_body(W_in, win, DM, XZW, bid & 127, bid >> 7);
    } else if (bid < 6144) {
        int b = bid - 4096;
        trans_body(W_out, wout, DI, DM, b & 31, b >> 5);
    } else if (bid < 6400) {
        int b = bid - 6144;
        trans_body(W_x, wx, DI, 96, b & 3, b >> 2);
    } else if (bid < 6528) {
        int b = bid - 6400;
        trans_body(W_dt, wdt, DT, DI, b & 63, b >> 6);
    } else {
        ln_body(x, ln_g, ln_b, xn, bid - 6528);
    }
}

// ================= unified fp16 GEMM, BK=64, 1 mma pass =================
// EPI 0: fp16 out. 1: fp32 out += E[off]. 2: softplus(v+E[col]) -> fp16. 3: fp32.
#define STG1 32768
#define SMEM1 (3 * STG1)
template<int EPI>
__global__ void __launch_bounds__(256, 2) gemmk(
    const __half* __restrict__ A, const __half* __restrict__ B,
    const float* __restrict__ E, void* __restrict__ Cv,
    int lda, int ldc, int nkt, size_t zstride) {
    extern __shared__ __align__(128) char sm[];
    const int tid = threadIdx.x, lane = tid & 31, wid = tid >> 5;
    const int m0 = blockIdx.y * 128, n0 = blockIdx.x * 128;
    const int wm = (wid >> 2) * 64, wn = (wid & 3) * 32;
    const int kt0 = blockIdx.z * nkt;
    const size_t coff = (size_t)blockIdx.z * zstride;
    const uint32_t sb = smem_u32(sm);

    float d[4][4][4];
    #pragma unroll
    for (int a = 0; a < 4; a++)
        #pragma unroll
        for (int b = 0; b < 4; b++)
            #pragma unroll
            for (int c = 0; c < 4; c++) d[a][b][c] = 0.f;

    // stage: A [128 x 64 half] 16KB, B [128 x 64 half] 16KB; 128B rows SW128.
    auto load_tile = [&](int kt, int stage) {
        uint32_t dst = sb + stage * STG1;
        #pragma unroll
        for (int j = 0; j < 8; j++) {
            int chunk = tid + j * 256;        // 0..2047
            int t = chunk >> 10;              // 0:A 1:B (uniform per j)
            int w = chunk & 1023;
            int row = w >> 3, c = w & 7;
            const __half* src = (t == 0) ? A : B;
            int g0 = (t == 0 ? m0 : n0) + row;
            const void* gp = (const char*)(src + (size_t)g0 * lda + (kt0 + kt) * 64) + c * 16;
            cp_async16(dst + t * 16384 + sw128(row, c), gp);
        }
        cp_commit();
    };

    load_tile(0, 0);
    if (nkt > 1) load_tile(1, 1);

    const int lrow = lane & 15, lk = lane >> 4;
    for (int i = 0; i < nkt; i++) {
        if (i + 1 < nkt) cp_wait1(); else cp_wait0();
        __syncthreads();
        if (i + 2 < nkt) load_tile(i + 2, (i + 2) % 3);

        uint32_t base = sb + (i % 3) * STG1;
        #pragma unroll
        for (int ks = 0; ks < 4; ks++) {
            uint32_t a[4][4], bf[4][2];
            #pragma unroll
            for (int mi = 0; mi < 4; mi++)
                ldsm4(a[mi], base + sw128(wm + mi * 16 + lrow, ks * 2 + lk));
            #pragma unroll
            for (int nj = 0; nj < 2; nj++) {
                uint32_t t4[4];
                ldsm4(t4, base + 16384 + sw128(wn + nj * 16 + lrow, ks * 2 + lk));
                bf[nj*2][0] = t4[0]; bf[nj*2][1] = t4[2];
                bf[nj*2+1][0] = t4[1]; bf[nj*2+1][1] = t4[3];
            }
            #pragma unroll
            for (int mi = 0; mi < 4; mi++)
                #pragma unroll
                for (int ni = 0; ni < 4; ni++)
                    mma_f16(d[mi][ni], a[mi], bf[ni]);
        }
    }

    #pragma unroll
    for (int mi = 0; mi < 4; mi++) {
        #pragma unroll
        for (int ni = 0; ni < 4; ni++) {
            int r = m0 + wm + mi * 16 + (lane >> 2);
            int col = n0 + wn + ni * 8 + (lane & 3) * 2;
            #pragma unroll
            for (int h = 0; h < 2; h++) {
                int rr = r + h * 8;
                float v0 = d[mi][ni][h*2], v1 = d[mi][ni][h*2+1];
                size_t off = coff + (size_t)rr * ldc + col;
                if (EPI == 0) {
                    __half* C = (__half*)Cv;
                    *reinterpret_cast<__half2*>(C + off) =
                        __halves2half2(__float2half_rn(v0), __float2half_rn(v1));
                } else if (EPI == 1) {
                    float* C = (float*)Cv;
                    v0 += E[off]; v1 += E[off + 1];
                    *reinterpret_cast<float2*>(C + off) = make_float2(v0, v1);
                } else if (EPI == 2) {
                    float a0 = v0 + E[col], a1 = v1 + E[col + 1];
                    v0 = (a0 > 20.f) ? a0 : log1pf(__expf(a0));
                    v1 = (a1 > 20.f) ? a1 : log1pf(__expf(a1));
                    __half* C = (__half*)Cv;
                    *reinterpret_cast<__half2*>(C + off) =
                        __halves2half2(__float2half_rn(v0), __float2half_rn(v1));
                } else {
                    float* C = (float*)Cv;
                    *reinterpret_cast<float2*>(C + off) = make_float2(v0, v1);
                }
            }
        }
    }
}

// ============ reduce split-K partials -> dblr; dt -> fp16 ============
__global__ void reduce_dbl_kernel(const float* __restrict__ dblp,
                                  float* __restrict__ dblr,
                                  __half* __restrict__ dt) {
    int i = blockIdx.x * 256 + threadIdx.x;
    if (i >= ROWS * DBLW) return;
    float s = dblp[i] + dblp[i + ROWS*DBLW] + dblp[i + 2*ROWS*DBLW] + dblp[i + 3*ROWS*DBLW];
    dblr[i] = s;
    int col = i & (DBLW - 1);
    if (col < DT) {
        int row = i >> 7;
        dt[row * DT + col] = __float2half_rn(s);
    }
}

// ======== vectorized depthwise conv + SiLU -> u (8 ch x 8 rows / thread) ========
__global__ void conv_silu_kernel(const __half* __restrict__ xz,
                                 const float* __restrict__ cw,
                                 const float* __restrict__ cb,
                                 __half* __restrict__ u) {
    int idx = blockIdx.x * 256 + threadIdx.x;
    int ncg = DI / 8;                  // 256 channel groups
    int cg = idx & (ncg - 1);
    int strip = idx >> 8;              // 0 .. ROWS/CRS-1
    int d0 = cg * 8;
    int row0 = strip * CRS;
    int b = row0 >> 11;
    int l0 = row0 & (LL - 1);

    float w[8][4], bias[8];
    #pragma unroll
    for (int c = 0; c < 8; c++) {
        float4 wv = reinterpret_cast<const float4*>(cw)[d0 + c];
        w[c][0] = wv.x; w[c][1] = wv.y; w[c][2] = wv.z; w[c][3] = wv.w;
        bias[c] = cb[d0 + c];
    }

    size_t xbase = ((size_t)b * LL + l0) * XZW + d0;
    size_t ubase = ((size_t)b * LL + l0) * DI + d0;

    float xw[3][8];
    #pragma unroll
    for (int k = 0; k < 3; k++) {
        int lk = l0 - 3 + k;
        if (lk >= 0) {
            uint4 v = *reinterpret_cast<const uint4*>(xz + xbase + (size_t)(k - 3) * XZW);
            unpack8(v, xw[k]);
        } else {
            #pragma unroll
            for (int c = 0; c < 8; c++) xw[k][c] = 0.f;
        }
    }

    #pragma unroll
    for (int j = 0; j < CRS; j++) {
        uint4 v = *reinterpret_cast<const uint4*>(xz + xbase + (size_t)j * XZW);
        float cur[8];
        unpack8(v, cur);
        uint4 ov;
        __half2* oh = reinterpret_cast<__half2*>(&ov);
        #pragma unroll
        for (int c = 0; c < 8; c += 2) {
            float a0 = bias[c]   + xw[0][c]  *w[c][0]   + xw[1][c]  *w[c][1]   + xw[2][c]  *w[c][2]   + cur[c]  *w[c][3];
            float a1 = bias[c+1] + xw[0][c+1]*w[c+1][0] + xw[1][c+1]*w[c+1][1] + xw[2][c+1]*w[c+1][2] + cur[c+1]*w[c+1][3];
            float r0 = a0 / (1.f + __expf(-a0));
            float r1 = a1 / (1.f + __expf(-a1));
            oh[c >> 1] = __halves2half2(__float2half_rn(r0), __float2half_rn(r1));
        }
        *reinterpret_cast<uint4*>(u + ubase + (size_t)j * DI) = ov;
        #pragma unroll
        for (int c = 0; c < 8; c++) { xw[0][c] = xw[1][c]; xw[1][c] = xw[2][c]; xw[2][c] = cur[c]; }
    }
}

// ================= chunked parallel scan =================
__device__ __forceinline__ bool load_A(const float* __restrict__ A_log, int d, float* A) {
    bool fast = true;
    #pragma unroll
    for (int n = 0; n < NS; n++) {
        A[n] = -__expf(A_log[d * NS + n]);
        fast = fast && (fabsf(A[n] + (float)(n + 1)) < 1e-5f * (float)(n + 1));
    }
    return fast;
}
__device__ __forceinline__ void pow_tree(float p, float* pw) {
    pw[0] = p;
    #pragma unroll
    for (int k = 1; k < NS; k++) pw[k] = pw[(k - 1) >> 1] * pw[k >> 1];
}

__global__ void scan_pass1(const float* __restrict__ dblr,
                           const __half* __restrict__ delta,
                           const __half* __restrict__ u,
                           const float* __restrict__ A_log,
                           float* __restrict__ S_out,
                           float* __restrict__ hend) {
    int d = blockIdx.x * 256 + threadIdx.x;
    int c = blockIdx.y, b = blockIdx.z;
    float A[NS];
    bool fast = load_A(A_log, d, A);
    float h[NS];
    #pragma unroll
    for (int n = 0; n < NS; n++) h[n] = 0.f;
    float S = 0.f;
    size_t rbase = (size_t)b * LL + (size_t)c * CL;
    for (int j = 0; j < CL; j++) {
        size_t row = rbase + j;
        float dl = __half2float(delta[row * DI + d]);
        float ul = __half2float(u[row * DI + d]);
        const float4* Bp = reinterpret_cast<const float4*>(dblr + row * DBLW + DT);
        float4 B0 = Bp[0], B1 = Bp[1], B2 = Bp[2], B3 = Bp[3];
        float Bv[NS] = {B0.x,B0.y,B0.z,B0.w, B1.x,B1.y,B1.z,B1.w,
                        B2.x,B2.y,B2.z,B2.w, B3.x,B3.y,B3.z,B3.w};
        S += dl;
        float su = dl * ul;
        if (fast) {
            float pw[NS];
            pow_tree(__expf(-dl), pw);
            #pragma unroll
            for (int n = 0; n < NS; n++) h[n] = fmaf(pw[n], h[n], su * Bv[n]);
        } else {
            #pragma unroll
            for (int n = 0; n < NS; n++) h[n] = fmaf(__expf(dl * A[n]), h[n], su * Bv[n]);
        }
    }
    size_t cb = (size_t)b * NC + c;
    S_out[cb * DI + d] = S;
    #pragma unroll
    for (int n = 0; n < NS; n++) hend[(cb * NS + n) * DI + d] = h[n];
}

__global__ void scan_pass2(const float* __restrict__ S_in,
                           const float* __restrict__ hend,
                           const float* __restrict__ A_log,
                           float* __restrict__ hstart) {
    int d = blockIdx.x * 256 + threadIdx.x;
    int b = blockIdx.y;
    float A[NS];
    bool fast = load_A(A_log, d, A);
    float h[NS];
    #pragma unroll
    for (int n = 0; n < NS; n++) h[n] = 0.f;
    for (int c = 0; c < NC; c++) {
        size_t cb = (size_t)b * NC + c;
        #pragma unroll
        for (int n = 0; n < NS; n++) hstart[(cb * NS + n) * DI + d] = h[n];
        float S = S_in[cb * DI + d];
        if (fast) {
            float pw[NS];
            pow_tree(__expf(-S), pw);
            #pragma unroll
            for (int n = 0; n < NS; n++)
                h[n] = fmaf(pw[n], h[n], hend[(cb * NS + n) * DI + d]);
        } else {
            #pragma unroll
            for (int n = 0; n < NS; n++)
                h[n] = fmaf(__expf(S * A[n]), h[n], hend[(cb * NS + n) * DI + d]);
        }
    }
}

__global__ void scan_pass3(const float* __restrict__ dblr,
                           const __half* __restrict__ delta,
                           const __half* __restrict__ u,
                           const __half* __restrict__ xz,
                           const float* __restrict__ A_log,
                           const float* __restrict__ Dskip,
                           const float* __restrict__ hstart,
                           __half* __restrict__ y) {
    int d = blockIdx.x * 256 + threadIdx.x;
    int c = blockIdx.y, b = blockIdx.z;
    float A[NS];
    bool fast = load_A(A_log, d, A);
    float Dd = Dskip[d];
    size_t cb = (size_t)b * NC + c;
    float h[NS];
    #pragma unroll
    for (int n = 0; n < NS; n++) h[n] = hstart[(cb * NS + n) * DI + d];
    size_t rbase = (size_t)b * LL + (size_t)c * CL;
    for (int j = 0; j < CL; j++) {
        size_t row = rbase + j;
        float dl = __half2float(delta[row * DI + d]);
        float ul = __half2float(u[row * DI + d]);
        float zl = __half2float(xz[row * XZW + DI + d]);
        const float4* Bp = reinterpret_cast<const float4*>(dblr + row * DBLW + DT);
        float4 B0 = Bp[0], B1 = Bp[1], B2 = Bp[2], B3 = Bp[3];
        float4 C0 = Bp[4], C1 = Bp[5], C2 = Bp[6], C3 = Bp[7];
        float Bv[NS] = {B0.x,B0.y,B0.z,B0.w, B1.x,B1.y,B1.z,B1.w,
                        B2.x,B2.y,B2.z,B2.w, B3.x,B3.y,B3.z,B3.w};
        float Cv[NS] = {C0.x,C0.y,C0.z,C0.w, C1.x,C1.y,C1.z,C1.w,
                        C2.x,C2.y,C2.z,C2.w, C3.x,C3.y,C3.z,C3.w};
        float su = dl * ul;
        float a0 = 0.f, a1 = 0.f, a2 = 0.f, a3 = 0.f;
        if (fast) {
            float pw[NS];
            pow_tree(__expf(-dl), pw);
            #pragma unroll
            for (int n = 0; n < NS; n++) {
                h[n] = fmaf(pw[n], h[n], su * Bv[n]);
                float* ap = (n & 2) ? ((n & 1) ? &a3 : &a2) : ((n & 1) ? &a1 : &a0);
                *ap = fmaf(h[n], Cv[n], *ap);
            }
        } else {
            #pragma unroll
            for (int n = 0; n < NS; n++) {
                h[n] = fmaf(__expf(dl * A[n]), h[n], su * Bv[n]);
                float* ap = (n & 2) ? ((n & 1) ? &a3 : &a2) : ((n & 1) ? &a1 : &a0);
                *ap = fmaf(h[n], Cv[n], *ap);
            }
        }
        float acc = (a0 + a1) + (a2 + a3);
        float sz = zl / (1.f + __expf(-zl));
        y[row * DI + d] = __float2half_rn(fmaf(ul, Dd, acc) * sz);
    }
}

// ================= launch =================
extern "C" void kernel_launch(void* const* d_in, const int* in_sizes, int n_in,
                              void* d_out, int out_size) {
    const float* x      = (const float*)d_in[0];
    const float* ln_g   = (const float*)d_in[1];
    const float* ln_b   = (const float*)d_in[2];
    const float* W_in   = (const float*)d_in[3];
    const float* conv_w = (const float*)d_in[4];
    const float* conv_b = (const float*)d_in[5];
    const float* W_x    = (const float*)d_in[6];
    const float* W_dt   = (const float*)d_in[7];
    const float* b_dt   = (const float*)d_in[8];
    const float* A_log  = (const float*)d_in[9];
    const float* Dskip  = (const float*)d_in[10];
    const float* W_out  = (const float*)d_in[11];
    float* out = (float*)d_out;

    float *dblp, *dblr, *Ssum, *hend, *hstart;
    __half *xz, *xn, *y, *u, *dt, *delta;
    __half *win, *wout, *wx, *wdt;
    cudaGetSymbolAddress((void**)&xz, g_xz);
    cudaGetSymbolAddress((void**)&dblp, g_dblp);
    cudaGetSymbolAddress((void**)&dblr, g_dblr);
    cudaGetSymbolAddress((void**)&delta, g_delta);
    cudaGetSymbolAddress((void**)&Ssum, g_S);
    cudaGetSymbolAddress((void**)&hend, g_hend);
    cudaGetSymbolAddress((void**)&hstart, g_hstart);
    cudaGetSymbolAddress((void**)&xn, g_xn);
    cudaGetSymbolAddress((void**)&y, g_y);
    cudaGetSymbolAddress((void**)&u, g_u);
    cudaGetSymbolAddress((void**)&dt, g_dt);
    cudaGetSymbolAddress((void**)&win, g_win);
    cudaGetSymbolAddress((void**)&wout, g_wout);
    cudaGetSymbolAddress((void**)&wx, g_wx);
    cudaGetSymbolAddress((void**)&wdt, g_wdt);

    cudaFuncSetAttribute(gemmk<0>, cudaFuncAttributeMaxDynamicSharedMemorySize, SMEM1);
    cudaFuncSetAttribute(gemmk<1>, cudaFuncAttributeMaxDynamicSharedMemorySize, SMEM1);
    cudaFuncSetAttribute(gemmk<2>, cudaFuncAttributeMaxDynamicSharedMemorySize, SMEM1);
    cudaFuncSetAttribute(gemmk<3>, cudaFuncAttributeMaxDynamicSharedMemorySize, SMEM1);

    // 0. fused weight prep (4 transposes) + LayerNorm, one launch
    prep_kernel<<<6528 + ROWS, 256>>>(W_in, W_out, W_x, W_dt, x, ln_g, ln_b,
                                      win, wout, wx, wdt, xn);

    // 1. xz = xn @ W_in   [4096,1024]x[1024,4096] -> fp16   (nkt = 1024/64)
    gemmk<0><<<dim3(XZW/128, ROWS/128, 1), 256, SMEM1>>>(xn, win,
        nullptr, xz, DM, XZW, DM/64, 0);

    // 2. conv + silu -> u fp16 (vectorized, sliding window)
    conv_silu_kernel<<<(ROWS/CRS) * (DI/8) / 256, 256>>>(xz, conv_w, conv_b, u);

    // 3. dbl = u @ W_x   (split-K x4 -> fp32 partials; nkt = 2048/64/4)
    gemmk<3><<<dim3(1, ROWS/128, 4), 256, SMEM1>>>(u, wx,
        nullptr, dblp, DI, DBLW, (DI/64)/4, (size_t)ROWS * DBLW);

    // 4. reduce + dt fp16
    reduce_dbl_kernel<<<(ROWS*DBLW)/256, 256>>>(dblp, dblr, dt);

    // 5. delta = softplus(dt @ W_dt + b_dt) -> fp16   (nkt = 64/64 = 1)
    gemmk<2><<<dim3(DI/128, ROWS/128, 1), 256, SMEM1>>>(dt, wdt,
        b_dt, delta, DT, DI, DT/64, 0);

    // 6. chunked scan -> y fp16
    scan_pass1<<<dim3(DI/256, NC, BB), 256>>>(dblr, delta, u, A_log, Ssum, hend);
    scan_pass2<<<dim3(DI/256, BB), 256>>>(Ssum, hend, A_log, hstart);
    scan_pass3<<<dim3(DI/256, NC, BB), 256>>>(dblr, delta, u, xz, A_log, Dskip,
                                              hstart, y);

    // 7. out = x + y @ W_out   (nkt = 2048/64)
    gemmk<1><<<dim3(DM/128, ROWS/128, 1), 256, SMEM1>>>(y, wout,
        x, out, DI, DM, DI/64, 0);
}